// round 1
// baseline (speedup 1.0000x reference)
#include <cuda_runtime.h>
#include <math.h>

#define BB     4
#define TT     4096
#define HID    2048
#define NHEADS 16
#define HDIM   128
#define INTER  8192
#define KSEL   512
#define NTOK   (BB*KSEL)    // 2048 selected tokens
#define NTOT   (BB*TT)      // 16384 total tokens
#define CH     (HID/4)      // 512 predictor hidden

// ---------------- device scratch (allocation-free) ----------------
__device__ float g_logits[NTOT];
__device__ float g_flags[NTOT];
__device__ int   g_idx[BB*KSEL];
__device__ float g_gate[BB*KSEL];
__device__ float g_act[NTOT*CH];          // predictor hidden activations
__device__ float g_x [NTOK*HID];
__device__ float g_h [NTOK*HID];
__device__ float g_q [NTOK*HID];
__device__ float g_k [NTOK*HID];
__device__ float g_v [NTOK*HID];
__device__ float g_ao[NTOK*HID];
__device__ float g_h1[NTOK*HID];
__device__ float g_h2[NTOK*HID];
__device__ float g_lo[NTOK*HID];
__device__ float g_gb[NTOK*INTER];
__device__ float g_ub[NTOK*INTER];
__device__ double g_f0sum, g_selsum, g_predsum;

// ---------------- init ----------------
__global__ void k_init() {
    int i = blockIdx.x*blockDim.x + threadIdx.x;
    if (i < NTOT) g_flags[i] = 0.f;
    if (i == 0) { g_f0sum = 0.0; g_selsum = 0.0; g_predsum = 0.0; }
}

// ---------------- router logits + BCE f0 term ----------------
__global__ void k_router(const float* __restrict__ hs, const float* __restrict__ rw) {
    int t = blockIdx.x;
    const float* row = hs + (size_t)t*HID;
    float s = 0.f;
    for (int i = threadIdx.x; i < HID; i += 256) s += row[i]*rw[i];
    __shared__ float red[256];
    red[threadIdx.x] = s; __syncthreads();
    for (int st = 128; st; st >>= 1) {
        if (threadIdx.x < st) red[threadIdx.x] += red[threadIdx.x+st];
        __syncthreads();
    }
    if (threadIdx.x == 0) {
        float l = red[0];
        g_logits[t] = l;
        float f0 = fmaxf(l, 0.f) + log1pf(expf(-fabsf(l)));
        atomicAdd(&g_f0sum, (double)f0);
    }
}

// ---------------- per-batch top-k (bitonic) + index sort ----------------
__global__ void k_topk() {
    int b = blockIdx.x;
    __shared__ float sv[TT];
    __shared__ int   si[TT];
    int tid = threadIdx.x;
    for (int i = tid; i < TT; i += 1024) { sv[i] = g_logits[b*TT + i]; si[i] = i; }
    __syncthreads();
    // sort descending by value, ties -> ascending index (matches jax top_k)
    for (int k = 2; k <= TT; k <<= 1) {
        for (int j = k >> 1; j > 0; j >>= 1) {
            for (int i = tid; i < TT; i += 1024) {
                int ixj = i ^ j;
                if (ixj > i) {
                    float va = sv[i], vb = sv[ixj];
                    int ia = si[i], ib = si[ixj];
                    bool lij = (vb > va) || (vb == va && ib < ia); // x[ixj] ranks before x[i]
                    bool lji = (va > vb) || (va == vb && ia < ib);
                    bool sw = ((i & k) == 0) ? lij : lji;
                    if (sw) { sv[i] = vb; sv[ixj] = va; si[i] = ib; si[ixj] = ia; }
                }
            }
            __syncthreads();
        }
    }
    // re-sort the top-KSEL by original index ascending (= argsort(topk_idx))
    for (int k = 2; k <= KSEL; k <<= 1) {
        for (int j = k >> 1; j > 0; j >>= 1) {
            if (tid < KSEL) {
                int i = tid, ixj = i ^ j;
                if (ixj > i) {
                    int ia = si[i], ib = si[ixj];
                    bool sw = ((i & k) == 0) ? (ib < ia) : (ia < ib);
                    if (sw) {
                        int ti = si[i]; si[i] = si[ixj]; si[ixj] = ti;
                        float tv = sv[i]; sv[i] = sv[ixj]; sv[ixj] = tv;
                    }
                }
            }
            __syncthreads();
        }
    }
    if (tid < KSEL) {
        int token = si[tid]; float val = sv[tid];
        g_idx[b*KSEL + tid] = token;
        g_gate[b*KSEL + tid] = 1.f/(1.f + expf(-val));
        g_flags[b*TT + token] = 1.f;
        atomicAdd(&g_selsum, (double)val);
    }
}

// ---------------- fp32 SGEMM: C[M,N] = A[M,K] * Bw[N,K]^T (+bias/gelu/+add) ----------------
// epi: 0 = +bias (if non-null); 1 = gelu(acc+bias); 2 = acc + add residual
__global__ void k_sgemm(const float* __restrict__ A, const float* __restrict__ Bw,
                        const float* __restrict__ bias, const float* __restrict__ add,
                        float* __restrict__ C, int M, int N, int K, int epi) {
    __shared__ float As[8][128];
    __shared__ float Bs[8][128];
    int tid = threadIdx.x;
    int bm = blockIdx.y << 7, bn = blockIdx.x << 7;
    int lrow = tid >> 1, lcol = (tid & 1) << 2;
    const float* Ap = A  + (size_t)(bm + lrow)*K + lcol;
    const float* Bp = Bw + (size_t)(bn + lrow)*K + lcol;
    int tx = tid & 15, ty = tid >> 4;
    float acc[8][8];
#pragma unroll
    for (int i = 0; i < 8; i++)
#pragma unroll
        for (int j = 0; j < 8; j++) acc[i][j] = 0.f;
    for (int k0 = 0; k0 < K; k0 += 8) {
        float4 av = *(const float4*)(Ap + k0);
        float4 bv = *(const float4*)(Bp + k0);
        __syncthreads();
        As[lcol+0][lrow] = av.x; As[lcol+1][lrow] = av.y;
        As[lcol+2][lrow] = av.z; As[lcol+3][lrow] = av.w;
        Bs[lcol+0][lrow] = bv.x; Bs[lcol+1][lrow] = bv.y;
        Bs[lcol+2][lrow] = bv.z; Bs[lcol+3][lrow] = bv.w;
        __syncthreads();
#pragma unroll
        for (int kk = 0; kk < 8; kk++) {
            float4 a0 = *(const float4*)&As[kk][ty*8];
            float4 a1 = *(const float4*)&As[kk][ty*8+4];
            float4 b0 = *(const float4*)&Bs[kk][tx*8];
            float4 b1 = *(const float4*)&Bs[kk][tx*8+4];
            float ar[8] = {a0.x,a0.y,a0.z,a0.w,a1.x,a1.y,a1.z,a1.w};
            float br[8] = {b0.x,b0.y,b0.z,b0.w,b1.x,b1.y,b1.z,b1.w};
#pragma unroll
            for (int i = 0; i < 8; i++)
#pragma unroll
                for (int j = 0; j < 8; j++) acc[i][j] += ar[i]*br[j];
        }
    }
#pragma unroll
    for (int i = 0; i < 8; i++) {
        int m = bm + ty*8 + i;
#pragma unroll
        for (int j = 0; j < 8; j++) {
            int n = bn + tx*8 + j;
            float v = acc[i][j];
            if (bias) v += bias[n];
            if (epi == 1) v = 0.5f*v*(1.f + erff(v*0.70710678118654752f));
            if (epi == 2) v += add[(size_t)m*N + n];
            C[(size_t)m*N + n] = v;
        }
    }
}

// ---------------- predictor stage-2 dot + BCE ----------------
__global__ void k_pred2(const float* __restrict__ w2, const float* __restrict__ b2) {
    int warp = threadIdx.x >> 5, lane = threadIdx.x & 31;
    int t = blockIdx.x*8 + warp;
    const float* a = g_act + (size_t)t*CH;
    float s = 0.f;
    for (int i = lane; i < CH; i += 32) s += a[i]*w2[i];
    for (int o = 16; o; o >>= 1) s += __shfl_xor_sync(0xffffffffu, s, o);
    __shared__ float ps[8];
    if (lane == 0) {
        float p = s + b2[0];
        float tg = g_flags[t];
        ps[warp] = fmaxf(p, 0.f) - p*tg + log1pf(expf(-fabsf(p)));
    }
    __syncthreads();
    if (threadIdx.x == 0) {
        float tot = 0.f;
        for (int i = 0; i < 8; i++) tot += ps[i];
        atomicAdd(&g_predsum, (double)tot);
    }
}

// ---------------- gather selected rows ----------------
__global__ void k_gather(const float* __restrict__ hs) {
    int bj = blockIdx.x, b = bj >> 9;
    int t = g_idx[bj];
    const float* src = hs + ((size_t)b*TT + t)*HID;
    float* dst = g_x + (size_t)bj*HID;
    int i = threadIdx.x*8;
    *(float4*)(dst+i)   = *(const float4*)(src+i);
    *(float4*)(dst+i+4) = *(const float4*)(src+i+4);
}

// ---------------- rmsnorm (block per row) ----------------
__global__ void k_rms(const float* __restrict__ in, const float* __restrict__ w,
                      float* __restrict__ out) {
    int row = blockIdx.x;
    const float* src = in + (size_t)row*HID;
    float* dst = out + (size_t)row*HID;
    int i = threadIdx.x*8;
    float4 a = *(const float4*)(src+i), b = *(const float4*)(src+i+4);
    float ss = a.x*a.x + a.y*a.y + a.z*a.z + a.w*a.w
             + b.x*b.x + b.y*b.y + b.z*b.z + b.w*b.w;
    __shared__ float red[256];
    red[threadIdx.x] = ss; __syncthreads();
    for (int st = 128; st; st >>= 1) {
        if (threadIdx.x < st) red[threadIdx.x] += red[threadIdx.x+st];
        __syncthreads();
    }
    float sc = 1.f/sqrtf(red[0]/(float)HID + 1e-6f);
    float4 w0 = *(const float4*)(w+i), w1 = *(const float4*)(w+i+4);
    a.x *= sc*w0.x; a.y *= sc*w0.y; a.z *= sc*w0.z; a.w *= sc*w0.w;
    b.x *= sc*w1.x; b.y *= sc*w1.y; b.z *= sc*w1.z; b.w *= sc*w1.w;
    *(float4*)(dst+i) = a; *(float4*)(dst+i+4) = b;
}

// ---------------- RoPE on q and k ----------------
__global__ void k_rope() {
    int bh = blockIdx.x;
    int bj = bh >> 4, h = bh & 15;
    int pos = g_idx[bj];
    int d = threadIdx.x;                                  // 0..63
    float ang = (float)pos * expf(-(float)d * 0.14391156831212787f); // ln(1e4)/64
    float c = cosf(ang), s = sinf(ang);
    size_t base = (size_t)bj*HID + h*HDIM;
    float q1 = g_q[base+d], q2 = g_q[base+d+64];
    g_q[base+d]    = q1*c - q2*s;
    g_q[base+d+64] = q2*c + q1*s;
    float k1 = g_k[base+d], k2 = g_k[base+d+64];
    g_k[base+d]    = k1*c - k2*s;
    g_k[base+d+64] = k2*c + k1*s;
}

// ---------------- flash attention (causal, fp32) ----------------
// grid: (8 q-tiles, B*NHEADS). 256 threads. quad-per-row online softmax.
__global__ void k_attn() {
    extern __shared__ float sm[];
    float* Qs = sm;                 // 64 x 129
    float* Ks = Qs + 64*129;        // 64 x 129
    float* Vs = Ks + 64*129;        // 64 x 129
    float* Ss = Vs + 64*129;        // 64 x 65
    int qt = blockIdx.x, bh = blockIdx.y;
    int b = bh >> 4, h = bh & 15;
    int tid = threadIdx.x;
    size_t headbase = (size_t)b*KSEL*HID + (size_t)h*HDIM;
    for (int u = tid; u < 64*32; u += 256) {
        int r = u >> 5, c4 = (u & 31) << 2;
        float4 v = *(const float4*)(g_q + headbase + (size_t)(qt*64+r)*HID + c4);
        Qs[r*129+c4+0] = v.x*0.08838834764831845f;
        Qs[r*129+c4+1] = v.y*0.08838834764831845f;
        Qs[r*129+c4+2] = v.z*0.08838834764831845f;
        Qs[r*129+c4+3] = v.w*0.08838834764831845f;
    }
    int r = tid >> 2, qq = tid & 3;
    float m = -INFINITY, l = 0.f;
    float acc[32];
#pragma unroll
    for (int i = 0; i < 32; i++) acc[i] = 0.f;
    for (int kt = 0; kt <= qt; ++kt) {
        __syncthreads();
        for (int u = tid; u < 64*32; u += 256) {
            int jr = u >> 5, c4 = (u & 31) << 2;
            float4 kv = *(const float4*)(g_k + headbase + (size_t)(kt*64+jr)*HID + c4);
            float4 vv = *(const float4*)(g_v + headbase + (size_t)(kt*64+jr)*HID + c4);
            Ks[jr*129+c4+0] = kv.x; Ks[jr*129+c4+1] = kv.y;
            Ks[jr*129+c4+2] = kv.z; Ks[jr*129+c4+3] = kv.w;
            Vs[jr*129+c4+0] = vv.x; Vs[jr*129+c4+1] = vv.y;
            Vs[jr*129+c4+2] = vv.z; Vs[jr*129+c4+3] = vv.w;
        }
        __syncthreads();
        float a[16];
#pragma unroll
        for (int jj = 0; jj < 16; jj++) a[jj] = 0.f;
        const float* qrow = Qs + r*129;
        for (int d0 = 0; d0 < 128; d0 += 4) {
            float q0 = qrow[d0], q1 = qrow[d0+1], q2 = qrow[d0+2], q3 = qrow[d0+3];
#pragma unroll
            for (int jj = 0; jj < 16; jj++) {
                const float* kp = Ks + (qq + (jj<<2))*129 + d0;
                a[jj] += q0*kp[0] + q1*kp[1] + q2*kp[2] + q3*kp[3];
            }
        }
        int qg = qt*64 + r;
        float sreg[16];
#pragma unroll
        for (int jj = 0; jj < 16; jj++) {
            int kg = kt*64 + qq + (jj<<2);
            sreg[jj] = (kg <= qg) ? a[jj] : -1e9f;
        }
        float mx = sreg[0];
#pragma unroll
        for (int jj = 1; jj < 16; jj++) mx = fmaxf(mx, sreg[jj]);
        mx = fmaxf(mx, __shfl_xor_sync(0xffffffffu, mx, 1));
        mx = fmaxf(mx, __shfl_xor_sync(0xffffffffu, mx, 2));
        float mn = fmaxf(m, mx);
        float corr = expf(m - mn);
        float ls = 0.f;
#pragma unroll
        for (int jj = 0; jj < 16; jj++) {
            float p = expf(sreg[jj] - mn);
            ls += p;
            Ss[r*65 + qq + (jj<<2)] = p;
        }
        ls += __shfl_xor_sync(0xffffffffu, ls, 1);
        ls += __shfl_xor_sync(0xffffffffu, ls, 2);
        l = l*corr + ls; m = mn;
        __syncwarp();
#pragma unroll
        for (int i = 0; i < 32; i++) acc[i] *= corr;
        for (int j = 0; j < 64; j++) {
            float pv = Ss[r*65 + j];
            const float* vp = Vs + j*129 + qq;
#pragma unroll
            for (int i = 0; i < 32; i++) acc[i] += pv * vp[i<<2];
        }
    }
    float inv = 1.f/l;
    float* outp = g_ao + headbase + (size_t)(qt*64+r)*HID;
#pragma unroll
    for (int i = 0; i < 32; i++) outp[qq + (i<<2)] = acc[i]*inv;
}

// ---------------- silu(gate)*up ----------------
__global__ void k_silumul() {
    size_t i = ((size_t)blockIdx.x*256 + threadIdx.x)*4;
    float4 g = *(float4*)(g_gb+i);
    float4 u = *(float4*)(g_ub+i);
    g.x = g.x/(1.f+expf(-g.x))*u.x;
    g.y = g.y/(1.f+expf(-g.y))*u.y;
    g.z = g.z/(1.f+expf(-g.z))*u.z;
    g.w = g.w/(1.f+expf(-g.w))*u.w;
    *(float4*)(g_gb+i) = g;
}

// ---------------- output assembly ----------------
__global__ void k_copy(const float* __restrict__ src, float* __restrict__ dst) {
    size_t i = ((size_t)blockIdx.x*256 + threadIdx.x)*4;
    *(float4*)(dst+i) = *(const float4*)(src+i);
}

__global__ void k_scatter(float* __restrict__ out) {
    int bj = blockIdx.x, b = bj >> 9;
    int t = g_idx[bj];
    float gt = g_gate[bj];
    float* dst = out + ((size_t)b*TT + t)*HID;
    const float* xp = g_x + (size_t)bj*HID;
    const float* lp = g_lo + (size_t)bj*HID;
    int i = threadIdx.x*8;
#pragma unroll
    for (int u = 0; u < 8; u++) {
        float xv = xp[i+u], lv = lp[i+u];
        dst[i+u] = xv + gt*(lv - xv);
    }
}

__global__ void k_final(float* out, long long N, long long out_size) {
    if (threadIdx.x == 0) {
        if (N   < out_size) out[N]   = (float)((g_f0sum - g_selsum)/(double)NTOT);
        if (N+1 < out_size) out[N+1] = (float)(g_predsum/(double)NTOT);
    }
}

// ---------------- launch ----------------
extern "C" void kernel_launch(void* const* d_in, const int* in_sizes, int n_in,
                              void* d_out, int out_size) {
    const float* hs     = (const float*)d_in[0];
    const float* rw     = (const float*)d_in[1];
    const float* cfc1_w = (const float*)d_in[2];
    const float* cfc1_b = (const float*)d_in[3];
    const float* cfc2_w = (const float*)d_in[4];
    const float* cfc2_b = (const float*)d_in[5];
    const float* ln1    = (const float*)d_in[6];
    const float* ln2    = (const float*)d_in[7];
    const float* q_w    = (const float*)d_in[8];
    const float* q_b    = (const float*)d_in[9];
    const float* k_w    = (const float*)d_in[10];
    const float* k_b    = (const float*)d_in[11];
    const float* v_w    = (const float*)d_in[12];
    const float* v_b    = (const float*)d_in[13];
    const float* o_w    = (const float*)d_in[14];
    const float* gate_w = (const float*)d_in[15];
    const float* up_w   = (const float*)d_in[16];
    const float* down_w = (const float*)d_in[17];
    float* out = (float*)d_out;

    float *px, *ph, *pq, *pk, *pv, *pao, *ph1, *ph2, *plo, *pgb, *pub, *pact;
    cudaGetSymbolAddress((void**)&px,  g_x);
    cudaGetSymbolAddress((void**)&ph,  g_h);
    cudaGetSymbolAddress((void**)&pq,  g_q);
    cudaGetSymbolAddress((void**)&pk,  g_k);
    cudaGetSymbolAddress((void**)&pv,  g_v);
    cudaGetSymbolAddress((void**)&pao, g_ao);
    cudaGetSymbolAddress((void**)&ph1, g_h1);
    cudaGetSymbolAddress((void**)&ph2, g_h2);
    cudaGetSymbolAddress((void**)&plo, g_lo);
    cudaGetSymbolAddress((void**)&pgb, g_gb);
    cudaGetSymbolAddress((void**)&pub, g_ub);
    cudaGetSymbolAddress((void**)&pact, g_act);

    k_init<<<64, 256>>>();
    k_router<<<NTOT, 256>>>(hs, rw);
    k_topk<<<BB, 1024>>>();

    // predictor: gelu(hs @ cfc1^T + b1) -> act ; dot(act, cfc2)+b2 -> BCE
    k_sgemm<<<dim3(CH/128, NTOT/128), 256>>>(hs, cfc1_w, cfc1_b, nullptr, pact,
                                             NTOT, CH, HID, 1);
    k_pred2<<<NTOT/8, 256>>>(cfc2_w, cfc2_b);

    // gather + rmsnorm1
    k_gather<<<NTOK, 256>>>(hs);
    k_rms<<<NTOK, 256>>>(px, ln1, ph);

    // QKV projections
    k_sgemm<<<dim3(HID/128, NTOK/128), 256>>>(ph, q_w, q_b, nullptr, pq, NTOK, HID, HID, 0);
    k_sgemm<<<dim3(HID/128, NTOK/128), 256>>>(ph, k_w, k_b, nullptr, pk, NTOK, HID, HID, 0);
    k_sgemm<<<dim3(HID/128, NTOK/128), 256>>>(ph, v_w, v_b, nullptr, pv, NTOK, HID, HID, 0);
    k_rope<<<NTOK*NHEADS, 64>>>();

    // attention
    const int ATTN_SMEM = (3*64*129 + 64*65)*4;  // 115712 B
    cudaFuncSetAttribute(k_attn, cudaFuncAttributeMaxDynamicSharedMemorySize, ATTN_SMEM);
    k_attn<<<dim3(KSEL/64, BB*NHEADS), 256, ATTN_SMEM>>>();

    // O-proj + residual -> h1 ; rmsnorm2 -> h2
    k_sgemm<<<dim3(HID/128, NTOK/128), 256>>>(pao, o_w, nullptr, px, ph1, NTOK, HID, HID, 2);
    k_rms<<<NTOK, 256>>>(ph1, ln2, ph2);

    // MLP
    k_sgemm<<<dim3(INTER/128, NTOK/128), 256>>>(ph2, gate_w, nullptr, nullptr, pgb, NTOK, INTER, HID, 0);
    k_sgemm<<<dim3(INTER/128, NTOK/128), 256>>>(ph2, up_w,   nullptr, nullptr, pub, NTOK, INTER, HID, 0);
    k_silumul<<<(NTOK*(INTER/4))/256, 256>>>();
    k_sgemm<<<dim3(HID/128, NTOK/128), 256>>>(pgb, down_w, nullptr, ph1, plo, NTOK, HID, INTER, 2);

    // assemble output
    k_copy<<<((size_t)NTOT*HID/4)/256, 256>>>(hs, out);
    k_scatter<<<NTOK, 256>>>(out);
    k_final<<<1, 32>>>(out, (long long)NTOT*HID, (long long)out_size);
}

// round 4
// speedup vs baseline: 2.1712x; 2.1712x over previous
#include <cuda_runtime.h>
#include <cuda_bf16.h>
#include <stdint.h>
#include <math.h>

#define BB     4
#define TT     4096
#define HID    2048
#define NHEADS 16
#define HDIM   128
#define INTER  8192
#define KSEL   512
#define NTOK   (BB*KSEL)
#define NTOT   (BB*TT)
#define CH     (HID/4)

// ================= helpers =================
__device__ __forceinline__ uint32_t smem_to_u32(const void* p) {
    uint32_t a;
    asm("{ .reg .u64 t; cvta.to.shared.u64 t, %1; cvt.u32.u64 %0, t; }" : "=r"(a) : "l"(p));
    return a;
}
__device__ __forceinline__ void cp16(uint32_t s, const void* g) {
    asm volatile("cp.async.cg.shared.global [%0], [%1], 16;" :: "r"(s), "l"(g));
}
__device__ __forceinline__ void ldsm_x4(uint32_t* r, uint32_t addr) {
    asm volatile("ldmatrix.sync.aligned.m8n8.x4.shared.b16 {%0,%1,%2,%3}, [%4];"
        : "=r"(r[0]), "=r"(r[1]), "=r"(r[2]), "=r"(r[3]) : "r"(addr));
}
__device__ __forceinline__ void ldsm_x2(uint32_t* r, uint32_t addr) {
    asm volatile("ldmatrix.sync.aligned.m8n8.x2.shared.b16 {%0,%1}, [%2];"
        : "=r"(r[0]), "=r"(r[1]) : "r"(addr));
}
__device__ __forceinline__ void mma16816(float* d, const uint32_t* a, const uint32_t* b) {
    asm volatile(
        "mma.sync.aligned.m16n8k16.row.col.f32.bf16.bf16.f32 "
        "{%0,%1,%2,%3}, {%4,%5,%6,%7}, {%8,%9}, {%0,%1,%2,%3};"
        : "+f"(d[0]), "+f"(d[1]), "+f"(d[2]), "+f"(d[3])
        : "r"(a[0]), "r"(a[1]), "r"(a[2]), "r"(a[3]), "r"(b[0]), "r"(b[1]));
}

// ================= device scratch =================
__device__ float g_logits[NTOT];
__device__ float g_flags[NTOT];
__device__ int   g_idx[BB*KSEL];
__device__ float g_gate[BB*KSEL];
__device__ float g_act[NTOT*CH];
__device__ float g_x [NTOK*HID];
__device__ float g_h [NTOK*HID];
__device__ float g_q [NTOK*HID];
__device__ float g_k [NTOK*HID];
__device__ float g_v [NTOK*HID];
__device__ float g_ao[NTOK*HID];
__device__ float g_h1[NTOK*HID];
__device__ float g_h2[NTOK*HID];
__device__ float g_lo[NTOK*HID];
__device__ float g_gb[NTOK*INTER];
__device__ float g_ub[NTOK*INTER];
__device__ double g_f0sum, g_selsum, g_predsum;
// bf16 split buffers (plain row-major)
__device__ __nv_bfloat16 g_Ahi[33554432];   // max: NTOT*HID
__device__ __nv_bfloat16 g_Alo[33554432];
__device__ __nv_bfloat16 g_Bhi[16777216];   // max: INTER*HID
__device__ __nv_bfloat16 g_Blo[16777216];

// ================= small kernels =================
__global__ void k_init() {
    int i = blockIdx.x*blockDim.x + threadIdx.x;
    if (i < NTOT) g_flags[i] = 0.f;
    if (i == 0) { g_f0sum = 0.0; g_selsum = 0.0; g_predsum = 0.0; }
}

__global__ void k_router(const float* __restrict__ hs, const float* __restrict__ rw) {
    int t = blockIdx.x;
    const float* row = hs + (size_t)t*HID;
    float s = 0.f;
    for (int i = threadIdx.x; i < HID; i += 256) s += row[i]*rw[i];
    __shared__ float red[256];
    red[threadIdx.x] = s; __syncthreads();
    for (int st = 128; st; st >>= 1) {
        if (threadIdx.x < st) red[threadIdx.x] += red[threadIdx.x+st];
        __syncthreads();
    }
    if (threadIdx.x == 0) {
        float l = red[0];
        g_logits[t] = l;
        float f0 = fmaxf(l, 0.f) + log1pf(expf(-fabsf(l)));
        atomicAdd(&g_f0sum, (double)f0);
    }
}

__global__ void k_topk() {
    int b = blockIdx.x;
    __shared__ float sv[TT];
    __shared__ int   si[TT];
    int tid = threadIdx.x;
    for (int i = tid; i < TT; i += 1024) { sv[i] = g_logits[b*TT + i]; si[i] = i; }
    __syncthreads();
    for (int k = 2; k <= TT; k <<= 1) {
        for (int j = k >> 1; j > 0; j >>= 1) {
            for (int i = tid; i < TT; i += 1024) {
                int ixj = i ^ j;
                if (ixj > i) {
                    float va = sv[i], vb = sv[ixj];
                    int ia = si[i], ib = si[ixj];
                    bool lij = (vb > va) || (vb == va && ib < ia);
                    bool lji = (va > vb) || (va == vb && ia < ib);
                    bool sw = ((i & k) == 0) ? lij : lji;
                    if (sw) { sv[i] = vb; sv[ixj] = va; si[i] = ib; si[ixj] = ia; }
                }
            }
            __syncthreads();
        }
    }
    for (int k = 2; k <= KSEL; k <<= 1) {
        for (int j = k >> 1; j > 0; j >>= 1) {
            if (tid < KSEL) {
                int i = tid, ixj = i ^ j;
                if (ixj > i) {
                    int ia = si[i], ib = si[ixj];
                    bool sw = ((i & k) == 0) ? (ib < ia) : (ia < ib);
                    if (sw) {
                        int ti = si[i]; si[i] = si[ixj]; si[ixj] = ti;
                        float tv = sv[i]; sv[i] = sv[ixj]; sv[ixj] = tv;
                    }
                }
            }
            __syncthreads();
        }
    }
    if (tid < KSEL) {
        int token = si[tid]; float val = sv[tid];
        g_idx[b*KSEL + tid] = token;
        g_gate[b*KSEL + tid] = 1.f/(1.f + expf(-val));
        g_flags[b*TT + token] = 1.f;
        atomicAdd(&g_selsum, (double)val);
    }
}

__global__ void k_pred2(const float* __restrict__ w2, const float* __restrict__ b2) {
    int warp = threadIdx.x >> 5, lane = threadIdx.x & 31;
    int t = blockIdx.x*8 + warp;
    const float* a = g_act + (size_t)t*CH;
    float s = 0.f;
    for (int i = lane; i < CH; i += 32) s += a[i]*w2[i];
    for (int o = 16; o; o >>= 1) s += __shfl_xor_sync(0xffffffffu, s, o);
    __shared__ float ps[8];
    if (lane == 0) {
        float p = s + b2[0];
        float tg = g_flags[t];
        ps[warp] = fmaxf(p, 0.f) - p*tg + log1pf(expf(-fabsf(p)));
    }
    __syncthreads();
    if (threadIdx.x == 0) {
        float tot = 0.f;
        for (int i = 0; i < 8; i++) tot += ps[i];
        atomicAdd(&g_predsum, (double)tot);
    }
}

__global__ void k_gather(const float* __restrict__ hs) {
    int bj = blockIdx.x, b = bj >> 9;
    int t = g_idx[bj];
    const float* src = hs + ((size_t)b*TT + t)*HID;
    float* dst = g_x + (size_t)bj*HID;
    int i = threadIdx.x*8;
    *(float4*)(dst+i)   = *(const float4*)(src+i);
    *(float4*)(dst+i+4) = *(const float4*)(src+i+4);
}

__global__ void k_rms(const float* __restrict__ in, const float* __restrict__ w,
                      float* __restrict__ out) {
    int row = blockIdx.x;
    const float* src = in + (size_t)row*HID;
    float* dst = out + (size_t)row*HID;
    int i = threadIdx.x*8;
    float4 a = *(const float4*)(src+i), b = *(const float4*)(src+i+4);
    float ss = a.x*a.x + a.y*a.y + a.z*a.z + a.w*a.w
             + b.x*b.x + b.y*b.y + b.z*b.z + b.w*b.w;
    __shared__ float red[256];
    red[threadIdx.x] = ss; __syncthreads();
    for (int st = 128; st; st >>= 1) {
        if (threadIdx.x < st) red[threadIdx.x] += red[threadIdx.x+st];
        __syncthreads();
    }
    float sc = 1.f/sqrtf(red[0]/(float)HID + 1e-6f);
    float4 w0 = *(const float4*)(w+i), w1 = *(const float4*)(w+i+4);
    a.x *= sc*w0.x; a.y *= sc*w0.y; a.z *= sc*w0.z; a.w *= sc*w0.w;
    b.x *= sc*w1.x; b.y *= sc*w1.y; b.z *= sc*w1.z; b.w *= sc*w1.w;
    *(float4*)(dst+i) = a; *(float4*)(dst+i+4) = b;
}

__global__ void k_rope() {
    int bh = blockIdx.x;
    int bj = bh >> 4, h = bh & 15;
    int pos = g_idx[bj];
    int d = threadIdx.x;
    float ang = (float)pos * expf(-(float)d * 0.14391156831212787f);
    float c = cosf(ang), s = sinf(ang);
    size_t base = (size_t)bj*HID + h*HDIM;
    float q1 = g_q[base+d], q2 = g_q[base+d+64];
    g_q[base+d]    = q1*c - q2*s;
    g_q[base+d+64] = q2*c + q1*s;
    float k1 = g_k[base+d], k2 = g_k[base+d+64];
    g_k[base+d]    = k1*c - k2*s;
    g_k[base+d+64] = k2*c + k1*s;
}

__global__ void k_attn() {
    extern __shared__ float sm[];
    float* Qs = sm;
    float* Ks = Qs + 64*129;
    float* Vs = Ks + 64*129;
    float* Ss = Vs + 64*129;
    int qt = blockIdx.x, bh = blockIdx.y;
    int b = bh >> 4, h = bh & 15;
    int tid = threadIdx.x;
    size_t headbase = (size_t)b*KSEL*HID + (size_t)h*HDIM;
    for (int u = tid; u < 64*32; u += 256) {
        int r = u >> 5, c4 = (u & 31) << 2;
        float4 v = *(const float4*)(g_q + headbase + (size_t)(qt*64+r)*HID + c4);
        Qs[r*129+c4+0] = v.x*0.08838834764831845f;
        Qs[r*129+c4+1] = v.y*0.08838834764831845f;
        Qs[r*129+c4+2] = v.z*0.08838834764831845f;
        Qs[r*129+c4+3] = v.w*0.08838834764831845f;
    }
    int r = tid >> 2, qq = tid & 3;
    float m = -INFINITY, l = 0.f;
    float acc[32];
#pragma unroll
    for (int i = 0; i < 32; i++) acc[i] = 0.f;
    for (int kt = 0; kt <= qt; ++kt) {
        __syncthreads();
        for (int u = tid; u < 64*32; u += 256) {
            int jr = u >> 5, c4 = (u & 31) << 2;
            float4 kv = *(const float4*)(g_k + headbase + (size_t)(kt*64+jr)*HID + c4);
            float4 vv = *(const float4*)(g_v + headbase + (size_t)(kt*64+jr)*HID + c4);
            Ks[jr*129+c4+0] = kv.x; Ks[jr*129+c4+1] = kv.y;
            Ks[jr*129+c4+2] = kv.z; Ks[jr*129+c4+3] = kv.w;
            Vs[jr*129+c4+0] = vv.x; Vs[jr*129+c4+1] = vv.y;
            Vs[jr*129+c4+2] = vv.z; Vs[jr*129+c4+3] = vv.w;
        }
        __syncthreads();
        float a[16];
#pragma unroll
        for (int jj = 0; jj < 16; jj++) a[jj] = 0.f;
        const float* qrow = Qs + r*129;
        for (int d0 = 0; d0 < 128; d0 += 4) {
            float q0 = qrow[d0], q1 = qrow[d0+1], q2 = qrow[d0+2], q3 = qrow[d0+3];
#pragma unroll
            for (int jj = 0; jj < 16; jj++) {
                const float* kp = Ks + (qq + (jj<<2))*129 + d0;
                a[jj] += q0*kp[0] + q1*kp[1] + q2*kp[2] + q3*kp[3];
            }
        }
        int qg = qt*64 + r;
        float sreg[16];
#pragma unroll
        for (int jj = 0; jj < 16; jj++) {
            int kg = kt*64 + qq + (jj<<2);
            sreg[jj] = (kg <= qg) ? a[jj] : -1e9f;
        }
        float mx = sreg[0];
#pragma unroll
        for (int jj = 1; jj < 16; jj++) mx = fmaxf(mx, sreg[jj]);
        mx = fmaxf(mx, __shfl_xor_sync(0xffffffffu, mx, 1));
        mx = fmaxf(mx, __shfl_xor_sync(0xffffffffu, mx, 2));
        float mn = fmaxf(m, mx);
        float corr = expf(m - mn);
        float ls = 0.f;
#pragma unroll
        for (int jj = 0; jj < 16; jj++) {
            float p = expf(sreg[jj] - mn);
            ls += p;
            Ss[r*65 + qq + (jj<<2)] = p;
        }
        ls += __shfl_xor_sync(0xffffffffu, ls, 1);
        ls += __shfl_xor_sync(0xffffffffu, ls, 2);
        l = l*corr + ls; m = mn;
        __syncwarp();
#pragma unroll
        for (int i = 0; i < 32; i++) acc[i] *= corr;
        for (int j = 0; j < 64; j++) {
            float pv = Ss[r*65 + j];
            const float* vp = Vs + j*129 + qq;
#pragma unroll
            for (int i = 0; i < 32; i++) acc[i] += pv * vp[i<<2];
        }
    }
    float inv = 1.f/l;
    float* outp = g_ao + headbase + (size_t)(qt*64+r)*HID;
#pragma unroll
    for (int i = 0; i < 32; i++) outp[qq + (i<<2)] = acc[i]*inv;
}

__global__ void k_silumul() {
    size_t i = ((size_t)blockIdx.x*256 + threadIdx.x)*4;
    float4 g = *(float4*)(g_gb+i);
    float4 u = *(float4*)(g_ub+i);
    g.x = g.x/(1.f+expf(-g.x))*u.x;
    g.y = g.y/(1.f+expf(-g.y))*u.y;
    g.z = g.z/(1.f+expf(-g.z))*u.z;
    g.w = g.w/(1.f+expf(-g.w))*u.w;
    *(float4*)(g_gb+i) = g;
}

__global__ void k_copy(const float* __restrict__ src, float* __restrict__ dst) {
    size_t i = ((size_t)blockIdx.x*256 + threadIdx.x)*4;
    *(float4*)(dst+i) = *(const float4*)(src+i);
}

__global__ void k_scatter(float* __restrict__ out) {
    int bj = blockIdx.x, b = bj >> 9;
    int t = g_idx[bj];
    float gt = g_gate[bj];
    float* dst = out + ((size_t)b*TT + t)*HID;
    const float* xp = g_x + (size_t)bj*HID;
    const float* lp = g_lo + (size_t)bj*HID;
    int i = threadIdx.x*8;
#pragma unroll
    for (int u = 0; u < 8; u++) {
        float xv = xp[i+u], lv = lp[i+u];
        dst[i+u] = xv + gt*(lv - xv);
    }
}

__global__ void k_final(float* out, long long N, long long out_size) {
    if (threadIdx.x == 0) {
        if (N   < out_size) out[N]   = (float)((g_f0sum - g_selsum)/(double)NTOT);
        if (N+1 < out_size) out[N+1] = (float)(g_predsum/(double)NTOT);
    }
}

// ======== fp32 -> bf16 hi/lo split (plain row-major) ========
__global__ void k_conv(const float* __restrict__ src, __nv_bfloat16* __restrict__ hi,
                       __nv_bfloat16* __restrict__ lo) {
    size_t base = ((size_t)blockIdx.x*256 + threadIdx.x)*8;
    const float4* s = (const float4*)(src + base);
    float4 x0 = s[0], x1 = s[1];
    float xs[8] = {x0.x, x0.y, x0.z, x0.w, x1.x, x1.y, x1.z, x1.w};
    unsigned int hw[4], lw[4];
#pragma unroll
    for (int j = 0; j < 4; j++) {
        float a = xs[2*j], b = xs[2*j+1];
        __nv_bfloat16 ha = __float2bfloat16(a), hb = __float2bfloat16(b);
        float ra = a - __bfloat162float(ha), rb = b - __bfloat162float(hb);
        __nv_bfloat16 la = __float2bfloat16(ra), lb = __float2bfloat16(rb);
        hw[j] = (unsigned int)*(unsigned short*)&ha | ((unsigned int)*(unsigned short*)&hb << 16);
        lw[j] = (unsigned int)*(unsigned short*)&la | ((unsigned int)*(unsigned short*)&lb << 16);
    }
    *(uint4*)(hi + base) = make_uint4(hw[0], hw[1], hw[2], hw[3]);
    *(uint4*)(lo + base) = make_uint4(lw[0], lw[1], lw[2], lw[3]);
}

// ================= bf16x3 MMA GEMM: C[M,N] = A[M,K] @ B[N,K]^T =================
// Tile 128x128x32, 256 threads (8 warps 2m x 4n), warp tile 64x32.
// smem rows padded to 40 bf16 (80B): ldmatrix + cp.async conflict-free.
// epi: 0 = +bias(if set); 1 = gelu(acc+bias); 2 = acc + add residual
#define PADK 40
#define STAGE_ELEMS 20480           // 4 matrices * 128 * 40
#define STAGE_BYTES (STAGE_ELEMS*2)

__device__ __forceinline__ void load_stage(uint32_t sb, int stage,
    const __nv_bfloat16* Ah, const __nv_bfloat16* Al,
    const __nv_bfloat16* Bh, const __nv_bfloat16* Bl,
    int K, int kt, int tid)
{
    uint32_t s0 = sb + stage*STAGE_BYTES;
#pragma unroll
    for (int u = 0; u < 2; u++) {
        int c = tid + u*256;
        int row = c >> 2, seg = (c & 3) << 3;
        size_t g = (size_t)row*K + (size_t)kt*32 + seg;
        uint32_t sm = s0 + (row*PADK + seg)*2;
        cp16(sm,         Ah + g);
        cp16(sm + 10240, Al + g);
        cp16(sm + 20480, Bh + g);
        cp16(sm + 30720, Bl + g);
    }
    asm volatile("cp.async.commit_group;" ::: "memory");
}

__global__ void __launch_bounds__(256, 1) tc_gemm(
    const __nv_bfloat16* __restrict__ Ahi, const __nv_bfloat16* __restrict__ Alo,
    const __nv_bfloat16* __restrict__ Bhi, const __nv_bfloat16* __restrict__ Blo,
    const float* __restrict__ bias, const float* __restrict__ add,
    float* __restrict__ C, int M, int N, int K, int epi)
{
    extern __shared__ __align__(16) char smem[];
    uint32_t sb = smem_to_u32(smem);
    const int tid = threadIdx.x, wid = tid >> 5, lane = tid & 31;
    const int wm = wid & 1, wn = wid >> 1;
    const long bm = (long)blockIdx.y << 7, bn = (long)blockIdx.x << 7;

    const __nv_bfloat16* pAh = Ahi + (size_t)bm*K;
    const __nv_bfloat16* pAl = Alo + (size_t)bm*K;
    const __nv_bfloat16* pBh = Bhi + (size_t)bn*K;
    const __nv_bfloat16* pBl = Blo + (size_t)bn*K;

    float acc[4][4][4];
#pragma unroll
    for (int mt = 0; mt < 4; mt++)
#pragma unroll
        for (int nt = 0; nt < 4; nt++)
#pragma unroll
            for (int i = 0; i < 4; i++) acc[mt][nt][i] = 0.f;

    const int NK = K >> 5;
    load_stage(sb, 0, pAh, pAl, pBh, pBl, K, 0, tid);

    for (int kt = 0; kt < NK; ++kt) {
        if (kt + 1 < NK) {
            load_stage(sb, (kt+1) & 1, pAh, pAl, pBh, pBl, K, kt+1, tid);
            asm volatile("cp.async.wait_group 1;" ::: "memory");
        } else {
            asm volatile("cp.async.wait_group 0;" ::: "memory");
        }
        __syncthreads();

        uint32_t s0 = sb + (kt & 1)*STAGE_BYTES;
#pragma unroll
        for (int kk = 0; kk < 32; kk += 16) {
            uint32_t Af[2][4][4], Bf[2][4][2];
            const int arow = wm*64 + (lane & 15);
            const int acol = kk + ((lane >> 4) << 3);
#pragma unroll
            for (int mt = 0; mt < 4; mt++) {
                uint32_t ad = s0 + (uint32_t)((arow + mt*16)*PADK + acol)*2;
                ldsm_x4(Af[0][mt], ad);
                ldsm_x4(Af[1][mt], ad + 10240);
            }
            const int brow = wn*32 + (lane & 7);
            const int bcol = kk + (((lane >> 3) & 1) << 3);
#pragma unroll
            for (int nt = 0; nt < 4; nt++) {
                uint32_t bd = s0 + 20480 + (uint32_t)((brow + nt*8)*PADK + bcol)*2;
                ldsm_x2(Bf[0][nt], bd);
                ldsm_x2(Bf[1][nt], bd + 10240);
            }
#pragma unroll
            for (int mt = 0; mt < 4; mt++) {
#pragma unroll
                for (int nt = 0; nt < 4; nt++) {
                    mma16816(acc[mt][nt], Af[0][mt], Bf[0][nt]);  // hi*hi
                    mma16816(acc[mt][nt], Af[0][mt], Bf[1][nt]);  // hi*lo
                    mma16816(acc[mt][nt], Af[1][mt], Bf[0][nt]);  // lo*hi
                }
            }
        }
        __syncthreads();
    }

    // ---- epilogue (fragment mapping: d0,d1 -> (m, n/n+1); d2,d3 -> (m+8, ...)) ----
#pragma unroll
    for (int mt = 0; mt < 4; mt++) {
#pragma unroll
        for (int nt = 0; nt < 4; nt++) {
            long m = bm + wm*64 + mt*16 + (lane >> 2);
            long n = bn + wn*32 + nt*8 + ((lane & 3) << 1);
            float* a = acc[mt][nt];
            float b0 = bias ? bias[n] : 0.f;
            float b1 = bias ? bias[n+1] : 0.f;
            float v0 = a[0] + b0, v1 = a[1] + b1, v2 = a[2] + b0, v3 = a[3] + b1;
            if (epi == 1) {
                v0 = 0.5f*v0*(1.f + erff(v0*0.70710678118654752f));
                v1 = 0.5f*v1*(1.f + erff(v1*0.70710678118654752f));
                v2 = 0.5f*v2*(1.f + erff(v2*0.70710678118654752f));
                v3 = 0.5f*v3*(1.f + erff(v3*0.70710678118654752f));
            }
            if (epi == 2) {
                v0 += add[m*N + n];     v1 += add[m*N + n + 1];
                v2 += add[(m+8)*N + n]; v3 += add[(m+8)*N + n + 1];
            }
            *(float2*)(C + m*N + n)     = make_float2(v0, v1);
            *(float2*)(C + (m+8)*N + n) = make_float2(v2, v3);
        }
    }
}

// ================= launch =================
#define GEMM_SMEM (2*STAGE_BYTES)   // 81920

extern "C" void kernel_launch(void* const* d_in, const int* in_sizes, int n_in,
                              void* d_out, int out_size) {
    const float* hs     = (const float*)d_in[0];
    const float* rw     = (const float*)d_in[1];
    const float* cfc1_w = (const float*)d_in[2];
    const float* cfc1_b = (const float*)d_in[3];
    const float* cfc2_w = (const float*)d_in[4];
    const float* cfc2_b = (const float*)d_in[5];
    const float* ln1    = (const float*)d_in[6];
    const float* ln2    = (const float*)d_in[7];
    const float* q_w    = (const float*)d_in[8];
    const float* q_b    = (const float*)d_in[9];
    const float* k_w    = (const float*)d_in[10];
    const float* k_b    = (const float*)d_in[11];
    const float* v_w    = (const float*)d_in[12];
    const float* v_b    = (const float*)d_in[13];
    const float* o_w    = (const float*)d_in[14];
    const float* gate_w = (const float*)d_in[15];
    const float* up_w   = (const float*)d_in[16];
    const float* down_w = (const float*)d_in[17];
    float* out = (float*)d_out;

    float *px, *ph, *pq, *pk, *pv, *pao, *ph1, *ph2, *plo, *pgb, *pub, *pact;
    cudaGetSymbolAddress((void**)&px,  g_x);
    cudaGetSymbolAddress((void**)&ph,  g_h);
    cudaGetSymbolAddress((void**)&pq,  g_q);
    cudaGetSymbolAddress((void**)&pk,  g_k);
    cudaGetSymbolAddress((void**)&pv,  g_v);
    cudaGetSymbolAddress((void**)&pao, g_ao);
    cudaGetSymbolAddress((void**)&ph1, g_h1);
    cudaGetSymbolAddress((void**)&ph2, g_h2);
    cudaGetSymbolAddress((void**)&plo, g_lo);
    cudaGetSymbolAddress((void**)&pgb, g_gb);
    cudaGetSymbolAddress((void**)&pub, g_ub);
    cudaGetSymbolAddress((void**)&pact, g_act);
    __nv_bfloat16 *pAhi, *pAlo, *pBhi, *pBlo;
    cudaGetSymbolAddress((void**)&pAhi, g_Ahi);
    cudaGetSymbolAddress((void**)&pAlo, g_Alo);
    cudaGetSymbolAddress((void**)&pBhi, g_Bhi);
    cudaGetSymbolAddress((void**)&pBlo, g_Blo);

    cudaFuncSetAttribute(tc_gemm, cudaFuncAttributeMaxDynamicSharedMemorySize, GEMM_SMEM);
    const int ATTN_SMEM = (3*64*129 + 64*65)*4;
    cudaFuncSetAttribute(k_attn, cudaFuncAttributeMaxDynamicSharedMemorySize, ATTN_SMEM);

#define CONV(src, hi, lo, R, K) k_conv<<<((size_t)(R)*(K)/8)/256, 256>>>(src, hi, lo)
#define GEMM(M, N, K, bias, add, Cp, epi) \
    tc_gemm<<<dim3((N)/128, (M)/128), 256, GEMM_SMEM>>>(pAhi, pAlo, pBhi, pBlo, bias, add, Cp, M, N, K, epi)

    k_init<<<64, 256>>>();
    k_router<<<NTOT, 256>>>(hs, rw);
    k_topk<<<BB, 1024>>>();

    // predictor: gelu(hs @ cfc1^T + b1) -> g_act ; then BCE
    CONV(hs, pAhi, pAlo, NTOT, HID);
    CONV(cfc1_w, pBhi, pBlo, CH, HID);
    GEMM(NTOT, CH, HID, cfc1_b, nullptr, pact, 1);
    k_pred2<<<NTOT/8, 256>>>(cfc2_w, cfc2_b);

    // gather + rmsnorm1
    k_gather<<<NTOK, 256>>>(hs);
    k_rms<<<NTOK, 256>>>(px, ln1, ph);

    // QKV
    CONV(ph, pAhi, pAlo, NTOK, HID);
    CONV(q_w, pBhi, pBlo, HID, HID);
    GEMM(NTOK, HID, HID, q_b, nullptr, pq, 0);
    CONV(k_w, pBhi, pBlo, HID, HID);
    GEMM(NTOK, HID, HID, k_b, nullptr, pk, 0);
    CONV(v_w, pBhi, pBlo, HID, HID);
    GEMM(NTOK, HID, HID, v_b, nullptr, pv, 0);
    k_rope<<<NTOK*NHEADS, 64>>>();

    // attention
    k_attn<<<dim3(KSEL/64, BB*NHEADS), 256, ATTN_SMEM>>>();

    // O-proj + residual
    CONV(pao, pAhi, pAlo, NTOK, HID);
    CONV(o_w, pBhi, pBlo, HID, HID);
    GEMM(NTOK, HID, HID, nullptr, px, ph1, 2);
    k_rms<<<NTOK, 256>>>(ph1, ln2, ph2);

    // MLP
    CONV(ph2, pAhi, pAlo, NTOK, HID);
    CONV(gate_w, pBhi, pBlo, INTER, HID);
    GEMM(NTOK, INTER, HID, nullptr, nullptr, pgb, 0);
    CONV(up_w, pBhi, pBlo, INTER, HID);
    GEMM(NTOK, INTER, HID, nullptr, nullptr, pub, 0);
    k_silumul<<<(NTOK*(INTER/4))/256, 256>>>();
    CONV(pgb, pAhi, pAlo, NTOK, INTER);
    CONV(down_w, pBhi, pBlo, HID, INTER);
    GEMM(NTOK, HID, INTER, nullptr, ph1, plo, 2);

    // output
    k_copy<<<((size_t)NTOT*HID/4)/256, 256>>>(hs, out);
    k_scatter<<<NTOK, 256>>>(out);
    k_final<<<1, 32>>>(out, (long long)NTOT*HID, (long long)out_size);
}

// round 5
// speedup vs baseline: 2.3167x; 1.0670x over previous
#include <cuda_runtime.h>
#include <cuda_bf16.h>
#include <stdint.h>
#include <math.h>

#define BB     4
#define TT     4096
#define HID    2048
#define NHEADS 16
#define HDIM   128
#define INTER  8192
#define KSEL   512
#define NTOK   (BB*KSEL)
#define NTOT   (BB*TT)
#define CH     (HID/4)

// ================= helpers =================
__device__ __forceinline__ uint32_t smem_to_u32(const void* p) {
    uint32_t a;
    asm("{ .reg .u64 t; cvta.to.shared.u64 t, %1; cvt.u32.u64 %0, t; }" : "=r"(a) : "l"(p));
    return a;
}
__device__ __forceinline__ void cp16(uint32_t s, const void* g) {
    asm volatile("cp.async.cg.shared.global [%0], [%1], 16;" :: "r"(s), "l"(g));
}
__device__ __forceinline__ void ldsm_x4(uint32_t* r, uint32_t addr) {
    asm volatile("ldmatrix.sync.aligned.m8n8.x4.shared.b16 {%0,%1,%2,%3}, [%4];"
        : "=r"(r[0]), "=r"(r[1]), "=r"(r[2]), "=r"(r[3]) : "r"(addr));
}
__device__ __forceinline__ void mma16816(float* d, const uint32_t* a, const uint32_t* b) {
    asm volatile(
        "mma.sync.aligned.m16n8k16.row.col.f32.bf16.bf16.f32 "
        "{%0,%1,%2,%3}, {%4,%5,%6,%7}, {%8,%9}, {%0,%1,%2,%3};"
        : "+f"(d[0]), "+f"(d[1]), "+f"(d[2]), "+f"(d[3])
        : "r"(a[0]), "r"(a[1]), "r"(a[2]), "r"(a[3]), "r"(b[0]), "r"(b[1]));
}
__device__ __forceinline__ void split2(float v, unsigned short& h, unsigned short& l) {
    __nv_bfloat16 hb = __float2bfloat16(v);
    __nv_bfloat16 lb = __float2bfloat16(v - __bfloat162float(hb));
    h = *(unsigned short*)&hb; l = *(unsigned short*)&lb;
}

// ================= device scratch =================
__device__ float g_logits[NTOT];
__device__ float g_flags[NTOT];
__device__ int   g_idx[BB*KSEL];
__device__ float g_gate[BB*KSEL];
__device__ float g_act[NTOT*CH];
__device__ float g_x [NTOK*HID];
__device__ float g_q [NTOK*HID];
__device__ float g_k [NTOK*HID];
__device__ float g_v [NTOK*HID];
__device__ float g_h1[NTOK*HID];
__device__ float g_lo[NTOK*HID];
__device__ float g_gb[NTOK*INTER];
__device__ float g_ub[NTOK*INTER];
__device__ double g_f0sum, g_selsum, g_predsum;
// bf16 split buffers (plain row-major)
__device__ __nv_bfloat16 g_Ahi[33554432];   // max: NTOT*HID
__device__ __nv_bfloat16 g_Alo[33554432];
__device__ __nv_bfloat16 g_Bhi[16777216];   // max: INTER*HID
__device__ __nv_bfloat16 g_Blo[16777216];

// ================= small kernels =================
__global__ void k_init() {
    int i = blockIdx.x*blockDim.x + threadIdx.x;
    if (i < NTOT) g_flags[i] = 0.f;
    if (i == 0) { g_f0sum = 0.0; g_selsum = 0.0; g_predsum = 0.0; }
}

__global__ void k_router(const float* __restrict__ hs, const float* __restrict__ rw) {
    int t = blockIdx.x;
    const float* row = hs + (size_t)t*HID;
    float s = 0.f;
    for (int i = threadIdx.x; i < HID; i += 256) s += row[i]*rw[i];
    __shared__ float red[256];
    red[threadIdx.x] = s; __syncthreads();
    for (int st = 128; st; st >>= 1) {
        if (threadIdx.x < st) red[threadIdx.x] += red[threadIdx.x+st];
        __syncthreads();
    }
    if (threadIdx.x == 0) {
        float l = red[0];
        g_logits[t] = l;
        float f0 = fmaxf(l, 0.f) + log1pf(expf(-fabsf(l)));
        atomicAdd(&g_f0sum, (double)f0);
    }
}

__global__ void k_topk() {
    int b = blockIdx.x;
    __shared__ float sv[TT];
    __shared__ int   si[TT];
    int tid = threadIdx.x;
    for (int i = tid; i < TT; i += 1024) { sv[i] = g_logits[b*TT + i]; si[i] = i; }
    __syncthreads();
    for (int k = 2; k <= TT; k <<= 1) {
        for (int j = k >> 1; j > 0; j >>= 1) {
            for (int i = tid; i < TT; i += 1024) {
                int ixj = i ^ j;
                if (ixj > i) {
                    float va = sv[i], vb = sv[ixj];
                    int ia = si[i], ib = si[ixj];
                    bool lij = (vb > va) || (vb == va && ib < ia);
                    bool lji = (va > vb) || (va == vb && ia < ib);
                    bool sw = ((i & k) == 0) ? lij : lji;
                    if (sw) { sv[i] = vb; sv[ixj] = va; si[i] = ib; si[ixj] = ia; }
                }
            }
            __syncthreads();
        }
    }
    for (int k = 2; k <= KSEL; k <<= 1) {
        for (int j = k >> 1; j > 0; j >>= 1) {
            if (tid < KSEL) {
                int i = tid, ixj = i ^ j;
                if (ixj > i) {
                    int ia = si[i], ib = si[ixj];
                    bool sw = ((i & k) == 0) ? (ib < ia) : (ia < ib);
                    if (sw) {
                        int ti = si[i]; si[i] = si[ixj]; si[ixj] = ti;
                        float tv = sv[i]; sv[i] = sv[ixj]; sv[ixj] = tv;
                    }
                }
            }
            __syncthreads();
        }
    }
    if (tid < KSEL) {
        int token = si[tid]; float val = sv[tid];
        g_idx[b*KSEL + tid] = token;
        g_gate[b*KSEL + tid] = 1.f/(1.f + expf(-val));
        g_flags[b*TT + token] = 1.f;
        atomicAdd(&g_selsum, (double)val);
    }
}

__global__ void k_pred2(const float* __restrict__ w2, const float* __restrict__ b2) {
    int warp = threadIdx.x >> 5, lane = threadIdx.x & 31;
    int t = blockIdx.x*8 + warp;
    const float* a = g_act + (size_t)t*CH;
    float s = 0.f;
    for (int i = lane; i < CH; i += 32) s += a[i]*w2[i];
    for (int o = 16; o; o >>= 1) s += __shfl_xor_sync(0xffffffffu, s, o);
    __shared__ float ps[8];
    if (lane == 0) {
        float p = s + b2[0];
        float tg = g_flags[t];
        ps[warp] = fmaxf(p, 0.f) - p*tg + log1pf(expf(-fabsf(p)));
    }
    __syncthreads();
    if (threadIdx.x == 0) {
        float tot = 0.f;
        for (int i = 0; i < 8; i++) tot += ps[i];
        atomicAdd(&g_predsum, (double)tot);
    }
}

__global__ void k_gather(const float* __restrict__ hs) {
    int bj = blockIdx.x, b = bj >> 9;
    int t = g_idx[bj];
    const float* src = hs + ((size_t)b*TT + t)*HID;
    float* dst = g_x + (size_t)bj*HID;
    int i = threadIdx.x*8;
    *(float4*)(dst+i)   = *(const float4*)(src+i);
    *(float4*)(dst+i+4) = *(const float4*)(src+i+4);
}

// rmsnorm -> directly emit bf16 hi/lo split (A operand)
__global__ void k_rms(const float* __restrict__ in, const float* __restrict__ w,
                      __nv_bfloat16* __restrict__ hi, __nv_bfloat16* __restrict__ lo) {
    int row = blockIdx.x;
    const float* src = in + (size_t)row*HID;
    int i = threadIdx.x*8;
    float4 a = *(const float4*)(src+i), b = *(const float4*)(src+i+4);
    float ss = a.x*a.x + a.y*a.y + a.z*a.z + a.w*a.w
             + b.x*b.x + b.y*b.y + b.z*b.z + b.w*b.w;
    __shared__ float red[256];
    red[threadIdx.x] = ss; __syncthreads();
    for (int st = 128; st; st >>= 1) {
        if (threadIdx.x < st) red[threadIdx.x] += red[threadIdx.x+st];
        __syncthreads();
    }
    float sc = 1.f/sqrtf(red[0]/(float)HID + 1e-6f);
    float4 w0 = *(const float4*)(w+i), w1 = *(const float4*)(w+i+4);
    float v[8] = {a.x*sc*w0.x, a.y*sc*w0.y, a.z*sc*w0.z, a.w*sc*w0.w,
                  b.x*sc*w1.x, b.y*sc*w1.y, b.z*sc*w1.z, b.w*sc*w1.w};
    unsigned short hv[8], lv[8];
#pragma unroll
    for (int j = 0; j < 8; j++) split2(v[j], hv[j], lv[j]);
    size_t base = (size_t)row*HID + i;
    *(uint4*)(hi + base) = *(uint4*)hv;
    *(uint4*)(lo + base) = *(uint4*)lv;
}

__global__ void k_rope() {
    int bh = blockIdx.x;
    int bj = bh >> 4, h = bh & 15;
    int pos = g_idx[bj];
    int d = threadIdx.x;
    float ang = (float)pos * expf(-(float)d * 0.14391156831212787f);
    float c = cosf(ang), s = sinf(ang);
    size_t base = (size_t)bj*HID + h*HDIM;
    float q1 = g_q[base+d], q2 = g_q[base+d+64];
    g_q[base+d]    = q1*c - q2*s;
    g_q[base+d+64] = q2*c + q1*s;
    float k1 = g_k[base+d], k2 = g_k[base+d+64];
    g_k[base+d]    = k1*c - k2*s;
    g_k[base+d+64] = k2*c + k1*s;
}

// flash attention -> emits hi/lo split directly (A operand for O-proj)
__global__ void k_attn(__nv_bfloat16* __restrict__ ohi, __nv_bfloat16* __restrict__ olo) {
    extern __shared__ float sm[];
    float* Qs = sm;
    float* Ks = Qs + 64*129;
    float* Vs = Ks + 64*129;
    float* Ss = Vs + 64*129;
    int qt = blockIdx.x, bh = blockIdx.y;
    int b = bh >> 4, h = bh & 15;
    int tid = threadIdx.x;
    size_t headbase = (size_t)b*KSEL*HID + (size_t)h*HDIM;
    for (int u = tid; u < 64*32; u += 256) {
        int r = u >> 5, c4 = (u & 31) << 2;
        float4 v = *(const float4*)(g_q + headbase + (size_t)(qt*64+r)*HID + c4);
        Qs[r*129+c4+0] = v.x*0.08838834764831845f;
        Qs[r*129+c4+1] = v.y*0.08838834764831845f;
        Qs[r*129+c4+2] = v.z*0.08838834764831845f;
        Qs[r*129+c4+3] = v.w*0.08838834764831845f;
    }
    int r = tid >> 2, qq = tid & 3;
    float m = -INFINITY, l = 0.f;
    float acc[32];
#pragma unroll
    for (int i = 0; i < 32; i++) acc[i] = 0.f;
    for (int kt = 0; kt <= qt; ++kt) {
        __syncthreads();
        for (int u = tid; u < 64*32; u += 256) {
            int jr = u >> 5, c4 = (u & 31) << 2;
            float4 kv = *(const float4*)(g_k + headbase + (size_t)(kt*64+jr)*HID + c4);
            float4 vv = *(const float4*)(g_v + headbase + (size_t)(kt*64+jr)*HID + c4);
            Ks[jr*129+c4+0] = kv.x; Ks[jr*129+c4+1] = kv.y;
            Ks[jr*129+c4+2] = kv.z; Ks[jr*129+c4+3] = kv.w;
            Vs[jr*129+c4+0] = vv.x; Vs[jr*129+c4+1] = vv.y;
            Vs[jr*129+c4+2] = vv.z; Vs[jr*129+c4+3] = vv.w;
        }
        __syncthreads();
        float a[16];
#pragma unroll
        for (int jj = 0; jj < 16; jj++) a[jj] = 0.f;
        const float* qrow = Qs + r*129;
        for (int d0 = 0; d0 < 128; d0 += 4) {
            float q0 = qrow[d0], q1 = qrow[d0+1], q2 = qrow[d0+2], q3 = qrow[d0+3];
#pragma unroll
            for (int jj = 0; jj < 16; jj++) {
                const float* kp = Ks + (qq + (jj<<2))*129 + d0;
                a[jj] += q0*kp[0] + q1*kp[1] + q2*kp[2] + q3*kp[3];
            }
        }
        int qg = qt*64 + r;
        float sreg[16];
#pragma unroll
        for (int jj = 0; jj < 16; jj++) {
            int kg = kt*64 + qq + (jj<<2);
            sreg[jj] = (kg <= qg) ? a[jj] : -1e9f;
        }
        float mx = sreg[0];
#pragma unroll
        for (int jj = 1; jj < 16; jj++) mx = fmaxf(mx, sreg[jj]);
        mx = fmaxf(mx, __shfl_xor_sync(0xffffffffu, mx, 1));
        mx = fmaxf(mx, __shfl_xor_sync(0xffffffffu, mx, 2));
        float mn = fmaxf(m, mx);
        float corr = expf(m - mn);
        float ls = 0.f;
#pragma unroll
        for (int jj = 0; jj < 16; jj++) {
            float p = expf(sreg[jj] - mn);
            ls += p;
            Ss[r*65 + qq + (jj<<2)] = p;
        }
        ls += __shfl_xor_sync(0xffffffffu, ls, 1);
        ls += __shfl_xor_sync(0xffffffffu, ls, 2);
        l = l*corr + ls; m = mn;
        __syncwarp();
#pragma unroll
        for (int i = 0; i < 32; i++) acc[i] *= corr;
        for (int j = 0; j < 64; j++) {
            float pv = Ss[r*65 + j];
            const float* vp = Vs + j*129 + qq;
#pragma unroll
            for (int i = 0; i < 32; i++) acc[i] += pv * vp[i<<2];
        }
    }
    float inv = 1.f/l;
    size_t outb = headbase + (size_t)(qt*64+r)*HID + qq;
#pragma unroll
    for (int i = 0; i < 32; i++) {
        unsigned short hv, lv;
        split2(acc[i]*inv, hv, lv);
        *(unsigned short*)(ohi + outb + (i<<2)) = hv;
        *(unsigned short*)(olo + outb + (i<<2)) = lv;
    }
}

// silu(gate)*up -> emits hi/lo split directly (A operand for down-proj)
__global__ void k_silumul(__nv_bfloat16* __restrict__ hi, __nv_bfloat16* __restrict__ lo) {
    size_t i = ((size_t)blockIdx.x*256 + threadIdx.x)*8;
    float4 g0 = *(float4*)(g_gb+i),   u0 = *(float4*)(g_ub+i);
    float4 g1 = *(float4*)(g_gb+i+4), u1 = *(float4*)(g_ub+i+4);
    float v[8] = {
        g0.x/(1.f+expf(-g0.x))*u0.x, g0.y/(1.f+expf(-g0.y))*u0.y,
        g0.z/(1.f+expf(-g0.z))*u0.z, g0.w/(1.f+expf(-g0.w))*u0.w,
        g1.x/(1.f+expf(-g1.x))*u1.x, g1.y/(1.f+expf(-g1.y))*u1.y,
        g1.z/(1.f+expf(-g1.z))*u1.z, g1.w/(1.f+expf(-g1.w))*u1.w };
    unsigned short hv[8], lv[8];
#pragma unroll
    for (int j = 0; j < 8; j++) split2(v[j], hv[j], lv[j]);
    *(uint4*)(hi + i) = *(uint4*)hv;
    *(uint4*)(lo + i) = *(uint4*)lv;
}

__global__ void k_copy(const float* __restrict__ src, float* __restrict__ dst) {
    size_t i = ((size_t)blockIdx.x*256 + threadIdx.x)*4;
    *(float4*)(dst+i) = *(const float4*)(src+i);
}

__global__ void k_scatter(float* __restrict__ out) {
    int bj = blockIdx.x, b = bj >> 9;
    int t = g_idx[bj];
    float gt = g_gate[bj];
    float* dst = out + ((size_t)b*TT + t)*HID;
    const float* xp = g_x + (size_t)bj*HID;
    const float* lp = g_lo + (size_t)bj*HID;
    int i = threadIdx.x*8;
#pragma unroll
    for (int u = 0; u < 8; u++) {
        float xv = xp[i+u], lv = lp[i+u];
        dst[i+u] = xv + gt*(lv - xv);
    }
}

__global__ void k_final(float* out, long long N, long long out_size) {
    if (threadIdx.x == 0) {
        if (N   < out_size) out[N]   = (float)((g_f0sum - g_selsum)/(double)NTOT);
        if (N+1 < out_size) out[N+1] = (float)(g_predsum/(double)NTOT);
    }
}

// ======== fp32 -> bf16 hi/lo split (plain row-major) ========
__global__ void k_conv(const float* __restrict__ src, __nv_bfloat16* __restrict__ hi,
                       __nv_bfloat16* __restrict__ lo) {
    size_t base = ((size_t)blockIdx.x*256 + threadIdx.x)*8;
    const float4* s = (const float4*)(src + base);
    float4 x0 = s[0], x1 = s[1];
    float xs[8] = {x0.x, x0.y, x0.z, x0.w, x1.x, x1.y, x1.z, x1.w};
    unsigned short hv[8], lv[8];
#pragma unroll
    for (int j = 0; j < 8; j++) split2(xs[j], hv[j], lv[j]);
    *(uint4*)(hi + base) = *(uint4*)hv;
    *(uint4*)(lo + base) = *(uint4*)lv;
}

// ================= bf16x3 MMA GEMM: C[M,N] = A[M,K] @ B[N,K]^T =================
// CTA tile 128x256x32, 256 threads (8 warps 2m x 4n), warp tile 64x64.
// 3-stage cp.async pipeline. smem rows padded to 40 bf16 (conflict-free ldmatrix).
// epi: 0 = +bias(if set); 1 = gelu(acc+bias); 2 = acc + add residual
#define PADK 40
#define A_BYTES   (128*PADK*2)          // 10240 per matrix
#define B_BYTES   (256*PADK*2)          // 20480 per matrix
#define STAGE_BYTES (2*A_BYTES + 2*B_BYTES)   // 61440
#define GEMM_SMEM (3*STAGE_BYTES)             // 184320

__device__ __forceinline__ void load_stage(uint32_t sb, int stage,
    const __nv_bfloat16* Ah, const __nv_bfloat16* Al,
    const __nv_bfloat16* Bh, const __nv_bfloat16* Bl,
    int K, int kt, int tid)
{
    uint32_t s0 = sb + stage*STAGE_BYTES;
    // A: 128 rows x 32 cols, hi+lo
#pragma unroll
    for (int u = 0; u < 2; u++) {
        int c = tid + u*256;
        int row = c >> 2, seg = (c & 3) << 3;
        size_t g = (size_t)row*K + (size_t)kt*32 + seg;
        uint32_t sm = s0 + (row*PADK + seg)*2;
        cp16(sm, Ah + g);
        cp16(sm + A_BYTES, Al + g);
    }
    // B: 256 rows x 32 cols, hi+lo
#pragma unroll
    for (int u = 0; u < 4; u++) {
        int c = tid + u*256;
        int row = c >> 2, seg = (c & 3) << 3;
        size_t g = (size_t)row*K + (size_t)kt*32 + seg;
        uint32_t sm = s0 + 2*A_BYTES + (row*PADK + seg)*2;
        cp16(sm, Bh + g);
        cp16(sm + B_BYTES, Bl + g);
    }
    asm volatile("cp.async.commit_group;" ::: "memory");
}

__global__ void __launch_bounds__(256, 1) tc_gemm(
    const __nv_bfloat16* __restrict__ Ahi, const __nv_bfloat16* __restrict__ Alo,
    const __nv_bfloat16* __restrict__ Bhi, const __nv_bfloat16* __restrict__ Blo,
    const float* __restrict__ bias, const float* __restrict__ add,
    float* __restrict__ C, int M, int N, int K, int epi)
{
    extern __shared__ __align__(16) char smem[];
    uint32_t sb = smem_to_u32(smem);
    const int tid = threadIdx.x, wid = tid >> 5, lane = tid & 31;
    const int wm = wid & 1, wn = wid >> 1;
    const long bm = (long)blockIdx.y << 7, bn = (long)blockIdx.x << 8;

    const __nv_bfloat16* pAh = Ahi + (size_t)bm*K;
    const __nv_bfloat16* pAl = Alo + (size_t)bm*K;
    const __nv_bfloat16* pBh = Bhi + (size_t)bn*K;
    const __nv_bfloat16* pBl = Blo + (size_t)bn*K;

    float acc[4][8][4];
#pragma unroll
    for (int mt = 0; mt < 4; mt++)
#pragma unroll
        for (int nt = 0; nt < 8; nt++)
#pragma unroll
            for (int i = 0; i < 4; i++) acc[mt][nt][i] = 0.f;

    const int NK = K >> 5;
    load_stage(sb, 0, pAh, pAl, pBh, pBl, K, 0, tid);
    load_stage(sb, 1, pAh, pAl, pBh, pBl, K, 1, tid);

    for (int kt = 0; kt < NK; ++kt) {
        if (kt + 2 < NK) {
            load_stage(sb, (kt+2)%3, pAh, pAl, pBh, pBl, K, kt+2, tid);
            asm volatile("cp.async.wait_group 2;" ::: "memory");
        } else {
            asm volatile("cp.async.wait_group 0;" ::: "memory");
        }
        __syncthreads();

        uint32_t s0 = sb + (kt%3)*STAGE_BYTES;
#pragma unroll
        for (int kk = 0; kk < 32; kk += 16) {
            // B fragments: 8 n-tiles, hi+lo (ldsm_x4 loads 2 n-tiles each)
            uint32_t Bf[2][8][2];
            const int brow = wn*64 + (lane & 7) + (((lane >> 4) & 1) << 3);
            const int bcol = kk + (((lane >> 3) & 1) << 3);
#pragma unroll
            for (int np = 0; np < 4; np++) {
                uint32_t bd = s0 + 2*A_BYTES + (uint32_t)((brow + np*16)*PADK + bcol)*2;
                uint32_t r[4];
                ldsm_x4(r, bd);
                Bf[0][np*2][0] = r[0]; Bf[0][np*2][1] = r[1];
                Bf[0][np*2+1][0] = r[2]; Bf[0][np*2+1][1] = r[3];
                ldsm_x4(r, bd + B_BYTES);
                Bf[1][np*2][0] = r[0]; Bf[1][np*2][1] = r[1];
                Bf[1][np*2+1][0] = r[2]; Bf[1][np*2+1][1] = r[3];
            }
            const int arow = wm*64 + (lane & 15);
            const int acol = kk + ((lane >> 4) << 3);
#pragma unroll
            for (int mt = 0; mt < 4; mt++) {
                uint32_t Ah[4], Al[4];
                uint32_t ad = s0 + (uint32_t)((arow + mt*16)*PADK + acol)*2;
                ldsm_x4(Ah, ad);
                ldsm_x4(Al, ad + A_BYTES);
#pragma unroll
                for (int nt = 0; nt < 8; nt++) {
                    mma16816(acc[mt][nt], Ah, Bf[0][nt]);  // hi*hi
                    mma16816(acc[mt][nt], Ah, Bf[1][nt]);  // hi*lo
                    mma16816(acc[mt][nt], Al, Bf[0][nt]);  // lo*hi
                }
            }
        }
        __syncthreads();
    }

    // ---- epilogue ----
#pragma unroll
    for (int mt = 0; mt < 4; mt++) {
#pragma unroll
        for (int nt = 0; nt < 8; nt++) {
            long m = bm + wm*64 + mt*16 + (lane >> 2);
            long n = bn + wn*64 + nt*8 + ((lane & 3) << 1);
            float* a = acc[mt][nt];
            float b0 = bias ? bias[n] : 0.f;
            float b1 = bias ? bias[n+1] : 0.f;
            float v0 = a[0] + b0, v1 = a[1] + b1, v2 = a[2] + b0, v3 = a[3] + b1;
            if (epi == 1) {
                v0 = 0.5f*v0*(1.f + erff(v0*0.70710678118654752f));
                v1 = 0.5f*v1*(1.f + erff(v1*0.70710678118654752f));
                v2 = 0.5f*v2*(1.f + erff(v2*0.70710678118654752f));
                v3 = 0.5f*v3*(1.f + erff(v3*0.70710678118654752f));
            }
            if (epi == 2) {
                v0 += add[m*N + n];     v1 += add[m*N + n + 1];
                v2 += add[(m+8)*N + n]; v3 += add[(m+8)*N + n + 1];
            }
            *(float2*)(C + m*N + n)     = make_float2(v0, v1);
            *(float2*)(C + (m+8)*N + n) = make_float2(v2, v3);
        }
    }
}

// ================= launch =================
extern "C" void kernel_launch(void* const* d_in, const int* in_sizes, int n_in,
                              void* d_out, int out_size) {
    const float* hs     = (const float*)d_in[0];
    const float* rw     = (const float*)d_in[1];
    const float* cfc1_w = (const float*)d_in[2];
    const float* cfc1_b = (const float*)d_in[3];
    const float* cfc2_w = (const float*)d_in[4];
    const float* cfc2_b = (const float*)d_in[5];
    const float* ln1    = (const float*)d_in[6];
    const float* ln2    = (const float*)d_in[7];
    const float* q_w    = (const float*)d_in[8];
    const float* q_b    = (const float*)d_in[9];
    const float* k_w    = (const float*)d_in[10];
    const float* k_b    = (const float*)d_in[11];
    const float* v_w    = (const float*)d_in[12];
    const float* v_b    = (const float*)d_in[13];
    const float* o_w    = (const float*)d_in[14];
    const float* gate_w = (const float*)d_in[15];
    const float* up_w   = (const float*)d_in[16];
    const float* down_w = (const float*)d_in[17];
    float* out = (float*)d_out;

    float *px, *pq, *pk, *pv, *ph1, *plo, *pgb, *pub, *pact;
    cudaGetSymbolAddress((void**)&px,  g_x);
    cudaGetSymbolAddress((void**)&pq,  g_q);
    cudaGetSymbolAddress((void**)&pk,  g_k);
    cudaGetSymbolAddress((void**)&pv,  g_v);
    cudaGetSymbolAddress((void**)&ph1, g_h1);
    cudaGetSymbolAddress((void**)&plo, g_lo);
    cudaGetSymbolAddress((void**)&pgb, g_gb);
    cudaGetSymbolAddress((void**)&pub, g_ub);
    cudaGetSymbolAddress((void**)&pact, g_act);
    __nv_bfloat16 *pAhi, *pAlo, *pBhi, *pBlo;
    cudaGetSymbolAddress((void**)&pAhi, g_Ahi);
    cudaGetSymbolAddress((void**)&pAlo, g_Alo);
    cudaGetSymbolAddress((void**)&pBhi, g_Bhi);
    cudaGetSymbolAddress((void**)&pBlo, g_Blo);

    cudaFuncSetAttribute(tc_gemm, cudaFuncAttributeMaxDynamicSharedMemorySize, GEMM_SMEM);
    const int ATTN_SMEM = (3*64*129 + 64*65)*4;
    cudaFuncSetAttribute(k_attn, cudaFuncAttributeMaxDynamicSharedMemorySize, ATTN_SMEM);

#define CONV(src, hi, lo, R, K) k_conv<<<((size_t)(R)*(K)/8)/256, 256>>>(src, hi, lo)
#define GEMM(M, N, K, bias, add, Cp, epi) \
    tc_gemm<<<dim3((N)/256, (M)/128), 256, GEMM_SMEM>>>(pAhi, pAlo, pBhi, pBlo, bias, add, Cp, M, N, K, epi)

    k_init<<<64, 256>>>();
    k_router<<<NTOT, 256>>>(hs, rw);
    k_topk<<<BB, 1024>>>();

    // predictor: gelu(hs @ cfc1^T + b1) -> g_act ; then BCE
    CONV(hs, pAhi, pAlo, NTOT, HID);
    CONV(cfc1_w, pBhi, pBlo, CH, HID);
    GEMM(NTOT, CH, HID, cfc1_b, nullptr, pact, 1);
    k_pred2<<<NTOT/8, 256>>>(cfc2_w, cfc2_b);

    // gather + rmsnorm1 (emits split A directly)
    k_gather<<<NTOK, 256>>>(hs);
    k_rms<<<NTOK, 256>>>(px, ln1, pAhi, pAlo);

    // QKV
    CONV(q_w, pBhi, pBlo, HID, HID);
    GEMM(NTOK, HID, HID, q_b, nullptr, pq, 0);
    CONV(k_w, pBhi, pBlo, HID, HID);
    GEMM(NTOK, HID, HID, k_b, nullptr, pk, 0);
    CONV(v_w, pBhi, pBlo, HID, HID);
    GEMM(NTOK, HID, HID, v_b, nullptr, pv, 0);
    k_rope<<<NTOK*NHEADS, 64>>>();

    // attention (emits split A for O-proj)
    k_attn<<<dim3(KSEL/64, BB*NHEADS), 256, ATTN_SMEM>>>(pAhi, pAlo);

    // O-proj + residual -> h1 ; rmsnorm2 emits split A for MLP
    CONV(o_w, pBhi, pBlo, HID, HID);
    GEMM(NTOK, HID, HID, nullptr, px, ph1, 2);
    k_rms<<<NTOK, 256>>>(ph1, ln2, pAhi, pAlo);

    // MLP
    CONV(gate_w, pBhi, pBlo, INTER, HID);
    GEMM(NTOK, INTER, HID, nullptr, nullptr, pgb, 0);
    CONV(up_w, pBhi, pBlo, INTER, HID);
    GEMM(NTOK, INTER, HID, nullptr, nullptr, pub, 0);
    k_silumul<<<(NTOK*(INTER/8))/256, 256>>>(pAhi, pAlo);
    CONV(down_w, pBhi, pBlo, HID, INTER);
    GEMM(NTOK, HID, INTER, nullptr, ph1, plo, 2);

    // output
    k_copy<<<((size_t)NTOT*HID/4)/256, 256>>>(hs, out);
    k_scatter<<<NTOK, 256>>>(out);
    k_final<<<1, 32>>>(out, (long long)NTOT*HID, (long long)out_size);
}

// round 6
// speedup vs baseline: 2.4186x; 1.0440x over previous
#include <cuda_runtime.h>
#include <cuda_bf16.h>
#include <stdint.h>
#include <math.h>

#define BB     4
#define TT     4096
#define HID    2048
#define NHEADS 16
#define HDIM   128
#define INTER  8192
#define KSEL   512
#define NTOK   (BB*KSEL)
#define NTOT   (BB*TT)
#define CH     (HID/4)

// ================= helpers =================
__device__ __forceinline__ uint32_t smem_to_u32(const void* p) {
    uint32_t a;
    asm("{ .reg .u64 t; cvta.to.shared.u64 t, %1; cvt.u32.u64 %0, t; }" : "=r"(a) : "l"(p));
    return a;
}
__device__ __forceinline__ void cp16(uint32_t s, const void* g) {
    asm volatile("cp.async.cg.shared.global [%0], [%1], 16;" :: "r"(s), "l"(g));
}
__device__ __forceinline__ void ldsm_x4(uint32_t* r, uint32_t addr) {
    asm volatile("ldmatrix.sync.aligned.m8n8.x4.shared.b16 {%0,%1,%2,%3}, [%4];"
        : "=r"(r[0]), "=r"(r[1]), "=r"(r[2]), "=r"(r[3]) : "r"(addr));
}
__device__ __forceinline__ void mma16816(float* d, const uint32_t* a, const uint32_t* b) {
    asm volatile(
        "mma.sync.aligned.m16n8k16.row.col.f32.bf16.bf16.f32 "
        "{%0,%1,%2,%3}, {%4,%5,%6,%7}, {%8,%9}, {%0,%1,%2,%3};"
        : "+f"(d[0]), "+f"(d[1]), "+f"(d[2]), "+f"(d[3])
        : "r"(a[0]), "r"(a[1]), "r"(a[2]), "r"(a[3]), "r"(b[0]), "r"(b[1]));
}
__device__ __forceinline__ void split2(float v, unsigned short& h, unsigned short& l) {
    __nv_bfloat16 hb = __float2bfloat16(v);
    __nv_bfloat16 lb = __float2bfloat16(v - __bfloat162float(hb));
    h = *(unsigned short*)&hb; l = *(unsigned short*)&lb;
}

// ================= device scratch =================
__device__ float g_logits[NTOT];
__device__ float g_flags[NTOT];
__device__ int   g_idx[BB*KSEL];
__device__ float g_gate[BB*KSEL];
__device__ float g_act[NTOT*CH];
__device__ float g_x [NTOK*HID];
__device__ float g_q [NTOK*HID];
__device__ float g_k [NTOK*HID];
__device__ float g_v [NTOK*HID];
__device__ float g_h1[NTOK*HID];
__device__ float g_lo[NTOK*HID];
__device__ float g_gb[NTOK*INTER];
__device__ float g_ub[NTOK*INTER];
__device__ double g_f0sum, g_selsum, g_predsum;
// bf16 split buffers (plain row-major)
__device__ __nv_bfloat16 g_Ahi[33554432];   // max: NTOT*HID
__device__ __nv_bfloat16 g_Alo[33554432];
__device__ __nv_bfloat16 g_Bhi[16777216];   // max: INTER*HID
__device__ __nv_bfloat16 g_Blo[16777216];

// ================= small kernels =================
__global__ void k_init() {
    int i = blockIdx.x*blockDim.x + threadIdx.x;
    if (i < NTOT) g_flags[i] = 0.f;
    if (i == 0) { g_f0sum = 0.0; g_selsum = 0.0; g_predsum = 0.0; }
}

__global__ void k_router(const float* __restrict__ hs, const float* __restrict__ rw) {
    int t = blockIdx.x;
    const float* row = hs + (size_t)t*HID;
    float s = 0.f;
    for (int i = threadIdx.x; i < HID; i += 256) s += row[i]*rw[i];
    __shared__ float red[256];
    red[threadIdx.x] = s; __syncthreads();
    for (int st = 128; st; st >>= 1) {
        if (threadIdx.x < st) red[threadIdx.x] += red[threadIdx.x+st];
        __syncthreads();
    }
    if (threadIdx.x == 0) {
        float l = red[0];
        g_logits[t] = l;
        float f0 = fmaxf(l, 0.f) + log1pf(expf(-fabsf(l)));
        atomicAdd(&g_f0sum, (double)f0);
    }
}

__global__ void k_topk() {
    int b = blockIdx.x;
    __shared__ float sv[TT];
    __shared__ int   si[TT];
    int tid = threadIdx.x;
    for (int i = tid; i < TT; i += 1024) { sv[i] = g_logits[b*TT + i]; si[i] = i; }
    __syncthreads();
    for (int k = 2; k <= TT; k <<= 1) {
        for (int j = k >> 1; j > 0; j >>= 1) {
            for (int i = tid; i < TT; i += 1024) {
                int ixj = i ^ j;
                if (ixj > i) {
                    float va = sv[i], vb = sv[ixj];
                    int ia = si[i], ib = si[ixj];
                    bool lij = (vb > va) || (vb == va && ib < ia);
                    bool lji = (va > vb) || (va == vb && ia < ib);
                    bool sw = ((i & k) == 0) ? lij : lji;
                    if (sw) { sv[i] = vb; sv[ixj] = va; si[i] = ib; si[ixj] = ia; }
                }
            }
            __syncthreads();
        }
    }
    for (int k = 2; k <= KSEL; k <<= 1) {
        for (int j = k >> 1; j > 0; j >>= 1) {
            if (tid < KSEL) {
                int i = tid, ixj = i ^ j;
                if (ixj > i) {
                    int ia = si[i], ib = si[ixj];
                    bool sw = ((i & k) == 0) ? (ib < ia) : (ia < ib);
                    if (sw) {
                        int ti = si[i]; si[i] = si[ixj]; si[ixj] = ti;
                        float tv = sv[i]; sv[i] = sv[ixj]; sv[ixj] = tv;
                    }
                }
            }
            __syncthreads();
        }
    }
    if (tid < KSEL) {
        int token = si[tid]; float val = sv[tid];
        g_idx[b*KSEL + tid] = token;
        g_gate[b*KSEL + tid] = 1.f/(1.f + expf(-val));
        g_flags[b*TT + token] = 1.f;
        atomicAdd(&g_selsum, (double)val);
    }
}

__global__ void k_pred2(const float* __restrict__ w2, const float* __restrict__ b2) {
    int warp = threadIdx.x >> 5, lane = threadIdx.x & 31;
    int t = blockIdx.x*8 + warp;
    const float* a = g_act + (size_t)t*CH;
    float s = 0.f;
    for (int i = lane; i < CH; i += 32) s += a[i]*w2[i];
    for (int o = 16; o; o >>= 1) s += __shfl_xor_sync(0xffffffffu, s, o);
    __shared__ float ps[8];
    if (lane == 0) {
        float p = s + b2[0];
        float tg = g_flags[t];
        ps[warp] = fmaxf(p, 0.f) - p*tg + log1pf(expf(-fabsf(p)));
    }
    __syncthreads();
    if (threadIdx.x == 0) {
        float tot = 0.f;
        for (int i = 0; i < 8; i++) tot += ps[i];
        atomicAdd(&g_predsum, (double)tot);
    }
}

__global__ void k_gather(const float* __restrict__ hs) {
    int bj = blockIdx.x, b = bj >> 9;
    int t = g_idx[bj];
    const float* src = hs + ((size_t)b*TT + t)*HID;
    float* dst = g_x + (size_t)bj*HID;
    int i = threadIdx.x*8;
    *(float4*)(dst+i)   = *(const float4*)(src+i);
    *(float4*)(dst+i+4) = *(const float4*)(src+i+4);
}

// rmsnorm -> directly emit bf16 hi/lo split (A operand)
__global__ void k_rms(const float* __restrict__ in, const float* __restrict__ w,
                      __nv_bfloat16* __restrict__ hi, __nv_bfloat16* __restrict__ lo) {
    int row = blockIdx.x;
    const float* src = in + (size_t)row*HID;
    int i = threadIdx.x*8;
    float4 a = *(const float4*)(src+i), b = *(const float4*)(src+i+4);
    float ss = a.x*a.x + a.y*a.y + a.z*a.z + a.w*a.w
             + b.x*b.x + b.y*b.y + b.z*b.z + b.w*b.w;
    __shared__ float red[256];
    red[threadIdx.x] = ss; __syncthreads();
    for (int st = 128; st; st >>= 1) {
        if (threadIdx.x < st) red[threadIdx.x] += red[threadIdx.x+st];
        __syncthreads();
    }
    float sc = 1.f/sqrtf(red[0]/(float)HID + 1e-6f);
    float4 w0 = *(const float4*)(w+i), w1 = *(const float4*)(w+i+4);
    float v[8] = {a.x*sc*w0.x, a.y*sc*w0.y, a.z*sc*w0.z, a.w*sc*w0.w,
                  b.x*sc*w1.x, b.y*sc*w1.y, b.z*sc*w1.z, b.w*sc*w1.w};
    unsigned short hv[8], lv[8];
#pragma unroll
    for (int j = 0; j < 8; j++) split2(v[j], hv[j], lv[j]);
    size_t base = (size_t)row*HID + i;
    *(uint4*)(hi + base) = *(uint4*)hv;
    *(uint4*)(lo + base) = *(uint4*)lv;
}

__global__ void k_rope() {
    int t256 = blockIdx.x*256 + threadIdx.x;   // [0, NTOK*NHEADS*64)
    int d = t256 & 63;
    int bh = t256 >> 6;
    int bj = bh >> 4, h = bh & 15;
    int pos = g_idx[bj];
    float ang = (float)pos * expf(-(float)d * 0.14391156831212787f);
    float c = cosf(ang), s = sinf(ang);
    size_t base = (size_t)bj*HID + h*HDIM;
    float q1 = g_q[base+d], q2 = g_q[base+d+64];
    g_q[base+d]    = q1*c - q2*s;
    g_q[base+d+64] = q2*c + q1*s;
    float k1 = g_k[base+d], k2 = g_k[base+d+64];
    g_k[base+d]    = k1*c - k2*s;
    g_k[base+d+64] = k2*c + k1*s;
}

// flash attention -> emits hi/lo split directly (A operand for O-proj)
__global__ void k_attn(__nv_bfloat16* __restrict__ ohi, __nv_bfloat16* __restrict__ olo) {
    extern __shared__ float sm[];
    float* Qs = sm;
    float* Ks = Qs + 64*129;
    float* Vs = Ks + 64*129;
    float* Ss = Vs + 64*129;
    int qt = blockIdx.x, bh = blockIdx.y;
    int b = bh >> 4, h = bh & 15;
    int tid = threadIdx.x;
    size_t headbase = (size_t)b*KSEL*HID + (size_t)h*HDIM;
    for (int u = tid; u < 64*32; u += 256) {
        int r = u >> 5, c4 = (u & 31) << 2;
        float4 v = *(const float4*)(g_q + headbase + (size_t)(qt*64+r)*HID + c4);
        Qs[r*129+c4+0] = v.x*0.08838834764831845f;
        Qs[r*129+c4+1] = v.y*0.08838834764831845f;
        Qs[r*129+c4+2] = v.z*0.08838834764831845f;
        Qs[r*129+c4+3] = v.w*0.08838834764831845f;
    }
    int r = tid >> 2, qq = tid & 3;
    float m = -INFINITY, l = 0.f;
    float acc[32];
#pragma unroll
    for (int i = 0; i < 32; i++) acc[i] = 0.f;
    for (int kt = 0; kt <= qt; ++kt) {
        __syncthreads();
        for (int u = tid; u < 64*32; u += 256) {
            int jr = u >> 5, c4 = (u & 31) << 2;
            float4 kv = *(const float4*)(g_k + headbase + (size_t)(kt*64+jr)*HID + c4);
            float4 vv = *(const float4*)(g_v + headbase + (size_t)(kt*64+jr)*HID + c4);
            Ks[jr*129+c4+0] = kv.x; Ks[jr*129+c4+1] = kv.y;
            Ks[jr*129+c4+2] = kv.z; Ks[jr*129+c4+3] = kv.w;
            Vs[jr*129+c4+0] = vv.x; Vs[jr*129+c4+1] = vv.y;
            Vs[jr*129+c4+2] = vv.z; Vs[jr*129+c4+3] = vv.w;
        }
        __syncthreads();
        float a[16];
#pragma unroll
        for (int jj = 0; jj < 16; jj++) a[jj] = 0.f;
        const float* qrow = Qs + r*129;
        for (int d0 = 0; d0 < 128; d0 += 4) {
            float q0 = qrow[d0], q1 = qrow[d0+1], q2 = qrow[d0+2], q3 = qrow[d0+3];
#pragma unroll
            for (int jj = 0; jj < 16; jj++) {
                const float* kp = Ks + (qq + (jj<<2))*129 + d0;
                a[jj] += q0*kp[0] + q1*kp[1] + q2*kp[2] + q3*kp[3];
            }
        }
        int qg = qt*64 + r;
        float sreg[16];
#pragma unroll
        for (int jj = 0; jj < 16; jj++) {
            int kg = kt*64 + qq + (jj<<2);
            sreg[jj] = (kg <= qg) ? a[jj] : -1e9f;
        }
        float mx = sreg[0];
#pragma unroll
        for (int jj = 1; jj < 16; jj++) mx = fmaxf(mx, sreg[jj]);
        mx = fmaxf(mx, __shfl_xor_sync(0xffffffffu, mx, 1));
        mx = fmaxf(mx, __shfl_xor_sync(0xffffffffu, mx, 2));
        float mn = fmaxf(m, mx);
        float corr = expf(m - mn);
        float ls = 0.f;
#pragma unroll
        for (int jj = 0; jj < 16; jj++) {
            float p = expf(sreg[jj] - mn);
            ls += p;
            Ss[r*65 + qq + (jj<<2)] = p;
        }
        ls += __shfl_xor_sync(0xffffffffu, ls, 1);
        ls += __shfl_xor_sync(0xffffffffu, ls, 2);
        l = l*corr + ls; m = mn;
        __syncwarp();
#pragma unroll
        for (int i = 0; i < 32; i++) acc[i] *= corr;
        for (int j = 0; j < 64; j++) {
            float pv = Ss[r*65 + j];
            const float* vp = Vs + j*129 + qq;
#pragma unroll
            for (int i = 0; i < 32; i++) acc[i] += pv * vp[i<<2];
        }
    }
    float inv = 1.f/l;
    size_t outb = headbase + (size_t)(qt*64+r)*HID + qq;
#pragma unroll
    for (int i = 0; i < 32; i++) {
        unsigned short hv, lv;
        split2(acc[i]*inv, hv, lv);
        *(unsigned short*)(ohi + outb + (i<<2)) = hv;
        *(unsigned short*)(olo + outb + (i<<2)) = lv;
    }
}

// silu(gate)*up -> emits hi/lo split directly (A operand for down-proj)
__global__ void k_silumul(__nv_bfloat16* __restrict__ hi, __nv_bfloat16* __restrict__ lo) {
    size_t i = ((size_t)blockIdx.x*256 + threadIdx.x)*8;
    float4 g0 = *(float4*)(g_gb+i),   u0 = *(float4*)(g_ub+i);
    float4 g1 = *(float4*)(g_gb+i+4), u1 = *(float4*)(g_ub+i+4);
    float v[8] = {
        g0.x/(1.f+expf(-g0.x))*u0.x, g0.y/(1.f+expf(-g0.y))*u0.y,
        g0.z/(1.f+expf(-g0.z))*u0.z, g0.w/(1.f+expf(-g0.w))*u0.w,
        g1.x/(1.f+expf(-g1.x))*u1.x, g1.y/(1.f+expf(-g1.y))*u1.y,
        g1.z/(1.f+expf(-g1.z))*u1.z, g1.w/(1.f+expf(-g1.w))*u1.w };
    unsigned short hv[8], lv[8];
#pragma unroll
    for (int j = 0; j < 8; j++) split2(v[j], hv[j], lv[j]);
    *(uint4*)(hi + i) = *(uint4*)hv;
    *(uint4*)(lo + i) = *(uint4*)lv;
}

__global__ void k_copy(const float* __restrict__ src, float* __restrict__ dst) {
    size_t i = ((size_t)blockIdx.x*256 + threadIdx.x)*4;
    *(float4*)(dst+i) = *(const float4*)(src+i);
}

__global__ void k_scatter(float* __restrict__ out) {
    int bj = blockIdx.x, b = bj >> 9;
    int t = g_idx[bj];
    float gt = g_gate[bj];
    float* dst = out + ((size_t)b*TT + t)*HID;
    const float* xp = g_x + (size_t)bj*HID;
    const float* lp = g_lo + (size_t)bj*HID;
    int i = threadIdx.x*8;
#pragma unroll
    for (int u = 0; u < 8; u++) {
        float xv = xp[i+u], lv = lp[i+u];
        dst[i+u] = xv + gt*(lv - xv);
    }
}

__global__ void k_final(float* out, long long N, long long out_size) {
    if (threadIdx.x == 0) {
        if (N   < out_size) out[N]   = (float)((g_f0sum - g_selsum)/(double)NTOT);
        if (N+1 < out_size) out[N+1] = (float)(g_predsum/(double)NTOT);
    }
}

// ======== fp32 -> bf16 hi/lo split (plain row-major) ========
__global__ void k_conv(const float* __restrict__ src, __nv_bfloat16* __restrict__ hi,
                       __nv_bfloat16* __restrict__ lo) {
    size_t base = ((size_t)blockIdx.x*256 + threadIdx.x)*8;
    const float4* s = (const float4*)(src + base);
    float4 x0 = s[0], x1 = s[1];
    float xs[8] = {x0.x, x0.y, x0.z, x0.w, x1.x, x1.y, x1.z, x1.w};
    unsigned short hv[8], lv[8];
#pragma unroll
    for (int j = 0; j < 8; j++) split2(xs[j], hv[j], lv[j]);
    *(uint4*)(hi + base) = *(uint4*)hv;
    *(uint4*)(lo + base) = *(uint4*)lv;
}

// ================= bf16 MMA GEMM: C[M,N] = A[M,K] @ B[N,K]^T =================
// CTA tile 128x256x32, 256 threads (8 warps 2m x 4n), warp tile 64x64.
// TERMS=3: split-precision (AhiBhi + AhiBlo + AloBhi). TERMS=1: plain bf16.
// 3-stage cp.async pipeline. smem rows padded to 40 bf16 (conflict-free ldmatrix).
// epi: 0 = +bias(if set); 1 = gelu(acc+bias); 2 = acc + add residual
#define PADK 40
#define A_BYTES   (128*PADK*2)          // 10240 per matrix
#define B_BYTES   (256*PADK*2)          // 20480 per matrix
#define STAGE_BYTES (2*A_BYTES + 2*B_BYTES)   // 61440
#define GEMM_SMEM (3*STAGE_BYTES)             // 184320

template<int TERMS>
__device__ __forceinline__ void load_stage(uint32_t sb, int stage,
    const __nv_bfloat16* Ah, const __nv_bfloat16* Al,
    const __nv_bfloat16* Bh, const __nv_bfloat16* Bl,
    int K, int kt, int tid)
{
    uint32_t s0 = sb + stage*STAGE_BYTES;
#pragma unroll
    for (int u = 0; u < 2; u++) {
        int c = tid + u*256;
        int row = c >> 2, seg = (c & 3) << 3;
        size_t g = (size_t)row*K + (size_t)kt*32 + seg;
        uint32_t sm = s0 + (row*PADK + seg)*2;
        cp16(sm, Ah + g);
        if (TERMS == 3) cp16(sm + A_BYTES, Al + g);
    }
#pragma unroll
    for (int u = 0; u < 4; u++) {
        int c = tid + u*256;
        int row = c >> 2, seg = (c & 3) << 3;
        size_t g = (size_t)row*K + (size_t)kt*32 + seg;
        uint32_t sm = s0 + 2*A_BYTES + (row*PADK + seg)*2;
        cp16(sm, Bh + g);
        if (TERMS == 3) cp16(sm + B_BYTES, Bl + g);
    }
    asm volatile("cp.async.commit_group;" ::: "memory");
}

template<int TERMS>
__global__ void __launch_bounds__(256, 1) tc_gemm(
    const __nv_bfloat16* __restrict__ Ahi, const __nv_bfloat16* __restrict__ Alo,
    const __nv_bfloat16* __restrict__ Bhi, const __nv_bfloat16* __restrict__ Blo,
    const float* __restrict__ bias, const float* __restrict__ add,
    float* __restrict__ C, int M, int N, int K, int epi)
{
    extern __shared__ __align__(16) char smem[];
    uint32_t sb = smem_to_u32(smem);
    const int tid = threadIdx.x, wid = tid >> 5, lane = tid & 31;
    const int wm = wid & 1, wn = wid >> 1;
    const long bm = (long)blockIdx.y << 7, bn = (long)blockIdx.x << 8;

    const __nv_bfloat16* pAh = Ahi + (size_t)bm*K;
    const __nv_bfloat16* pAl = Alo + (size_t)bm*K;
    const __nv_bfloat16* pBh = Bhi + (size_t)bn*K;
    const __nv_bfloat16* pBl = Blo + (size_t)bn*K;

    float acc[4][8][4];
#pragma unroll
    for (int mt = 0; mt < 4; mt++)
#pragma unroll
        for (int nt = 0; nt < 8; nt++)
#pragma unroll
            for (int i = 0; i < 4; i++) acc[mt][nt][i] = 0.f;

    const int NK = K >> 5;
    load_stage<TERMS>(sb, 0, pAh, pAl, pBh, pBl, K, 0, tid);
    load_stage<TERMS>(sb, 1, pAh, pAl, pBh, pBl, K, 1, tid);

    for (int kt = 0; kt < NK; ++kt) {
        if (kt + 2 < NK) {
            load_stage<TERMS>(sb, (kt+2)%3, pAh, pAl, pBh, pBl, K, kt+2, tid);
            asm volatile("cp.async.wait_group 2;" ::: "memory");
        } else {
            asm volatile("cp.async.wait_group 0;" ::: "memory");
        }
        __syncthreads();

        uint32_t s0 = sb + (kt%3)*STAGE_BYTES;
#pragma unroll
        for (int kk = 0; kk < 32; kk += 16) {
            // A fragments first: all 4 m-tiles, hi (+lo)
            uint32_t Ahf[4][4], Alf[4][4];
            const int arow = wm*64 + (lane & 15);
            const int acol = kk + ((lane >> 4) << 3);
#pragma unroll
            for (int mt = 0; mt < 4; mt++) {
                uint32_t ad = s0 + (uint32_t)((arow + mt*16)*PADK + acol)*2;
                ldsm_x4(Ahf[mt], ad);
                if (TERMS == 3) ldsm_x4(Alf[mt], ad + A_BYTES);
            }
            // B streamed in pairs of n-tiles
            const int brow = wn*64 + (lane & 7) + (((lane >> 4) & 1) << 3);
            const int bcol = kk + (((lane >> 3) & 1) << 3);
#pragma unroll
            for (int np = 0; np < 4; np++) {
                uint32_t Bh[4], Bl[4];
                uint32_t bd = s0 + 2*A_BYTES + (uint32_t)((brow + np*16)*PADK + bcol)*2;
                ldsm_x4(Bh, bd);
                if (TERMS == 3) ldsm_x4(Bl, bd + B_BYTES);
#pragma unroll
                for (int mt = 0; mt < 4; mt++) {
                    mma16816(acc[mt][np*2],   Ahf[mt], Bh);
                    mma16816(acc[mt][np*2+1], Ahf[mt], Bh+2);
                    if (TERMS == 3) {
                        mma16816(acc[mt][np*2],   Ahf[mt], Bl);
                        mma16816(acc[mt][np*2+1], Ahf[mt], Bl+2);
                        mma16816(acc[mt][np*2],   Alf[mt], Bh);
                        mma16816(acc[mt][np*2+1], Alf[mt], Bh+2);
                    }
                }
            }
        }
        __syncthreads();
    }

    // ---- epilogue ----
#pragma unroll
    for (int mt = 0; mt < 4; mt++) {
#pragma unroll
        for (int nt = 0; nt < 8; nt++) {
            long m = bm + wm*64 + mt*16 + (lane >> 2);
            long n = bn + wn*64 + nt*8 + ((lane & 3) << 1);
            float* a = acc[mt][nt];
            float b0 = bias ? bias[n] : 0.f;
            float b1 = bias ? bias[n+1] : 0.f;
            float v0 = a[0] + b0, v1 = a[1] + b1, v2 = a[2] + b0, v3 = a[3] + b1;
            if (epi == 1) {
                v0 = 0.5f*v0*(1.f + erff(v0*0.70710678118654752f));
                v1 = 0.5f*v1*(1.f + erff(v1*0.70710678118654752f));
                v2 = 0.5f*v2*(1.f + erff(v2*0.70710678118654752f));
                v3 = 0.5f*v3*(1.f + erff(v3*0.70710678118654752f));
            }
            if (epi == 2) {
                v0 += add[m*N + n];     v1 += add[m*N + n + 1];
                v2 += add[(m+8)*N + n]; v3 += add[(m+8)*N + n + 1];
            }
            *(float2*)(C + m*N + n)     = make_float2(v0, v1);
            *(float2*)(C + (m+8)*N + n) = make_float2(v2, v3);
        }
    }
}

// ================= launch =================
extern "C" void kernel_launch(void* const* d_in, const int* in_sizes, int n_in,
                              void* d_out, int out_size) {
    const float* hs     = (const float*)d_in[0];
    const float* rw     = (const float*)d_in[1];
    const float* cfc1_w = (const float*)d_in[2];
    const float* cfc1_b = (const float*)d_in[3];
    const float* cfc2_w = (const float*)d_in[4];
    const float* cfc2_b = (const float*)d_in[5];
    const float* ln1    = (const float*)d_in[6];
    const float* ln2    = (const float*)d_in[7];
    const float* q_w    = (const float*)d_in[8];
    const float* q_b    = (const float*)d_in[9];
    const float* k_w    = (const float*)d_in[10];
    const float* k_b    = (const float*)d_in[11];
    const float* v_w    = (const float*)d_in[12];
    const float* v_b    = (const float*)d_in[13];
    const float* o_w    = (const float*)d_in[14];
    const float* gate_w = (const float*)d_in[15];
    const float* up_w   = (const float*)d_in[16];
    const float* down_w = (const float*)d_in[17];
    float* out = (float*)d_out;

    float *px, *pq, *pk, *pv, *ph1, *plo, *pgb, *pub, *pact;
    cudaGetSymbolAddress((void**)&px,  g_x);
    cudaGetSymbolAddress((void**)&pq,  g_q);
    cudaGetSymbolAddress((void**)&pk,  g_k);
    cudaGetSymbolAddress((void**)&pv,  g_v);
    cudaGetSymbolAddress((void**)&ph1, g_h1);
    cudaGetSymbolAddress((void**)&plo, g_lo);
    cudaGetSymbolAddress((void**)&pgb, g_gb);
    cudaGetSymbolAddress((void**)&pub, g_ub);
    cudaGetSymbolAddress((void**)&pact, g_act);
    __nv_bfloat16 *pAhi, *pAlo, *pBhi, *pBlo;
    cudaGetSymbolAddress((void**)&pAhi, g_Ahi);
    cudaGetSymbolAddress((void**)&pAlo, g_Alo);
    cudaGetSymbolAddress((void**)&pBhi, g_Bhi);
    cudaGetSymbolAddress((void**)&pBlo, g_Blo);

    cudaFuncSetAttribute(tc_gemm<3>, cudaFuncAttributeMaxDynamicSharedMemorySize, GEMM_SMEM);
    cudaFuncSetAttribute(tc_gemm<1>, cudaFuncAttributeMaxDynamicSharedMemorySize, GEMM_SMEM);
    const int ATTN_SMEM = (3*64*129 + 64*65)*4;
    cudaFuncSetAttribute(k_attn, cudaFuncAttributeMaxDynamicSharedMemorySize, ATTN_SMEM);

#define CONV(src, hi, lo, R, K) k_conv<<<((size_t)(R)*(K)/8)/256, 256>>>(src, hi, lo)
#define GEMM(M, N, K, bias, add, Cp, epi) \
    tc_gemm<3><<<dim3((N)/256, (M)/128), 256, GEMM_SMEM>>>(pAhi, pAlo, pBhi, pBlo, bias, add, Cp, M, N, K, epi)
#define GEMM1(M, N, K, bias, add, Cp, epi) \
    tc_gemm<1><<<dim3((N)/256, (M)/128), 256, GEMM_SMEM>>>(pAhi, pAlo, pBhi, pBlo, bias, add, Cp, M, N, K, epi)

    k_init<<<64, 256>>>();
    k_router<<<NTOT, 256>>>(hs, rw);
    k_topk<<<BB, 1024>>>();

    // predictor: gelu(hs @ cfc1^T + b1) -> g_act ; then BCE (loss-only: 1-term bf16)
    CONV(hs, pAhi, pAlo, NTOT, HID);
    CONV(cfc1_w, pBhi, pBlo, CH, HID);
    GEMM1(NTOT, CH, HID, cfc1_b, nullptr, pact, 1);
    k_pred2<<<NTOT/8, 256>>>(cfc2_w, cfc2_b);

    // gather + rmsnorm1 (emits split A directly)
    k_gather<<<NTOK, 256>>>(hs);
    k_rms<<<NTOK, 256>>>(px, ln1, pAhi, pAlo);

    // QKV
    CONV(q_w, pBhi, pBlo, HID, HID);
    GEMM(NTOK, HID, HID, q_b, nullptr, pq, 0);
    CONV(k_w, pBhi, pBlo, HID, HID);
    GEMM(NTOK, HID, HID, k_b, nullptr, pk, 0);
    CONV(v_w, pBhi, pBlo, HID, HID);
    GEMM(NTOK, HID, HID, v_b, nullptr, pv, 0);
    k_rope<<<(NTOK*NHEADS*64)/256, 256>>>();

    // attention (emits split A for O-proj)
    k_attn<<<dim3(KSEL/64, BB*NHEADS), 256, ATTN_SMEM>>>(pAhi, pAlo);

    // O-proj + residual -> h1 ; rmsnorm2 emits split A for MLP
    CONV(o_w, pBhi, pBlo, HID, HID);
    GEMM(NTOK, HID, HID, nullptr, px, ph1, 2);
    k_rms<<<NTOK, 256>>>(ph1, ln2, pAhi, pAlo);

    // MLP
    CONV(gate_w, pBhi, pBlo, INTER, HID);
    GEMM(NTOK, INTER, HID, nullptr, nullptr, pgb, 0);
    CONV(up_w, pBhi, pBlo, INTER, HID);
    GEMM(NTOK, INTER, HID, nullptr, nullptr, pub, 0);
    k_silumul<<<(NTOK*(INTER/8))/256, 256>>>(pAhi, pAlo);
    CONV(down_w, pBhi, pBlo, HID, INTER);
    GEMM(NTOK, HID, INTER, nullptr, ph1, plo, 2);

    // output
    k_copy<<<((size_t)NTOT*HID/4)/256, 256>>>(hs, out);
    k_scatter<<<NTOK, 256>>>(out);
    k_final<<<1, 32>>>(out, (long long)NTOT*HID, (long long)out_size);
}

// round 7
// speedup vs baseline: 3.1579x; 1.3057x over previous
#include <cuda_runtime.h>
#include <cuda_fp16.h>
#include <stdint.h>
#include <math.h>

#define BB     4
#define TT     4096
#define HID    2048
#define NHEADS 16
#define HDIM   128
#define INTER  8192
#define KSEL   512
#define NTOK   (BB*KSEL)
#define NTOT   (BB*TT)
#define CH     (HID/4)

// ================= helpers =================
__device__ __forceinline__ uint32_t smem_to_u32(const void* p) {
    uint32_t a;
    asm("{ .reg .u64 t; cvta.to.shared.u64 t, %1; cvt.u32.u64 %0, t; }" : "=r"(a) : "l"(p));
    return a;
}
__device__ __forceinline__ void cp16(uint32_t s, const void* g) {
    asm volatile("cp.async.cg.shared.global [%0], [%1], 16;" :: "r"(s), "l"(g));
}
__device__ __forceinline__ void ldsm_x4(uint32_t* r, uint32_t addr) {
    asm volatile("ldmatrix.sync.aligned.m8n8.x4.shared.b16 {%0,%1,%2,%3}, [%4];"
        : "=r"(r[0]), "=r"(r[1]), "=r"(r[2]), "=r"(r[3]) : "r"(addr));
}
__device__ __forceinline__ void mma16816(float* d, const uint32_t* a, const uint32_t* b) {
    asm volatile(
        "mma.sync.aligned.m16n8k16.row.col.f32.f16.f16.f32 "
        "{%0,%1,%2,%3}, {%4,%5,%6,%7}, {%8,%9}, {%0,%1,%2,%3};"
        : "+f"(d[0]), "+f"(d[1]), "+f"(d[2]), "+f"(d[3])
        : "r"(a[0]), "r"(a[1]), "r"(a[2]), "r"(a[3]), "r"(b[0]), "r"(b[1]));
}
// fp16 hi/lo split: hi+lo captures ~22 mantissa bits of v
__device__ __forceinline__ void split2(float v, unsigned short& h, unsigned short& l) {
    __half hb = __float2half_rn(v);
    __half lb = __float2half_rn(v - __half2float(hb));
    h = *(unsigned short*)&hb; l = *(unsigned short*)&lb;
}

// ================= device scratch =================
__device__ float g_logits[NTOT];
__device__ float g_flags[NTOT];
__device__ int   g_idx[BB*KSEL];
__device__ float g_gate[BB*KSEL];
__device__ float g_act[NTOT*CH];
__device__ float g_x [NTOK*HID];
__device__ float g_q [NTOK*HID];
__device__ float g_k [NTOK*HID];
__device__ float g_v [NTOK*HID];
__device__ float g_h1[NTOK*HID];
__device__ float g_lo[NTOK*HID];
__device__ float g_gb[NTOK*INTER];
__device__ float g_ub[NTOK*INTER];
__device__ double g_f0sum, g_selsum, g_predsum;
// fp16 operand buffers (plain row-major)
__device__ __half g_Ahi[33554432];   // max: NTOT*HID
__device__ __half g_Alo[33554432];
__device__ __half g_Bhi[16777216];   // max: INTER*HID

// ================= small kernels =================
__global__ void k_init() {
    int i = blockIdx.x*blockDim.x + threadIdx.x;
    if (i < NTOT) g_flags[i] = 0.f;
    if (i == 0) { g_f0sum = 0.0; g_selsum = 0.0; g_predsum = 0.0; }
}

__global__ void k_router(const float* __restrict__ hs, const float* __restrict__ rw) {
    int t = blockIdx.x;
    const float* row = hs + (size_t)t*HID;
    float s = 0.f;
    for (int i = threadIdx.x; i < HID; i += 256) s += row[i]*rw[i];
    __shared__ float red[256];
    red[threadIdx.x] = s; __syncthreads();
    for (int st = 128; st; st >>= 1) {
        if (threadIdx.x < st) red[threadIdx.x] += red[threadIdx.x+st];
        __syncthreads();
    }
    if (threadIdx.x == 0) {
        float l = red[0];
        g_logits[t] = l;
        float f0 = fmaxf(l, 0.f) + log1pf(expf(-fabsf(l)));
        atomicAdd(&g_f0sum, (double)f0);
    }
}

__global__ void k_topk() {
    int b = blockIdx.x;
    __shared__ float sv[TT];
    __shared__ int   si[TT];
    int tid = threadIdx.x;
    for (int i = tid; i < TT; i += 1024) { sv[i] = g_logits[b*TT + i]; si[i] = i; }
    __syncthreads();
    for (int k = 2; k <= TT; k <<= 1) {
        for (int j = k >> 1; j > 0; j >>= 1) {
            for (int i = tid; i < TT; i += 1024) {
                int ixj = i ^ j;
                if (ixj > i) {
                    float va = sv[i], vb = sv[ixj];
                    int ia = si[i], ib = si[ixj];
                    bool lij = (vb > va) || (vb == va && ib < ia);
                    bool lji = (va > vb) || (va == vb && ia < ib);
                    bool sw = ((i & k) == 0) ? lij : lji;
                    if (sw) { sv[i] = vb; sv[ixj] = va; si[i] = ib; si[ixj] = ia; }
                }
            }
            __syncthreads();
        }
    }
    for (int k = 2; k <= KSEL; k <<= 1) {
        for (int j = k >> 1; j > 0; j >>= 1) {
            if (tid < KSEL) {
                int i = tid, ixj = i ^ j;
                if (ixj > i) {
                    int ia = si[i], ib = si[ixj];
                    bool sw = ((i & k) == 0) ? (ib < ia) : (ia < ib);
                    if (sw) {
                        int ti = si[i]; si[i] = si[ixj]; si[ixj] = ti;
                        float tv = sv[i]; sv[i] = sv[ixj]; sv[ixj] = tv;
                    }
                }
            }
            __syncthreads();
        }
    }
    if (tid < KSEL) {
        int token = si[tid]; float val = sv[tid];
        g_idx[b*KSEL + tid] = token;
        g_gate[b*KSEL + tid] = 1.f/(1.f + expf(-val));
        g_flags[b*TT + token] = 1.f;
        atomicAdd(&g_selsum, (double)val);
    }
}

__global__ void k_pred2(const float* __restrict__ w2, const float* __restrict__ b2) {
    int warp = threadIdx.x >> 5, lane = threadIdx.x & 31;
    int t = blockIdx.x*8 + warp;
    const float* a = g_act + (size_t)t*CH;
    float s = 0.f;
    for (int i = lane; i < CH; i += 32) s += a[i]*w2[i];
    for (int o = 16; o; o >>= 1) s += __shfl_xor_sync(0xffffffffu, s, o);
    __shared__ float ps[8];
    if (lane == 0) {
        float p = s + b2[0];
        float tg = g_flags[t];
        ps[warp] = fmaxf(p, 0.f) - p*tg + log1pf(expf(-fabsf(p)));
    }
    __syncthreads();
    if (threadIdx.x == 0) {
        float tot = 0.f;
        for (int i = 0; i < 8; i++) tot += ps[i];
        atomicAdd(&g_predsum, (double)tot);
    }
}

__global__ void k_gather(const float* __restrict__ hs) {
    int bj = blockIdx.x, b = bj >> 9;
    int t = g_idx[bj];
    const float* src = hs + ((size_t)b*TT + t)*HID;
    float* dst = g_x + (size_t)bj*HID;
    int i = threadIdx.x*8;
    *(float4*)(dst+i)   = *(const float4*)(src+i);
    *(float4*)(dst+i+4) = *(const float4*)(src+i+4);
}

// rmsnorm -> directly emit fp16 hi/lo split (A operand)
__global__ void k_rms(const float* __restrict__ in, const float* __restrict__ w,
                      __half* __restrict__ hi, __half* __restrict__ lo) {
    int row = blockIdx.x;
    const float* src = in + (size_t)row*HID;
    int i = threadIdx.x*8;
    float4 a = *(const float4*)(src+i), b = *(const float4*)(src+i+4);
    float ss = a.x*a.x + a.y*a.y + a.z*a.z + a.w*a.w
             + b.x*b.x + b.y*b.y + b.z*b.z + b.w*b.w;
    __shared__ float red[256];
    red[threadIdx.x] = ss; __syncthreads();
    for (int st = 128; st; st >>= 1) {
        if (threadIdx.x < st) red[threadIdx.x] += red[threadIdx.x+st];
        __syncthreads();
    }
    float sc = 1.f/sqrtf(red[0]/(float)HID + 1e-6f);
    float4 w0 = *(const float4*)(w+i), w1 = *(const float4*)(w+i+4);
    float v[8] = {a.x*sc*w0.x, a.y*sc*w0.y, a.z*sc*w0.z, a.w*sc*w0.w,
                  b.x*sc*w1.x, b.y*sc*w1.y, b.z*sc*w1.z, b.w*sc*w1.w};
    unsigned short hv[8], lv[8];
#pragma unroll
    for (int j = 0; j < 8; j++) split2(v[j], hv[j], lv[j]);
    size_t base = (size_t)row*HID + i;
    *(uint4*)(hi + base) = *(uint4*)hv;
    *(uint4*)(lo + base) = *(uint4*)lv;
}

__global__ void k_rope() {
    int t256 = blockIdx.x*256 + threadIdx.x;
    int d = t256 & 63;
    int bh = t256 >> 6;
    int bj = bh >> 4, h = bh & 15;
    int pos = g_idx[bj];
    float ang = (float)pos * expf(-(float)d * 0.14391156831212787f);
    float c = cosf(ang), s = sinf(ang);
    size_t base = (size_t)bj*HID + h*HDIM;
    float q1 = g_q[base+d], q2 = g_q[base+d+64];
    g_q[base+d]    = q1*c - q2*s;
    g_q[base+d+64] = q2*c + q1*s;
    float k1 = g_k[base+d], k2 = g_k[base+d+64];
    g_k[base+d]    = k1*c - k2*s;
    g_k[base+d+64] = k2*c + k1*s;
}

// flash attention -> emits fp16 hi/lo split directly (A operand for O-proj)
__global__ void k_attn(__half* __restrict__ ohi, __half* __restrict__ olo) {
    extern __shared__ float sm[];
    float* Qs = sm;
    float* Ks = Qs + 64*129;
    float* Vs = Ks + 64*129;
    float* Ss = Vs + 64*129;
    int qt = blockIdx.x, bh = blockIdx.y;
    int b = bh >> 4, h = bh & 15;
    int tid = threadIdx.x;
    size_t headbase = (size_t)b*KSEL*HID + (size_t)h*HDIM;
    for (int u = tid; u < 64*32; u += 256) {
        int r = u >> 5, c4 = (u & 31) << 2;
        float4 v = *(const float4*)(g_q + headbase + (size_t)(qt*64+r)*HID + c4);
        Qs[r*129+c4+0] = v.x*0.08838834764831845f;
        Qs[r*129+c4+1] = v.y*0.08838834764831845f;
        Qs[r*129+c4+2] = v.z*0.08838834764831845f;
        Qs[r*129+c4+3] = v.w*0.08838834764831845f;
    }
    int r = tid >> 2, qq = tid & 3;
    float m = -INFINITY, l = 0.f;
    float acc[32];
#pragma unroll
    for (int i = 0; i < 32; i++) acc[i] = 0.f;
    for (int kt = 0; kt <= qt; ++kt) {
        __syncthreads();
        for (int u = tid; u < 64*32; u += 256) {
            int jr = u >> 5, c4 = (u & 31) << 2;
            float4 kv = *(const float4*)(g_k + headbase + (size_t)(kt*64+jr)*HID + c4);
            float4 vv = *(const float4*)(g_v + headbase + (size_t)(kt*64+jr)*HID + c4);
            Ks[jr*129+c4+0] = kv.x; Ks[jr*129+c4+1] = kv.y;
            Ks[jr*129+c4+2] = kv.z; Ks[jr*129+c4+3] = kv.w;
            Vs[jr*129+c4+0] = vv.x; Vs[jr*129+c4+1] = vv.y;
            Vs[jr*129+c4+2] = vv.z; Vs[jr*129+c4+3] = vv.w;
        }
        __syncthreads();
        float a[16];
#pragma unroll
        for (int jj = 0; jj < 16; jj++) a[jj] = 0.f;
        const float* qrow = Qs + r*129;
        for (int d0 = 0; d0 < 128; d0 += 4) {
            float q0 = qrow[d0], q1 = qrow[d0+1], q2 = qrow[d0+2], q3 = qrow[d0+3];
#pragma unroll
            for (int jj = 0; jj < 16; jj++) {
                const float* kp = Ks + (qq + (jj<<2))*129 + d0;
                a[jj] += q0*kp[0] + q1*kp[1] + q2*kp[2] + q3*kp[3];
            }
        }
        int qg = qt*64 + r;
        float sreg[16];
#pragma unroll
        for (int jj = 0; jj < 16; jj++) {
            int kg = kt*64 + qq + (jj<<2);
            sreg[jj] = (kg <= qg) ? a[jj] : -1e9f;
        }
        float mx = sreg[0];
#pragma unroll
        for (int jj = 1; jj < 16; jj++) mx = fmaxf(mx, sreg[jj]);
        mx = fmaxf(mx, __shfl_xor_sync(0xffffffffu, mx, 1));
        mx = fmaxf(mx, __shfl_xor_sync(0xffffffffu, mx, 2));
        float mn = fmaxf(m, mx);
        float corr = expf(m - mn);
        float ls = 0.f;
#pragma unroll
        for (int jj = 0; jj < 16; jj++) {
            float p = expf(sreg[jj] - mn);
            ls += p;
            Ss[r*65 + qq + (jj<<2)] = p;
        }
        ls += __shfl_xor_sync(0xffffffffu, ls, 1);
        ls += __shfl_xor_sync(0xffffffffu, ls, 2);
        l = l*corr + ls; m = mn;
        __syncwarp();
#pragma unroll
        for (int i = 0; i < 32; i++) acc[i] *= corr;
        for (int j = 0; j < 64; j++) {
            float pv = Ss[r*65 + j];
            const float* vp = Vs + j*129 + qq;
#pragma unroll
            for (int i = 0; i < 32; i++) acc[i] += pv * vp[i<<2];
        }
    }
    float inv = 1.f/l;
    size_t outb = headbase + (size_t)(qt*64+r)*HID + qq;
#pragma unroll
    for (int i = 0; i < 32; i++) {
        unsigned short hv, lv;
        split2(acc[i]*inv, hv, lv);
        *(unsigned short*)(ohi + outb + (i<<2)) = hv;
        *(unsigned short*)(olo + outb + (i<<2)) = lv;
    }
}

// silu(gate)*up -> emits fp16 hi/lo split directly (A operand for down-proj)
__global__ void k_silumul(__half* __restrict__ hi, __half* __restrict__ lo) {
    size_t i = ((size_t)blockIdx.x*256 + threadIdx.x)*8;
    float4 g0 = *(float4*)(g_gb+i),   u0 = *(float4*)(g_ub+i);
    float4 g1 = *(float4*)(g_gb+i+4), u1 = *(float4*)(g_ub+i+4);
    float v[8] = {
        g0.x/(1.f+expf(-g0.x))*u0.x, g0.y/(1.f+expf(-g0.y))*u0.y,
        g0.z/(1.f+expf(-g0.z))*u0.z, g0.w/(1.f+expf(-g0.w))*u0.w,
        g1.x/(1.f+expf(-g1.x))*u1.x, g1.y/(1.f+expf(-g1.y))*u1.y,
        g1.z/(1.f+expf(-g1.z))*u1.z, g1.w/(1.f+expf(-g1.w))*u1.w };
    unsigned short hv[8], lv[8];
#pragma unroll
    for (int j = 0; j < 8; j++) split2(v[j], hv[j], lv[j]);
    *(uint4*)(hi + i) = *(uint4*)hv;
    *(uint4*)(lo + i) = *(uint4*)lv;
}

__global__ void k_copy(const float* __restrict__ src, float* __restrict__ dst) {
    size_t i = ((size_t)blockIdx.x*256 + threadIdx.x)*4;
    *(float4*)(dst+i) = *(const float4*)(src+i);
}

__global__ void k_scatter(float* __restrict__ out) {
    int bj = blockIdx.x, b = bj >> 9;
    int t = g_idx[bj];
    float gt = g_gate[bj];
    float* dst = out + ((size_t)b*TT + t)*HID;
    const float* xp = g_x + (size_t)bj*HID;
    const float* lp = g_lo + (size_t)bj*HID;
    int i = threadIdx.x*8;
#pragma unroll
    for (int u = 0; u < 8; u++) {
        float xv = xp[i+u], lv = lp[i+u];
        dst[i+u] = xv + gt*(lv - xv);
    }
}

__global__ void k_final(float* out, long long N, long long out_size) {
    if (threadIdx.x == 0) {
        if (N   < out_size) out[N]   = (float)((g_f0sum - g_selsum)/(double)NTOT);
        if (N+1 < out_size) out[N+1] = (float)(g_predsum/(double)NTOT);
    }
}

// ======== fp32 -> fp16 cast (single output; used for weights + predictor A) ========
__global__ void k_convB(const float* __restrict__ src, __half* __restrict__ dst) {
    size_t base = ((size_t)blockIdx.x*256 + threadIdx.x)*8;
    const float4* s = (const float4*)(src + base);
    float4 x0 = s[0], x1 = s[1];
    float xs[8] = {x0.x, x0.y, x0.z, x0.w, x1.x, x1.y, x1.z, x1.w};
    unsigned short hv[8];
#pragma unroll
    for (int j = 0; j < 8; j++) {
        __half hb = __float2half_rn(xs[j]);
        hv[j] = *(unsigned short*)&hb;
    }
    *(uint4*)(dst + base) = *(uint4*)hv;
}

// ================= fp16 MMA GEMM: C[M,N] = A[M,K] @ B[N,K]^T =================
// CTA tile 128x256x32, 256 threads (8 warps 2m x 4n), warp tile 64x64.
// TERMS=2: A split fp16 hi/lo (Ahi*B + Alo*B). TERMS=1: plain fp16.
// B is single fp16 in both modes.
// 3-stage cp.async pipeline. smem rows padded to 40 halves (conflict-free ldmatrix).
// epi: 0 = +bias(if set); 1 = gelu(acc+bias); 2 = acc + add residual
#define PADK 40
#define A_BYTES   (128*PADK*2)                 // 10240 per matrix
#define B_BYTES   (256*PADK*2)                 // 20480
#define STAGE_BYTES (2*A_BYTES + B_BYTES)      // 40960
#define GEMM_SMEM (3*STAGE_BYTES)              // 122880

template<int TERMS>
__device__ __forceinline__ void load_stage(uint32_t sb, int stage,
    const __half* Ah, const __half* Al, const __half* Bh,
    int K, int kt, int tid)
{
    uint32_t s0 = sb + stage*STAGE_BYTES;
#pragma unroll
    for (int u = 0; u < 2; u++) {
        int c = tid + u*256;
        int row = c >> 2, seg = (c & 3) << 3;
        size_t g = (size_t)row*K + (size_t)kt*32 + seg;
        uint32_t sm = s0 + (row*PADK + seg)*2;
        cp16(sm, Ah + g);
        if (TERMS == 2) cp16(sm + A_BYTES, Al + g);
    }
#pragma unroll
    for (int u = 0; u < 4; u++) {
        int c = tid + u*256;
        int row = c >> 2, seg = (c & 3) << 3;
        size_t g = (size_t)row*K + (size_t)kt*32 + seg;
        cp16(s0 + 2*A_BYTES + (row*PADK + seg)*2, Bh + g);
    }
    asm volatile("cp.async.commit_group;" ::: "memory");
}

template<int TERMS>
__global__ void __launch_bounds__(256, 1) tc_gemm(
    const __half* __restrict__ Ahi, const __half* __restrict__ Alo,
    const __half* __restrict__ Bhi,
    const float* __restrict__ bias, const float* __restrict__ add,
    float* __restrict__ C, int M, int N, int K, int epi)
{
    extern __shared__ __align__(16) char smem[];
    uint32_t sb = smem_to_u32(smem);
    const int tid = threadIdx.x, wid = tid >> 5, lane = tid & 31;
    const int wm = wid & 1, wn = wid >> 1;
    const long bm = (long)blockIdx.y << 7, bn = (long)blockIdx.x << 8;

    const __half* pAh = Ahi + (size_t)bm*K;
    const __half* pAl = Alo + (size_t)bm*K;
    const __half* pBh = Bhi + (size_t)bn*K;

    float acc[4][8][4];
#pragma unroll
    for (int mt = 0; mt < 4; mt++)
#pragma unroll
        for (int nt = 0; nt < 8; nt++)
#pragma unroll
            for (int i = 0; i < 4; i++) acc[mt][nt][i] = 0.f;

    const int NK = K >> 5;
    load_stage<TERMS>(sb, 0, pAh, pAl, pBh, K, 0, tid);
    load_stage<TERMS>(sb, 1, pAh, pAl, pBh, K, 1, tid);

    for (int kt = 0; kt < NK; ++kt) {
        if (kt + 2 < NK) {
            load_stage<TERMS>(sb, (kt+2)%3, pAh, pAl, pBh, K, kt+2, tid);
            asm volatile("cp.async.wait_group 2;" ::: "memory");
        } else {
            asm volatile("cp.async.wait_group 0;" ::: "memory");
        }
        __syncthreads();

        uint32_t s0 = sb + (kt%3)*STAGE_BYTES;
#pragma unroll
        for (int kk = 0; kk < 32; kk += 16) {
            // A fragments: all 4 m-tiles, hi (+lo)
            uint32_t Ahf[4][4], Alf[4][4];
            const int arow = wm*64 + (lane & 15);
            const int acol = kk + ((lane >> 4) << 3);
#pragma unroll
            for (int mt = 0; mt < 4; mt++) {
                uint32_t ad = s0 + (uint32_t)((arow + mt*16)*PADK + acol)*2;
                ldsm_x4(Ahf[mt], ad);
                if (TERMS == 2) ldsm_x4(Alf[mt], ad + A_BYTES);
            }
            // B streamed in pairs of n-tiles
            const int brow = wn*64 + (lane & 7) + (((lane >> 4) & 1) << 3);
            const int bcol = kk + (((lane >> 3) & 1) << 3);
#pragma unroll
            for (int np = 0; np < 4; np++) {
                uint32_t Bh[4];
                ldsm_x4(Bh, s0 + 2*A_BYTES + (uint32_t)((brow + np*16)*PADK + bcol)*2);
#pragma unroll
                for (int mt = 0; mt < 4; mt++) {
                    mma16816(acc[mt][np*2],   Ahf[mt], Bh);
                    mma16816(acc[mt][np*2+1], Ahf[mt], Bh+2);
                    if (TERMS == 2) {
                        mma16816(acc[mt][np*2],   Alf[mt], Bh);
                        mma16816(acc[mt][np*2+1], Alf[mt], Bh+2);
                    }
                }
            }
        }
        __syncthreads();
    }

    // ---- epilogue ----
#pragma unroll
    for (int mt = 0; mt < 4; mt++) {
#pragma unroll
        for (int nt = 0; nt < 8; nt++) {
            long m = bm + wm*64 + mt*16 + (lane >> 2);
            long n = bn + wn*64 + nt*8 + ((lane & 3) << 1);
            float* a = acc[mt][nt];
            float b0 = bias ? bias[n] : 0.f;
            float b1 = bias ? bias[n+1] : 0.f;
            float v0 = a[0] + b0, v1 = a[1] + b1, v2 = a[2] + b0, v3 = a[3] + b1;
            if (epi == 1) {
                v0 = 0.5f*v0*(1.f + erff(v0*0.70710678118654752f));
                v1 = 0.5f*v1*(1.f + erff(v1*0.70710678118654752f));
                v2 = 0.5f*v2*(1.f + erff(v2*0.70710678118654752f));
                v3 = 0.5f*v3*(1.f + erff(v3*0.70710678118654752f));
            }
            if (epi == 2) {
                v0 += add[m*N + n];     v1 += add[m*N + n + 1];
                v2 += add[(m+8)*N + n]; v3 += add[(m+8)*N + n + 1];
            }
            *(float2*)(C + m*N + n)     = make_float2(v0, v1);
            *(float2*)(C + (m+8)*N + n) = make_float2(v2, v3);
        }
    }
}

// ================= launch =================
extern "C" void kernel_launch(void* const* d_in, const int* in_sizes, int n_in,
                              void* d_out, int out_size) {
    const float* hs     = (const float*)d_in[0];
    const float* rw     = (const float*)d_in[1];
    const float* cfc1_w = (const float*)d_in[2];
    const float* cfc1_b = (const float*)d_in[3];
    const float* cfc2_w = (const float*)d_in[4];
    const float* cfc2_b = (const float*)d_in[5];
    const float* ln1    = (const float*)d_in[6];
    const float* ln2    = (const float*)d_in[7];
    const float* q_w    = (const float*)d_in[8];
    const float* q_b    = (const float*)d_in[9];
    const float* k_w    = (const float*)d_in[10];
    const float* k_b    = (const float*)d_in[11];
    const float* v_w    = (const float*)d_in[12];
    const float* v_b    = (const float*)d_in[13];
    const float* o_w    = (const float*)d_in[14];
    const float* gate_w = (const float*)d_in[15];
    const float* up_w   = (const float*)d_in[16];
    const float* down_w = (const float*)d_in[17];
    float* out = (float*)d_out;

    float *px, *pq, *pk, *pv, *ph1, *plo, *pgb, *pub, *pact;
    cudaGetSymbolAddress((void**)&px,  g_x);
    cudaGetSymbolAddress((void**)&pq,  g_q);
    cudaGetSymbolAddress((void**)&pk,  g_k);
    cudaGetSymbolAddress((void**)&pv,  g_v);
    cudaGetSymbolAddress((void**)&ph1, g_h1);
    cudaGetSymbolAddress((void**)&plo, g_lo);
    cudaGetSymbolAddress((void**)&pgb, g_gb);
    cudaGetSymbolAddress((void**)&pub, g_ub);
    cudaGetSymbolAddress((void**)&pact, g_act);
    __half *pAhi, *pAlo, *pBhi;
    cudaGetSymbolAddress((void**)&pAhi, g_Ahi);
    cudaGetSymbolAddress((void**)&pAlo, g_Alo);
    cudaGetSymbolAddress((void**)&pBhi, g_Bhi);

    cudaFuncSetAttribute(tc_gemm<2>, cudaFuncAttributeMaxDynamicSharedMemorySize, GEMM_SMEM);
    cudaFuncSetAttribute(tc_gemm<1>, cudaFuncAttributeMaxDynamicSharedMemorySize, GEMM_SMEM);
    const int ATTN_SMEM = (3*64*129 + 64*65)*4;
    cudaFuncSetAttribute(k_attn, cudaFuncAttributeMaxDynamicSharedMemorySize, ATTN_SMEM);

#define CONVB(src, dst, R, K) k_convB<<<((size_t)(R)*(K)/8)/256, 256>>>(src, dst)
#define GEMM(M, N, K, bias, add, Cp, epi) \
    tc_gemm<2><<<dim3((N)/256, (M)/128), 256, GEMM_SMEM>>>(pAhi, pAlo, pBhi, bias, add, Cp, M, N, K, epi)
#define GEMM1(M, N, K, bias, add, Cp, epi) \
    tc_gemm<1><<<dim3((N)/256, (M)/128), 256, GEMM_SMEM>>>(pAhi, pAlo, pBhi, bias, add, Cp, M, N, K, epi)

    k_init<<<64, 256>>>();
    k_router<<<NTOT, 256>>>(hs, rw);
    k_topk<<<BB, 1024>>>();

    // predictor: gelu(hs @ cfc1^T + b1) -> g_act ; then BCE (loss-only: 1-term fp16)
    CONVB(hs, pAhi, NTOT, HID);
    CONVB(cfc1_w, pBhi, CH, HID);
    GEMM1(NTOT, CH, HID, cfc1_b, nullptr, pact, 1);
    k_pred2<<<NTOT/8, 256>>>(cfc2_w, cfc2_b);

    // gather + rmsnorm1 (emits split A directly)
    k_gather<<<NTOK, 256>>>(hs);
    k_rms<<<NTOK, 256>>>(px, ln1, pAhi, pAlo);

    // QKV
    CONVB(q_w, pBhi, HID, HID);
    GEMM(NTOK, HID, HID, q_b, nullptr, pq, 0);
    CONVB(k_w, pBhi, HID, HID);
    GEMM(NTOK, HID, HID, k_b, nullptr, pk, 0);
    CONVB(v_w, pBhi, HID, HID);
    GEMM(NTOK, HID, HID, v_b, nullptr, pv, 0);
    k_rope<<<(NTOK*NHEADS*64)/256, 256>>>();

    // attention (emits split A for O-proj)
    k_attn<<<dim3(KSEL/64, BB*NHEADS), 256, ATTN_SMEM>>>(pAhi, pAlo);

    // O-proj + residual -> h1 ; rmsnorm2 emits split A for MLP
    CONVB(o_w, pBhi, HID, HID);
    GEMM(NTOK, HID, HID, nullptr, px, ph1, 2);
    k_rms<<<NTOK, 256>>>(ph1, ln2, pAhi, pAlo);

    // MLP
    CONVB(gate_w, pBhi, INTER, HID);
    GEMM(NTOK, INTER, HID, nullptr, nullptr, pgb, 0);
    CONVB(up_w, pBhi, INTER, HID);
    GEMM(NTOK, INTER, HID, nullptr, nullptr, pub, 0);
    k_silumul<<<(NTOK*(INTER/8))/256, 256>>>(pAhi, pAlo);
    CONVB(down_w, pBhi, HID, INTER);
    GEMM(NTOK, HID, INTER, nullptr, ph1, plo, 2);

    // output
    k_copy<<<((size_t)NTOT*HID/4)/256, 256>>>(hs, out);
    k_scatter<<<NTOK, 256>>>(out);
    k_final<<<1, 32>>>(out, (long long)NTOT*HID, (long long)out_size);
}

// round 8
// speedup vs baseline: 4.2475x; 1.3450x over previous
#include <cuda_runtime.h>
#include <cuda_fp16.h>
#include <stdint.h>
#include <math.h>

#define BB     4
#define TT     4096
#define HID    2048
#define NHEADS 16
#define HDIM   128
#define INTER  8192
#define KSEL   512
#define NTOK   (BB*KSEL)
#define NTOT   (BB*TT)
#define CH     (HID/4)

// ================= helpers =================
__device__ __forceinline__ uint32_t smem_to_u32(const void* p) {
    uint32_t a;
    asm("{ .reg .u64 t; cvta.to.shared.u64 t, %1; cvt.u32.u64 %0, t; }" : "=r"(a) : "l"(p));
    return a;
}
__device__ __forceinline__ void cp16(uint32_t s, const void* g) {
    asm volatile("cp.async.cg.shared.global [%0], [%1], 16;" :: "r"(s), "l"(g));
}
__device__ __forceinline__ void ldsm_x4(uint32_t* r, uint32_t addr) {
    asm volatile("ldmatrix.sync.aligned.m8n8.x4.shared.b16 {%0,%1,%2,%3}, [%4];"
        : "=r"(r[0]), "=r"(r[1]), "=r"(r[2]), "=r"(r[3]) : "r"(addr));
}
__device__ __forceinline__ void mma16816(float* d, const uint32_t* a, const uint32_t* b) {
    asm volatile(
        "mma.sync.aligned.m16n8k16.row.col.f32.f16.f16.f32 "
        "{%0,%1,%2,%3}, {%4,%5,%6,%7}, {%8,%9}, {%0,%1,%2,%3};"
        : "+f"(d[0]), "+f"(d[1]), "+f"(d[2]), "+f"(d[3])
        : "r"(a[0]), "r"(a[1]), "r"(a[2]), "r"(a[3]), "r"(b[0]), "r"(b[1]));
}

// ================= device scratch =================
__device__ float g_logits[NTOT];
__device__ float g_flags[NTOT];
__device__ int   g_idx[BB*KSEL];
__device__ float g_gate[BB*KSEL];
__device__ float g_act[NTOT*CH];
__device__ float g_x [NTOK*HID];
__device__ float g_q [NTOK*HID];
__device__ float g_k [NTOK*HID];
__device__ float g_v [NTOK*HID];
__device__ float g_h1[NTOK*HID];
__device__ float g_lo[NTOK*HID];
__device__ float g_gb[NTOK*INTER];
__device__ float g_ub[NTOK*INTER];
__device__ double g_f0sum, g_selsum, g_predsum;
// fp16 operand buffers (plain row-major)
__device__ __half g_A[33554432];     // max: NTOT*HID
__device__ __half g_B[16777216];     // max: INTER*HID

// ================= small kernels =================
__global__ void k_init() {
    int i = blockIdx.x*blockDim.x + threadIdx.x;
    if (i < NTOT) g_flags[i] = 0.f;
    if (i == 0) { g_f0sum = 0.0; g_selsum = 0.0; g_predsum = 0.0; }
}

__global__ void k_router(const float* __restrict__ hs, const float* __restrict__ rw) {
    int t = blockIdx.x;
    const float* row = hs + (size_t)t*HID;
    float s = 0.f;
    for (int i = threadIdx.x; i < HID; i += 256) s += row[i]*rw[i];
    __shared__ float red[256];
    red[threadIdx.x] = s; __syncthreads();
    for (int st = 128; st; st >>= 1) {
        if (threadIdx.x < st) red[threadIdx.x] += red[threadIdx.x+st];
        __syncthreads();
    }
    if (threadIdx.x == 0) {
        float l = red[0];
        g_logits[t] = l;
        float f0 = fmaxf(l, 0.f) + log1pf(expf(-fabsf(l)));
        atomicAdd(&g_f0sum, (double)f0);
    }
}

__global__ void k_topk() {
    int b = blockIdx.x;
    __shared__ float sv[TT];
    __shared__ int   si[TT];
    int tid = threadIdx.x;
    for (int i = tid; i < TT; i += 1024) { sv[i] = g_logits[b*TT + i]; si[i] = i; }
    __syncthreads();
    for (int k = 2; k <= TT; k <<= 1) {
        for (int j = k >> 1; j > 0; j >>= 1) {
            for (int i = tid; i < TT; i += 1024) {
                int ixj = i ^ j;
                if (ixj > i) {
                    float va = sv[i], vb = sv[ixj];
                    int ia = si[i], ib = si[ixj];
                    bool lij = (vb > va) || (vb == va && ib < ia);
                    bool lji = (va > vb) || (va == vb && ia < ib);
                    bool sw = ((i & k) == 0) ? lij : lji;
                    if (sw) { sv[i] = vb; sv[ixj] = va; si[i] = ib; si[ixj] = ia; }
                }
            }
            __syncthreads();
        }
    }
    for (int k = 2; k <= KSEL; k <<= 1) {
        for (int j = k >> 1; j > 0; j >>= 1) {
            if (tid < KSEL) {
                int i = tid, ixj = i ^ j;
                if (ixj > i) {
                    int ia = si[i], ib = si[ixj];
                    bool sw = ((i & k) == 0) ? (ib < ia) : (ia < ib);
                    if (sw) {
                        int ti = si[i]; si[i] = si[ixj]; si[ixj] = ti;
                        float tv = sv[i]; sv[i] = sv[ixj]; sv[ixj] = tv;
                    }
                }
            }
            __syncthreads();
        }
    }
    if (tid < KSEL) {
        int token = si[tid]; float val = sv[tid];
        g_idx[b*KSEL + tid] = token;
        g_gate[b*KSEL + tid] = 1.f/(1.f + expf(-val));
        g_flags[b*TT + token] = 1.f;
        atomicAdd(&g_selsum, (double)val);
    }
}

__global__ void k_pred2(const float* __restrict__ w2, const float* __restrict__ b2) {
    int warp = threadIdx.x >> 5, lane = threadIdx.x & 31;
    int t = blockIdx.x*8 + warp;
    const float* a = g_act + (size_t)t*CH;
    float s = 0.f;
    for (int i = lane; i < CH; i += 32) s += a[i]*w2[i];
    for (int o = 16; o; o >>= 1) s += __shfl_xor_sync(0xffffffffu, s, o);
    __shared__ float ps[8];
    if (lane == 0) {
        float p = s + b2[0];
        float tg = g_flags[t];
        ps[warp] = fmaxf(p, 0.f) - p*tg + log1pf(expf(-fabsf(p)));
    }
    __syncthreads();
    if (threadIdx.x == 0) {
        float tot = 0.f;
        for (int i = 0; i < 8; i++) tot += ps[i];
        atomicAdd(&g_predsum, (double)tot);
    }
}

__global__ void k_gather(const float* __restrict__ hs) {
    int bj = blockIdx.x, b = bj >> 9;
    int t = g_idx[bj];
    const float* src = hs + ((size_t)b*TT + t)*HID;
    float* dst = g_x + (size_t)bj*HID;
    int i = threadIdx.x*8;
    *(float4*)(dst+i)   = *(const float4*)(src+i);
    *(float4*)(dst+i+4) = *(const float4*)(src+i+4);
}

// rmsnorm -> directly emit fp16 (A operand)
__global__ void k_rms(const float* __restrict__ in, const float* __restrict__ w,
                      __half* __restrict__ ha) {
    int row = blockIdx.x;
    const float* src = in + (size_t)row*HID;
    int i = threadIdx.x*8;
    float4 a = *(const float4*)(src+i), b = *(const float4*)(src+i+4);
    float ss = a.x*a.x + a.y*a.y + a.z*a.z + a.w*a.w
             + b.x*b.x + b.y*b.y + b.z*b.z + b.w*b.w;
    __shared__ float red[256];
    red[threadIdx.x] = ss; __syncthreads();
    for (int st = 128; st; st >>= 1) {
        if (threadIdx.x < st) red[threadIdx.x] += red[threadIdx.x+st];
        __syncthreads();
    }
    float sc = 1.f/sqrtf(red[0]/(float)HID + 1e-6f);
    float4 w0 = *(const float4*)(w+i), w1 = *(const float4*)(w+i+4);
    float v[8] = {a.x*sc*w0.x, a.y*sc*w0.y, a.z*sc*w0.z, a.w*sc*w0.w,
                  b.x*sc*w1.x, b.y*sc*w1.y, b.z*sc*w1.z, b.w*sc*w1.w};
    unsigned short hv[8];
#pragma unroll
    for (int j = 0; j < 8; j++) {
        __half hb = __float2half_rn(v[j]);
        hv[j] = *(unsigned short*)&hb;
    }
    *(uint4*)(ha + (size_t)row*HID + i) = *(uint4*)hv;
}

__global__ void k_rope() {
    int t256 = blockIdx.x*256 + threadIdx.x;
    int d = t256 & 63;
    int bh = t256 >> 6;
    int bj = bh >> 4, h = bh & 15;
    int pos = g_idx[bj];
    float ang = (float)pos * expf(-(float)d * 0.14391156831212787f);
    float c = cosf(ang), s = sinf(ang);
    size_t base = (size_t)bj*HID + h*HDIM;
    float q1 = g_q[base+d], q2 = g_q[base+d+64];
    g_q[base+d]    = q1*c - q2*s;
    g_q[base+d+64] = q2*c + q1*s;
    float k1 = g_k[base+d], k2 = g_k[base+d+64];
    g_k[base+d]    = k1*c - k2*s;
    g_k[base+d+64] = k2*c + k1*s;
}

// flash attention -> emits fp16 directly (A operand for O-proj)
__global__ void k_attn(__half* __restrict__ oa) {
    extern __shared__ float sm[];
    float* Qs = sm;
    float* Ks = Qs + 64*129;
    float* Vs = Ks + 64*129;
    float* Ss = Vs + 64*129;
    int qt = blockIdx.x, bh = blockIdx.y;
    int b = bh >> 4, h = bh & 15;
    int tid = threadIdx.x;
    size_t headbase = (size_t)b*KSEL*HID + (size_t)h*HDIM;
    for (int u = tid; u < 64*32; u += 256) {
        int r = u >> 5, c4 = (u & 31) << 2;
        float4 v = *(const float4*)(g_q + headbase + (size_t)(qt*64+r)*HID + c4);
        Qs[r*129+c4+0] = v.x*0.08838834764831845f;
        Qs[r*129+c4+1] = v.y*0.08838834764831845f;
        Qs[r*129+c4+2] = v.z*0.08838834764831845f;
        Qs[r*129+c4+3] = v.w*0.08838834764831845f;
    }
    int r = tid >> 2, qq = tid & 3;
    float m = -INFINITY, l = 0.f;
    float acc[32];
#pragma unroll
    for (int i = 0; i < 32; i++) acc[i] = 0.f;
    for (int kt = 0; kt <= qt; ++kt) {
        __syncthreads();
        for (int u = tid; u < 64*32; u += 256) {
            int jr = u >> 5, c4 = (u & 31) << 2;
            float4 kv = *(const float4*)(g_k + headbase + (size_t)(kt*64+jr)*HID + c4);
            float4 vv = *(const float4*)(g_v + headbase + (size_t)(kt*64+jr)*HID + c4);
            Ks[jr*129+c4+0] = kv.x; Ks[jr*129+c4+1] = kv.y;
            Ks[jr*129+c4+2] = kv.z; Ks[jr*129+c4+3] = kv.w;
            Vs[jr*129+c4+0] = vv.x; Vs[jr*129+c4+1] = vv.y;
            Vs[jr*129+c4+2] = vv.z; Vs[jr*129+c4+3] = vv.w;
        }
        __syncthreads();
        float a[16];
#pragma unroll
        for (int jj = 0; jj < 16; jj++) a[jj] = 0.f;
        const float* qrow = Qs + r*129;
        for (int d0 = 0; d0 < 128; d0 += 4) {
            float q0 = qrow[d0], q1 = qrow[d0+1], q2 = qrow[d0+2], q3 = qrow[d0+3];
#pragma unroll
            for (int jj = 0; jj < 16; jj++) {
                const float* kp = Ks + (qq + (jj<<2))*129 + d0;
                a[jj] += q0*kp[0] + q1*kp[1] + q2*kp[2] + q3*kp[3];
            }
        }
        int qg = qt*64 + r;
        float sreg[16];
#pragma unroll
        for (int jj = 0; jj < 16; jj++) {
            int kg = kt*64 + qq + (jj<<2);
            sreg[jj] = (kg <= qg) ? a[jj] : -1e9f;
        }
        float mx = sreg[0];
#pragma unroll
        for (int jj = 1; jj < 16; jj++) mx = fmaxf(mx, sreg[jj]);
        mx = fmaxf(mx, __shfl_xor_sync(0xffffffffu, mx, 1));
        mx = fmaxf(mx, __shfl_xor_sync(0xffffffffu, mx, 2));
        float mn = fmaxf(m, mx);
        float corr = expf(m - mn);
        float ls = 0.f;
#pragma unroll
        for (int jj = 0; jj < 16; jj++) {
            float p = expf(sreg[jj] - mn);
            ls += p;
            Ss[r*65 + qq + (jj<<2)] = p;
        }
        ls += __shfl_xor_sync(0xffffffffu, ls, 1);
        ls += __shfl_xor_sync(0xffffffffu, ls, 2);
        l = l*corr + ls; m = mn;
        __syncwarp();
#pragma unroll
        for (int i = 0; i < 32; i++) acc[i] *= corr;
        for (int j = 0; j < 64; j++) {
            float pv = Ss[r*65 + j];
            const float* vp = Vs + j*129 + qq;
#pragma unroll
            for (int i = 0; i < 32; i++) acc[i] += pv * vp[i<<2];
        }
    }
    float inv = 1.f/l;
    size_t outb = headbase + (size_t)(qt*64+r)*HID + qq;
#pragma unroll
    for (int i = 0; i < 32; i++) {
        __half hb = __float2half_rn(acc[i]*inv);
        *(unsigned short*)(oa + outb + (i<<2)) = *(unsigned short*)&hb;
    }
}

// silu(gate)*up -> emits fp16 directly (A operand for down-proj)
__global__ void k_silumul(__half* __restrict__ ha) {
    size_t i = ((size_t)blockIdx.x*256 + threadIdx.x)*8;
    float4 g0 = *(float4*)(g_gb+i),   u0 = *(float4*)(g_ub+i);
    float4 g1 = *(float4*)(g_gb+i+4), u1 = *(float4*)(g_ub+i+4);
    float v[8] = {
        g0.x/(1.f+expf(-g0.x))*u0.x, g0.y/(1.f+expf(-g0.y))*u0.y,
        g0.z/(1.f+expf(-g0.z))*u0.z, g0.w/(1.f+expf(-g0.w))*u0.w,
        g1.x/(1.f+expf(-g1.x))*u1.x, g1.y/(1.f+expf(-g1.y))*u1.y,
        g1.z/(1.f+expf(-g1.z))*u1.z, g1.w/(1.f+expf(-g1.w))*u1.w };
    unsigned short hv[8];
#pragma unroll
    for (int j = 0; j < 8; j++) {
        __half hb = __float2half_rn(v[j]);
        hv[j] = *(unsigned short*)&hb;
    }
    *(uint4*)(ha + i) = *(uint4*)hv;
}

__global__ void k_copy(const float* __restrict__ src, float* __restrict__ dst) {
    size_t i = ((size_t)blockIdx.x*256 + threadIdx.x)*4;
    *(float4*)(dst+i) = *(const float4*)(src+i);
}

__global__ void k_scatter(float* __restrict__ out) {
    int bj = blockIdx.x, b = bj >> 9;
    int t = g_idx[bj];
    float gt = g_gate[bj];
    float* dst = out + ((size_t)b*TT + t)*HID;
    const float* xp = g_x + (size_t)bj*HID;
    const float* lp = g_lo + (size_t)bj*HID;
    int i = threadIdx.x*8;
#pragma unroll
    for (int u = 0; u < 8; u++) {
        float xv = xp[i+u], lv = lp[i+u];
        dst[i+u] = xv + gt*(lv - xv);
    }
}

__global__ void k_final(float* out, long long N, long long out_size) {
    if (threadIdx.x == 0) {
        if (N   < out_size) out[N]   = (float)((g_f0sum - g_selsum)/(double)NTOT);
        if (N+1 < out_size) out[N+1] = (float)(g_predsum/(double)NTOT);
    }
}

// ======== fp32 -> fp16 cast ========
__global__ void k_convB(const float* __restrict__ src, __half* __restrict__ dst) {
    size_t base = ((size_t)blockIdx.x*256 + threadIdx.x)*8;
    const float4* s = (const float4*)(src + base);
    float4 x0 = s[0], x1 = s[1];
    float xs[8] = {x0.x, x0.y, x0.z, x0.w, x1.x, x1.y, x1.z, x1.w};
    unsigned short hv[8];
#pragma unroll
    for (int j = 0; j < 8; j++) {
        __half hb = __float2half_rn(xs[j]);
        hv[j] = *(unsigned short*)&hb;
    }
    *(uint4*)(dst + base) = *(uint4*)hv;
}

// ================= fp16 MMA GEMM: C[M,N] = A[M,K] @ B[N,K]^T =================
// CTA tile 128x256x32, 256 threads (8 warps 2m x 4n), warp tile 64x64.
// 3-stage cp.async pipeline. smem rows padded to 40 halves (conflict-free ldmatrix).
// epi: 0 = +bias(if set); 1 = gelu(acc+bias); 2 = acc + add residual
#define PADK 40
#define A_BYTES   (128*PADK*2)            // 10240
#define B_BYTES   (256*PADK*2)            // 20480
#define STAGE_BYTES (A_BYTES + B_BYTES)   // 30720
#define GEMM_SMEM (3*STAGE_BYTES)         // 92160

__device__ __forceinline__ void load_stage(uint32_t sb, int stage,
    const __half* A, const __half* B, int K, int kt, int tid)
{
    uint32_t s0 = sb + stage*STAGE_BYTES;
#pragma unroll
    for (int u = 0; u < 2; u++) {
        int c = tid + u*256;
        int row = c >> 2, seg = (c & 3) << 3;
        size_t g = (size_t)row*K + (size_t)kt*32 + seg;
        cp16(s0 + (row*PADK + seg)*2, A + g);
    }
#pragma unroll
    for (int u = 0; u < 4; u++) {
        int c = tid + u*256;
        int row = c >> 2, seg = (c & 3) << 3;
        size_t g = (size_t)row*K + (size_t)kt*32 + seg;
        cp16(s0 + A_BYTES + (row*PADK + seg)*2, B + g);
    }
    asm volatile("cp.async.commit_group;" ::: "memory");
}

__global__ void __launch_bounds__(256, 1) tc_gemm(
    const __half* __restrict__ Ag, const __half* __restrict__ Bg,
    const float* __restrict__ bias, const float* __restrict__ add,
    float* __restrict__ C, int M, int N, int K, int epi)
{
    extern __shared__ __align__(16) char smem[];
    uint32_t sb = smem_to_u32(smem);
    const int tid = threadIdx.x, wid = tid >> 5, lane = tid & 31;
    const int wm = wid & 1, wn = wid >> 1;
    const long bm = (long)blockIdx.y << 7, bn = (long)blockIdx.x << 8;

    const __half* pA = Ag + (size_t)bm*K;
    const __half* pB = Bg + (size_t)bn*K;

    float acc[4][8][4];
#pragma unroll
    for (int mt = 0; mt < 4; mt++)
#pragma unroll
        for (int nt = 0; nt < 8; nt++)
#pragma unroll
            for (int i = 0; i < 4; i++) acc[mt][nt][i] = 0.f;

    const int NK = K >> 5;
    load_stage(sb, 0, pA, pB, K, 0, tid);
    load_stage(sb, 1, pA, pB, K, 1, tid);

    for (int kt = 0; kt < NK; ++kt) {
        if (kt + 2 < NK) {
            load_stage(sb, (kt+2)%3, pA, pB, K, kt+2, tid);
            asm volatile("cp.async.wait_group 2;" ::: "memory");
        } else {
            asm volatile("cp.async.wait_group 0;" ::: "memory");
        }
        __syncthreads();

        uint32_t s0 = sb + (kt%3)*STAGE_BYTES;
#pragma unroll
        for (int kk = 0; kk < 32; kk += 16) {
            uint32_t Af[4][4];
            const int arow = wm*64 + (lane & 15);
            const int acol = kk + ((lane >> 4) << 3);
#pragma unroll
            for (int mt = 0; mt < 4; mt++)
                ldsm_x4(Af[mt], s0 + (uint32_t)((arow + mt*16)*PADK + acol)*2);
            const int brow = wn*64 + (lane & 7) + (((lane >> 4) & 1) << 3);
            const int bcol = kk + (((lane >> 3) & 1) << 3);
#pragma unroll
            for (int np = 0; np < 4; np++) {
                uint32_t Bf[4];
                ldsm_x4(Bf, s0 + A_BYTES + (uint32_t)((brow + np*16)*PADK + bcol)*2);
#pragma unroll
                for (int mt = 0; mt < 4; mt++) {
                    mma16816(acc[mt][np*2],   Af[mt], Bf);
                    mma16816(acc[mt][np*2+1], Af[mt], Bf+2);
                }
            }
        }
        __syncthreads();
    }

    // ---- epilogue ----
#pragma unroll
    for (int mt = 0; mt < 4; mt++) {
#pragma unroll
        for (int nt = 0; nt < 8; nt++) {
            long m = bm + wm*64 + mt*16 + (lane >> 2);
            long n = bn + wn*64 + nt*8 + ((lane & 3) << 1);
            float* a = acc[mt][nt];
            float b0 = bias ? bias[n] : 0.f;
            float b1 = bias ? bias[n+1] : 0.f;
            float v0 = a[0] + b0, v1 = a[1] + b1, v2 = a[2] + b0, v3 = a[3] + b1;
            if (epi == 1) {
                v0 = 0.5f*v0*(1.f + erff(v0*0.70710678118654752f));
                v1 = 0.5f*v1*(1.f + erff(v1*0.70710678118654752f));
                v2 = 0.5f*v2*(1.f + erff(v2*0.70710678118654752f));
                v3 = 0.5f*v3*(1.f + erff(v3*0.70710678118654752f));
            }
            if (epi == 2) {
                v0 += add[m*N + n];     v1 += add[m*N + n + 1];
                v2 += add[(m+8)*N + n]; v3 += add[(m+8)*N + n + 1];
            }
            *(float2*)(C + m*N + n)     = make_float2(v0, v1);
            *(float2*)(C + (m+8)*N + n) = make_float2(v2, v3);
        }
    }
}

// ================= launch =================
extern "C" void kernel_launch(void* const* d_in, const int* in_sizes, int n_in,
                              void* d_out, int out_size) {
    const float* hs     = (const float*)d_in[0];
    const float* rw     = (const float*)d_in[1];
    const float* cfc1_w = (const float*)d_in[2];
    const float* cfc1_b = (const float*)d_in[3];
    const float* cfc2_w = (const float*)d_in[4];
    const float* cfc2_b = (const float*)d_in[5];
    const float* ln1    = (const float*)d_in[6];
    const float* ln2    = (const float*)d_in[7];
    const float* q_w    = (const float*)d_in[8];
    const float* q_b    = (const float*)d_in[9];
    const float* k_w    = (const float*)d_in[10];
    const float* k_b    = (const float*)d_in[11];
    const float* v_w    = (const float*)d_in[12];
    const float* v_b    = (const float*)d_in[13];
    const float* o_w    = (const float*)d_in[14];
    const float* gate_w = (const float*)d_in[15];
    const float* up_w   = (const float*)d_in[16];
    const float* down_w = (const float*)d_in[17];
    float* out = (float*)d_out;

    float *px, *pq, *pk, *pv, *ph1, *plo, *pgb, *pub, *pact;
    cudaGetSymbolAddress((void**)&px,  g_x);
    cudaGetSymbolAddress((void**)&pq,  g_q);
    cudaGetSymbolAddress((void**)&pk,  g_k);
    cudaGetSymbolAddress((void**)&pv,  g_v);
    cudaGetSymbolAddress((void**)&ph1, g_h1);
    cudaGetSymbolAddress((void**)&plo, g_lo);
    cudaGetSymbolAddress((void**)&pgb, g_gb);
    cudaGetSymbolAddress((void**)&pub, g_ub);
    cudaGetSymbolAddress((void**)&pact, g_act);
    __half *pA, *pB;
    cudaGetSymbolAddress((void**)&pA, g_A);
    cudaGetSymbolAddress((void**)&pB, g_B);

    cudaFuncSetAttribute(tc_gemm, cudaFuncAttributeMaxDynamicSharedMemorySize, GEMM_SMEM);
    const int ATTN_SMEM = (3*64*129 + 64*65)*4;
    cudaFuncSetAttribute(k_attn, cudaFuncAttributeMaxDynamicSharedMemorySize, ATTN_SMEM);

#define CONVB(src, dst, R, K) k_convB<<<((size_t)(R)*(K)/8)/256, 256>>>(src, dst)
#define GEMM(M, N, K, bias, add, Cp, epi) \
    tc_gemm<<<dim3((N)/256, (M)/128), 256, GEMM_SMEM>>>(pA, pB, bias, add, Cp, M, N, K, epi)

    k_init<<<64, 256>>>();
    k_router<<<NTOT, 256>>>(hs, rw);
    k_topk<<<BB, 1024>>>();

    // predictor: gelu(hs @ cfc1^T + b1) -> g_act ; then BCE
    CONVB(hs, pA, NTOT, HID);
    CONVB(cfc1_w, pB, CH, HID);
    GEMM(NTOT, CH, HID, cfc1_b, nullptr, pact, 1);
    k_pred2<<<NTOT/8, 256>>>(cfc2_w, cfc2_b);

    // gather + rmsnorm1 (emits fp16 A directly)
    k_gather<<<NTOK, 256>>>(hs);
    k_rms<<<NTOK, 256>>>(px, ln1, pA);

    // QKV
    CONVB(q_w, pB, HID, HID);
    GEMM(NTOK, HID, HID, q_b, nullptr, pq, 0);
    CONVB(k_w, pB, HID, HID);
    GEMM(NTOK, HID, HID, k_b, nullptr, pk, 0);
    CONVB(v_w, pB, HID, HID);
    GEMM(NTOK, HID, HID, v_b, nullptr, pv, 0);
    k_rope<<<(NTOK*NHEADS*64)/256, 256>>>();

    // attention (emits fp16 A for O-proj)
    k_attn<<<dim3(KSEL/64, BB*NHEADS), 256, ATTN_SMEM>>>(pA);

    // O-proj + residual -> h1 ; rmsnorm2 emits fp16 A for MLP
    CONVB(o_w, pB, HID, HID);
    GEMM(NTOK, HID, HID, nullptr, px, ph1, 2);
    k_rms<<<NTOK, 256>>>(ph1, ln2, pA);

    // MLP
    CONVB(gate_w, pB, INTER, HID);
    GEMM(NTOK, INTER, HID, nullptr, nullptr, pgb, 0);
    CONVB(up_w, pB, INTER, HID);
    GEMM(NTOK, INTER, HID, nullptr, nullptr, pub, 0);
    k_silumul<<<(NTOK*(INTER/8))/256, 256>>>(pA);
    CONVB(down_w, pB, HID, INTER);
    GEMM(NTOK, HID, INTER, nullptr, ph1, plo, 2);

    // output
    k_copy<<<((size_t)NTOT*HID/4)/256, 256>>>(hs, out);
    k_scatter<<<NTOK, 256>>>(out);
    k_final<<<1, 32>>>(out, (long long)NTOT*HID, (long long)out_size);
}

// round 9
// speedup vs baseline: 5.3235x; 1.2533x over previous
#include <cuda_runtime.h>
#include <cuda_fp16.h>
#include <stdint.h>
#include <math.h>

#define BB     4
#define TT     4096
#define HID    2048
#define NHEADS 16
#define HDIM   128
#define INTER  8192
#define KSEL   512
#define NTOK   (BB*KSEL)
#define NTOT   (BB*TT)
#define CH     (HID/4)
#define QSTR   (3*HID)   // 6144

// ================= helpers =================
__device__ __forceinline__ uint32_t smem_to_u32(const void* p) {
    uint32_t a;
    asm("{ .reg .u64 t; cvta.to.shared.u64 t, %1; cvt.u32.u64 %0, t; }" : "=r"(a) : "l"(p));
    return a;
}
__device__ __forceinline__ void cp16(uint32_t s, const void* g) {
    asm volatile("cp.async.cg.shared.global [%0], [%1], 16;" :: "r"(s), "l"(g));
}
__device__ __forceinline__ void ldsm_x4(uint32_t* r, uint32_t addr) {
    asm volatile("ldmatrix.sync.aligned.m8n8.x4.shared.b16 {%0,%1,%2,%3}, [%4];"
        : "=r"(r[0]), "=r"(r[1]), "=r"(r[2]), "=r"(r[3]) : "r"(addr));
}
__device__ __forceinline__ void ldsm_x4_t(uint32_t* r, uint32_t addr) {
    asm volatile("ldmatrix.sync.aligned.m8n8.x4.trans.shared.b16 {%0,%1,%2,%3}, [%4];"
        : "=r"(r[0]), "=r"(r[1]), "=r"(r[2]), "=r"(r[3]) : "r"(addr));
}
__device__ __forceinline__ void mma16816(float* d, const uint32_t* a, const uint32_t* b) {
    asm volatile(
        "mma.sync.aligned.m16n8k16.row.col.f32.f16.f16.f32 "
        "{%0,%1,%2,%3}, {%4,%5,%6,%7}, {%8,%9}, {%0,%1,%2,%3};"
        : "+f"(d[0]), "+f"(d[1]), "+f"(d[2]), "+f"(d[3])
        : "r"(a[0]), "r"(a[1]), "r"(a[2]), "r"(a[3]), "r"(b[0]), "r"(b[1]));
}
__device__ __forceinline__ uint32_t packh2(float a, float b) {
    __half2 p = __floats2half2_rn(a, b);
    return *(uint32_t*)&p;
}

// ================= device scratch =================
__device__ float g_logits[NTOT];
__device__ float g_flags[NTOT];
__device__ int   g_idx[BB*KSEL];
__device__ float g_gate[BB*KSEL];
__device__ float g_act[NTOT*CH];
__device__ float g_x [NTOK*HID];
__device__ float g_h1[NTOK*HID];
__device__ float g_lo[NTOK*HID];
__device__ float g_gb[NTOK*INTER];
__device__ float g_ub[NTOK*INTER];
__device__ float g_qkvb[QSTR];
__device__ double g_f0sum, g_selsum, g_predsum;
__device__ __half g_A[33554432];        // fp16 A operand (max NTOT*HID)
__device__ __half g_B[16777216];        // fp16 B operand (max INTER*HID)
__device__ __half g_qkvh[NTOK*QSTR];    // fused QKV output, fp16

// ================= small kernels =================
__global__ void k_init() {
    int i = blockIdx.x*blockDim.x + threadIdx.x;
    if (i < NTOT) g_flags[i] = 0.f;
    if (i == 0) { g_f0sum = 0.0; g_selsum = 0.0; g_predsum = 0.0; }
}

__global__ void k_router(const float* __restrict__ hs, const float* __restrict__ rw) {
    int t = blockIdx.x;
    const float* row = hs + (size_t)t*HID;
    float s = 0.f;
    for (int i = threadIdx.x; i < HID; i += 256) s += row[i]*rw[i];
    __shared__ float red[256];
    red[threadIdx.x] = s; __syncthreads();
    for (int st = 128; st; st >>= 1) {
        if (threadIdx.x < st) red[threadIdx.x] += red[threadIdx.x+st];
        __syncthreads();
    }
    if (threadIdx.x == 0) {
        float l = red[0];
        g_logits[t] = l;
        float f0 = fmaxf(l, 0.f) + log1pf(expf(-fabsf(l)));
        atomicAdd(&g_f0sum, (double)f0);
    }
}

__global__ void k_topk() {
    int b = blockIdx.x;
    __shared__ float sv[TT];
    __shared__ int   si[TT];
    int tid = threadIdx.x;
    for (int i = tid; i < TT; i += 1024) { sv[i] = g_logits[b*TT + i]; si[i] = i; }
    __syncthreads();
    for (int k = 2; k <= TT; k <<= 1) {
        for (int j = k >> 1; j > 0; j >>= 1) {
            for (int i = tid; i < TT; i += 1024) {
                int ixj = i ^ j;
                if (ixj > i) {
                    float va = sv[i], vb = sv[ixj];
                    int ia = si[i], ib = si[ixj];
                    bool lij = (vb > va) || (vb == va && ib < ia);
                    bool lji = (va > vb) || (va == vb && ia < ib);
                    bool sw = ((i & k) == 0) ? lij : lji;
                    if (sw) { sv[i] = vb; sv[ixj] = va; si[i] = ib; si[ixj] = ia; }
                }
            }
            __syncthreads();
        }
    }
    for (int k = 2; k <= KSEL; k <<= 1) {
        for (int j = k >> 1; j > 0; j >>= 1) {
            if (tid < KSEL) {
                int i = tid, ixj = i ^ j;
                if (ixj > i) {
                    int ia = si[i], ib = si[ixj];
                    bool sw = ((i & k) == 0) ? (ib < ia) : (ia < ib);
                    if (sw) {
                        int ti = si[i]; si[i] = si[ixj]; si[ixj] = ti;
                        float tv = sv[i]; sv[i] = sv[ixj]; sv[ixj] = tv;
                    }
                }
            }
            __syncthreads();
        }
    }
    if (tid < KSEL) {
        int token = si[tid]; float val = sv[tid];
        g_idx[b*KSEL + tid] = token;
        g_gate[b*KSEL + tid] = 1.f/(1.f + expf(-val));
        g_flags[b*TT + token] = 1.f;
        atomicAdd(&g_selsum, (double)val);
    }
}

__global__ void k_pred2(const float* __restrict__ w2, const float* __restrict__ b2) {
    int warp = threadIdx.x >> 5, lane = threadIdx.x & 31;
    int t = blockIdx.x*8 + warp;
    const float* a = g_act + (size_t)t*CH;
    float s = 0.f;
    for (int i = lane; i < CH; i += 32) s += a[i]*w2[i];
    for (int o = 16; o; o >>= 1) s += __shfl_xor_sync(0xffffffffu, s, o);
    __shared__ float ps[8];
    if (lane == 0) {
        float p = s + b2[0];
        float tg = g_flags[t];
        ps[warp] = fmaxf(p, 0.f) - p*tg + log1pf(expf(-fabsf(p)));
    }
    __syncthreads();
    if (threadIdx.x == 0) {
        float tot = 0.f;
        for (int i = 0; i < 8; i++) tot += ps[i];
        atomicAdd(&g_predsum, (double)tot);
    }
}

__global__ void k_gather(const float* __restrict__ hs) {
    int bj = blockIdx.x, b = bj >> 9;
    int t = g_idx[bj];
    const float* src = hs + ((size_t)b*TT + t)*HID;
    float* dst = g_x + (size_t)bj*HID;
    int i = threadIdx.x*8;
    *(float4*)(dst+i)   = *(const float4*)(src+i);
    *(float4*)(dst+i+4) = *(const float4*)(src+i+4);
}

// rmsnorm -> fp16 A operand
__global__ void k_rms(const float* __restrict__ in, const float* __restrict__ w,
                      __half* __restrict__ ha) {
    int row = blockIdx.x;
    const float* src = in + (size_t)row*HID;
    int i = threadIdx.x*8;
    float4 a = *(const float4*)(src+i), b = *(const float4*)(src+i+4);
    float ss = a.x*a.x + a.y*a.y + a.z*a.z + a.w*a.w
             + b.x*b.x + b.y*b.y + b.z*b.z + b.w*b.w;
    __shared__ float red[256];
    red[threadIdx.x] = ss; __syncthreads();
    for (int st = 128; st; st >>= 1) {
        if (threadIdx.x < st) red[threadIdx.x] += red[threadIdx.x+st];
        __syncthreads();
    }
    float sc = 1.f/sqrtf(red[0]/(float)HID + 1e-6f);
    float4 w0 = *(const float4*)(w+i), w1 = *(const float4*)(w+i+4);
    float v[8] = {a.x*sc*w0.x, a.y*sc*w0.y, a.z*sc*w0.z, a.w*sc*w0.w,
                  b.x*sc*w1.x, b.y*sc*w1.y, b.z*sc*w1.z, b.w*sc*w1.w};
    unsigned short hv[8];
#pragma unroll
    for (int j = 0; j < 8; j++) {
        __half hb = __float2half_rn(v[j]);
        hv[j] = *(unsigned short*)&hb;
    }
    *(uint4*)(ha + (size_t)row*HID + i) = *(uint4*)hv;
}

__global__ void k_catbias(const float* __restrict__ qb, const float* __restrict__ kb,
                          const float* __restrict__ vb) {
    int i = blockIdx.x*256 + threadIdx.x;
    float v = (i < HID) ? qb[i] : (i < 2*HID ? kb[i-HID] : vb[i-2*HID]);
    g_qkvb[i] = v;
}

// rope on fused fp16 qkv buffer
__global__ void k_rope() {
    int t = blockIdx.x*256 + threadIdx.x;   // [0, NTOK*NHEADS*64)
    int d = t & 63;
    int bh = t >> 6;
    int bj = bh >> 4, h = bh & 15;
    int pos = g_idx[bj];
    float ang = (float)pos * expf(-(float)d * 0.14391156831212787f);
    float c = cosf(ang), s = sinf(ang);
    size_t base = (size_t)bj*QSTR + h*HDIM;
    float q1 = __half2float(g_qkvh[base+d]), q2 = __half2float(g_qkvh[base+d+64]);
    g_qkvh[base+d]    = __float2half_rn(q1*c - q2*s);
    g_qkvh[base+d+64] = __float2half_rn(q2*c + q1*s);
    size_t kb = base + HID;
    float k1 = __half2float(g_qkvh[kb+d]), k2 = __half2float(g_qkvh[kb+d+64]);
    g_qkvh[kb+d]    = __float2half_rn(k1*c - k2*s);
    g_qkvh[kb+d+64] = __float2half_rn(k2*c + k1*s);
}

// ============== tensor-core flash attention ==============
// block = 128 threads (4 warps), each warp 16 q-rows; tiles 64q x 64kv x 128d.
#define PADQ 136
#define ATT_TB (64*PADQ*2)             // 17408 bytes per tile
#define ATT_SMEM (3*ATT_TB)            // Q, K, V

__device__ __forceinline__ void att_load_tile(uint32_t sdst, const __half* gsrc, int tid) {
#pragma unroll
    for (int u = 0; u < 8; u++) {
        int c = tid + u*128;
        int row = c >> 4, seg = (c & 15) << 3;
        cp16(sdst + (uint32_t)(row*PADQ + seg)*2, gsrc + (size_t)row*QSTR + seg);
    }
}

__global__ void __launch_bounds__(128, 1) k_attn(__half* __restrict__ oa) {
    extern __shared__ char smem[];
    uint32_t sb = smem_to_u32(smem);
    int qt = blockIdx.x, bh = blockIdx.y;
    int b = bh >> 4, h = bh & 15;
    int tid = threadIdx.x, w = tid >> 5, lane = tid & 31;

    const __half* qbase = g_qkvh + ((size_t)(b*KSEL + qt*64))*QSTR + h*HDIM;
    att_load_tile(sb, qbase, tid);
    asm volatile("cp.async.commit_group;" ::: "memory");
    asm volatile("cp.async.wait_group 0;" ::: "memory");
    __syncthreads();

    uint32_t Aq[8][4];
    {
        int arow = w*16 + (lane & 15);
        int acol = (lane >> 4) << 3;
#pragma unroll
        for (int ks = 0; ks < 8; ks++)
            ldsm_x4(Aq[ks], sb + (uint32_t)(arow*PADQ + ks*16 + acol)*2);
    }

    float co[16][4];
#pragma unroll
    for (int nt = 0; nt < 16; nt++)
#pragma unroll
        for (int i = 0; i < 4; i++) co[nt][i] = 0.f;
    float m0 = -1e30f, m1 = -1e30f, l0 = 0.f, l1 = 0.f;

    for (int kt = 0; kt <= qt; ++kt) {
        const __half* kbp = g_qkvh + ((size_t)(b*KSEL + kt*64))*QSTR + HID + h*HDIM;
        const __half* vbp = kbp + HID;
        __syncthreads();                 // prior compute done before K/V overwrite
        att_load_tile(sb + ATT_TB,   kbp, tid);
        att_load_tile(sb + 2*ATT_TB, vbp, tid);
        asm volatile("cp.async.commit_group;" ::: "memory");
        asm volatile("cp.async.wait_group 0;" ::: "memory");
        __syncthreads();

        // ---- S = Q K^T ----
        float s[8][4];
#pragma unroll
        for (int nt = 0; nt < 8; nt++)
#pragma unroll
            for (int i = 0; i < 4; i++) s[nt][i] = 0.f;
        {
            int krow0 = (lane & 7) + ((lane >> 4) & 1)*8;
            int kcol0 = ((lane >> 3) & 1) << 3;
#pragma unroll
            for (int ks = 0; ks < 8; ks++) {
#pragma unroll
                for (int np = 0; np < 4; np++) {
                    uint32_t Kf[4];
                    ldsm_x4(Kf, sb + ATT_TB +
                        (uint32_t)((np*16 + krow0)*PADQ + ks*16 + kcol0)*2);
                    mma16816(s[2*np],   Aq[ks], Kf);
                    mma16816(s[2*np+1], Aq[ks], Kf+2);
                }
            }
        }
        const float SC = 0.08838834764831845f;
#pragma unroll
        for (int nt = 0; nt < 8; nt++)
#pragma unroll
            for (int i = 0; i < 4; i++) s[nt][i] *= SC;
        if (kt == qt) {
            int rq = w*16 + (lane >> 2);
#pragma unroll
            for (int nt = 0; nt < 8; nt++) {
                int j0 = nt*8 + 2*(lane & 3);
                if (j0   > rq)   s[nt][0] = -1e9f;
                if (j0+1 > rq)   s[nt][1] = -1e9f;
                if (j0   > rq+8) s[nt][2] = -1e9f;
                if (j0+1 > rq+8) s[nt][3] = -1e9f;
            }
        }
        // ---- online softmax ----
        float mx0 = -1e30f, mx1 = -1e30f;
#pragma unroll
        for (int nt = 0; nt < 8; nt++) {
            mx0 = fmaxf(mx0, fmaxf(s[nt][0], s[nt][1]));
            mx1 = fmaxf(mx1, fmaxf(s[nt][2], s[nt][3]));
        }
        mx0 = fmaxf(mx0, __shfl_xor_sync(0xffffffffu, mx0, 1));
        mx0 = fmaxf(mx0, __shfl_xor_sync(0xffffffffu, mx0, 2));
        mx1 = fmaxf(mx1, __shfl_xor_sync(0xffffffffu, mx1, 1));
        mx1 = fmaxf(mx1, __shfl_xor_sync(0xffffffffu, mx1, 2));
        float mn0 = fmaxf(m0, mx0), mn1 = fmaxf(m1, mx1);
        float c0 = __expf(m0 - mn0), c1 = __expf(m1 - mn1);
        float ls0 = 0.f, ls1 = 0.f;
#pragma unroll
        for (int nt = 0; nt < 8; nt++) {
            s[nt][0] = __expf(s[nt][0] - mn0); ls0 += s[nt][0];
            s[nt][1] = __expf(s[nt][1] - mn0); ls0 += s[nt][1];
            s[nt][2] = __expf(s[nt][2] - mn1); ls1 += s[nt][2];
            s[nt][3] = __expf(s[nt][3] - mn1); ls1 += s[nt][3];
        }
        ls0 += __shfl_xor_sync(0xffffffffu, ls0, 1);
        ls0 += __shfl_xor_sync(0xffffffffu, ls0, 2);
        ls1 += __shfl_xor_sync(0xffffffffu, ls1, 1);
        ls1 += __shfl_xor_sync(0xffffffffu, ls1, 2);
        l0 = l0*c0 + ls0; m0 = mn0;
        l1 = l1*c1 + ls1; m1 = mn1;
#pragma unroll
        for (int nt = 0; nt < 16; nt++) {
            co[nt][0] *= c0; co[nt][1] *= c0;
            co[nt][2] *= c1; co[nt][3] *= c1;
        }
        // ---- P fragments (QK C-frag maps directly onto PV A-frag) ----
        uint32_t Ap[4][4];
#pragma unroll
        for (int p = 0; p < 4; p++) {
            Ap[p][0] = packh2(s[2*p][0],   s[2*p][1]);
            Ap[p][1] = packh2(s[2*p][2],   s[2*p][3]);
            Ap[p][2] = packh2(s[2*p+1][0], s[2*p+1][1]);
            Ap[p][3] = packh2(s[2*p+1][2], s[2*p+1][3]);
        }
        // ---- O += P V ----
        {
            int vrow0 = lane & 15;
            int vcol0 = (lane >> 4) << 3;
#pragma unroll
            for (int ksj = 0; ksj < 4; ksj++) {
#pragma unroll
                for (int dc = 0; dc < 8; dc++) {
                    uint32_t Vf[4];
                    ldsm_x4_t(Vf, sb + 2*ATT_TB +
                        (uint32_t)((ksj*16 + vrow0)*PADQ + dc*16 + vcol0)*2);
                    mma16816(co[2*dc],   Ap[ksj], Vf);
                    mma16816(co[2*dc+1], Ap[ksj], Vf+2);
                }
            }
        }
    }
    // ---- write O (fp16 A operand for O-proj) ----
    float i0 = 1.f/l0, i1 = 1.f/l1;
    int r0 = qt*64 + w*16 + (lane >> 2);
    __half* ob = oa + ((size_t)(b*KSEL))*HID + h*HDIM;
#pragma unroll
    for (int nt = 0; nt < 16; nt++) {
        int d = nt*8 + 2*(lane & 3);
        *(uint32_t*)(ob + (size_t)r0*HID + d)     = packh2(co[nt][0]*i0, co[nt][1]*i0);
        *(uint32_t*)(ob + (size_t)(r0+8)*HID + d) = packh2(co[nt][2]*i1, co[nt][3]*i1);
    }
}

// silu(gate)*up -> fp16 A operand
__global__ void k_silumul(__half* __restrict__ ha) {
    size_t i = ((size_t)blockIdx.x*256 + threadIdx.x)*8;
    float4 g0 = *(float4*)(g_gb+i),   u0 = *(float4*)(g_ub+i);
    float4 g1 = *(float4*)(g_gb+i+4), u1 = *(float4*)(g_ub+i+4);
    float v[8] = {
        g0.x/(1.f+expf(-g0.x))*u0.x, g0.y/(1.f+expf(-g0.y))*u0.y,
        g0.z/(1.f+expf(-g0.z))*u0.z, g0.w/(1.f+expf(-g0.w))*u0.w,
        g1.x/(1.f+expf(-g1.x))*u1.x, g1.y/(1.f+expf(-g1.y))*u1.y,
        g1.z/(1.f+expf(-g1.z))*u1.z, g1.w/(1.f+expf(-g1.w))*u1.w };
    unsigned short hv[8];
#pragma unroll
    for (int j = 0; j < 8; j++) {
        __half hb = __float2half_rn(v[j]);
        hv[j] = *(unsigned short*)&hb;
    }
    *(uint4*)(ha + i) = *(uint4*)hv;
}

__global__ void k_copy(const float* __restrict__ src, float* __restrict__ dst) {
    size_t i = ((size_t)blockIdx.x*256 + threadIdx.x)*4;
    *(float4*)(dst+i) = *(const float4*)(src+i);
}

__global__ void k_scatter(float* __restrict__ out) {
    int bj = blockIdx.x, b = bj >> 9;
    int t = g_idx[bj];
    float gt = g_gate[bj];
    float* dst = out + ((size_t)b*TT + t)*HID;
    const float* xp = g_x + (size_t)bj*HID;
    const float* lp = g_lo + (size_t)bj*HID;
    int i = threadIdx.x*8;
#pragma unroll
    for (int u = 0; u < 8; u++) {
        float xv = xp[i+u], lv = lp[i+u];
        dst[i+u] = xv + gt*(lv - xv);
    }
}

__global__ void k_final(float* out, long long N, long long out_size) {
    if (threadIdx.x == 0) {
        if (N   < out_size) out[N]   = (float)((g_f0sum - g_selsum)/(double)NTOT);
        if (N+1 < out_size) out[N+1] = (float)(g_predsum/(double)NTOT);
    }
}

// ======== fp32 -> fp16 cast ========
__global__ void k_convB(const float* __restrict__ src, __half* __restrict__ dst) {
    size_t base = ((size_t)blockIdx.x*256 + threadIdx.x)*8;
    const float4* s = (const float4*)(src + base);
    float4 x0 = s[0], x1 = s[1];
    float xs[8] = {x0.x, x0.y, x0.z, x0.w, x1.x, x1.y, x1.z, x1.w};
    unsigned short hv[8];
#pragma unroll
    for (int j = 0; j < 8; j++) {
        __half hb = __float2half_rn(xs[j]);
        hv[j] = *(unsigned short*)&hb;
    }
    *(uint4*)(dst + base) = *(uint4*)hv;
}

// ================= fp16 MMA GEMM: C[M,N] = A[M,K] @ B[N,K]^T =================
// epi: 0 = +bias(if set); 1 = gelu(acc+bias); 2 = acc + add residual; 3 = +bias, write fp16
#define PADK 40
#define A_BYTES   (128*PADK*2)
#define B_BYTES   (256*PADK*2)
#define STAGE_BYTES (A_BYTES + B_BYTES)
#define GEMM_SMEM (3*STAGE_BYTES)

__device__ __forceinline__ void load_stage(uint32_t sb, int stage,
    const __half* A, const __half* B, int K, int kt, int tid)
{
    uint32_t s0 = sb + stage*STAGE_BYTES;
#pragma unroll
    for (int u = 0; u < 2; u++) {
        int c = tid + u*256;
        int row = c >> 2, seg = (c & 3) << 3;
        cp16(s0 + (row*PADK + seg)*2, A + (size_t)row*K + (size_t)kt*32 + seg);
    }
#pragma unroll
    for (int u = 0; u < 4; u++) {
        int c = tid + u*256;
        int row = c >> 2, seg = (c & 3) << 3;
        cp16(s0 + A_BYTES + (row*PADK + seg)*2, B + (size_t)row*K + (size_t)kt*32 + seg);
    }
    asm volatile("cp.async.commit_group;" ::: "memory");
}

__global__ void __launch_bounds__(256, 1) tc_gemm(
    const __half* __restrict__ Ag, const __half* __restrict__ Bg,
    const float* __restrict__ bias, const float* __restrict__ add,
    float* __restrict__ C, int M, int N, int K, int epi)
{
    extern __shared__ __align__(16) char smem[];
    uint32_t sb = smem_to_u32(smem);
    const int tid = threadIdx.x, wid = tid >> 5, lane = tid & 31;
    const int wm = wid & 1, wn = wid >> 1;
    const long bm = (long)blockIdx.y << 7, bn = (long)blockIdx.x << 8;

    const __half* pA = Ag + (size_t)bm*K;
    const __half* pB = Bg + (size_t)bn*K;

    float acc[4][8][4];
#pragma unroll
    for (int mt = 0; mt < 4; mt++)
#pragma unroll
        for (int nt = 0; nt < 8; nt++)
#pragma unroll
            for (int i = 0; i < 4; i++) acc[mt][nt][i] = 0.f;

    const int NK = K >> 5;
    load_stage(sb, 0, pA, pB, K, 0, tid);
    load_stage(sb, 1, pA, pB, K, 1, tid);

    for (int kt = 0; kt < NK; ++kt) {
        if (kt + 2 < NK) {
            load_stage(sb, (kt+2)%3, pA, pB, K, kt+2, tid);
            asm volatile("cp.async.wait_group 2;" ::: "memory");
        } else {
            asm volatile("cp.async.wait_group 0;" ::: "memory");
        }
        __syncthreads();

        uint32_t s0 = sb + (kt%3)*STAGE_BYTES;
#pragma unroll
        for (int kk = 0; kk < 32; kk += 16) {
            uint32_t Af[4][4];
            const int arow = wm*64 + (lane & 15);
            const int acol = kk + ((lane >> 4) << 3);
#pragma unroll
            for (int mt = 0; mt < 4; mt++)
                ldsm_x4(Af[mt], s0 + (uint32_t)((arow + mt*16)*PADK + acol)*2);
            const int brow = wn*64 + (lane & 7) + (((lane >> 4) & 1) << 3);
            const int bcol = kk + (((lane >> 3) & 1) << 3);
#pragma unroll
            for (int np = 0; np < 4; np++) {
                uint32_t Bf[4];
                ldsm_x4(Bf, s0 + A_BYTES + (uint32_t)((brow + np*16)*PADK + bcol)*2);
#pragma unroll
                for (int mt = 0; mt < 4; mt++) {
                    mma16816(acc[mt][np*2],   Af[mt], Bf);
                    mma16816(acc[mt][np*2+1], Af[mt], Bf+2);
                }
            }
        }
        __syncthreads();
    }

    // ---- epilogue ----
#pragma unroll
    for (int mt = 0; mt < 4; mt++) {
#pragma unroll
        for (int nt = 0; nt < 8; nt++) {
            long m = bm + wm*64 + mt*16 + (lane >> 2);
            long n = bn + wn*64 + nt*8 + ((lane & 3) << 1);
            float* a = acc[mt][nt];
            float b0 = bias ? bias[n] : 0.f;
            float b1 = bias ? bias[n+1] : 0.f;
            float v0 = a[0] + b0, v1 = a[1] + b1, v2 = a[2] + b0, v3 = a[3] + b1;
            if (epi == 1) {
                v0 = 0.5f*v0*(1.f + erff(v0*0.70710678118654752f));
                v1 = 0.5f*v1*(1.f + erff(v1*0.70710678118654752f));
                v2 = 0.5f*v2*(1.f + erff(v2*0.70710678118654752f));
                v3 = 0.5f*v3*(1.f + erff(v3*0.70710678118654752f));
            }
            if (epi == 2) {
                v0 += add[m*N + n];     v1 += add[m*N + n + 1];
                v2 += add[(m+8)*N + n]; v3 += add[(m+8)*N + n + 1];
            }
            if (epi == 3) {
                __half* Ch = (__half*)C;
                *(uint32_t*)(Ch + m*(size_t)N + n)     = packh2(v0, v1);
                *(uint32_t*)(Ch + (m+8)*(size_t)N + n) = packh2(v2, v3);
            } else {
                *(float2*)(C + m*N + n)     = make_float2(v0, v1);
                *(float2*)(C + (m+8)*N + n) = make_float2(v2, v3);
            }
        }
    }
}

// ================= launch =================
extern "C" void kernel_launch(void* const* d_in, const int* in_sizes, int n_in,
                              void* d_out, int out_size) {
    const float* hs     = (const float*)d_in[0];
    const float* rw     = (const float*)d_in[1];
    const float* cfc1_w = (const float*)d_in[2];
    const float* cfc1_b = (const float*)d_in[3];
    const float* cfc2_w = (const float*)d_in[4];
    const float* cfc2_b = (const float*)d_in[5];
    const float* ln1    = (const float*)d_in[6];
    const float* ln2    = (const float*)d_in[7];
    const float* q_w    = (const float*)d_in[8];
    const float* q_b    = (const float*)d_in[9];
    const float* k_w    = (const float*)d_in[10];
    const float* k_b    = (const float*)d_in[11];
    const float* v_w    = (const float*)d_in[12];
    const float* v_b    = (const float*)d_in[13];
    const float* o_w    = (const float*)d_in[14];
    const float* gate_w = (const float*)d_in[15];
    const float* up_w   = (const float*)d_in[16];
    const float* down_w = (const float*)d_in[17];
    float* out = (float*)d_out;

    float *px, *ph1, *plo, *pgb, *pub, *pact, *pqkvb;
    cudaGetSymbolAddress((void**)&px,  g_x);
    cudaGetSymbolAddress((void**)&ph1, g_h1);
    cudaGetSymbolAddress((void**)&plo, g_lo);
    cudaGetSymbolAddress((void**)&pgb, g_gb);
    cudaGetSymbolAddress((void**)&pub, g_ub);
    cudaGetSymbolAddress((void**)&pact, g_act);
    cudaGetSymbolAddress((void**)&pqkvb, g_qkvb);
    __half *pA, *pB, *pqkvh;
    cudaGetSymbolAddress((void**)&pA, g_A);
    cudaGetSymbolAddress((void**)&pB, g_B);
    cudaGetSymbolAddress((void**)&pqkvh, g_qkvh);

    cudaFuncSetAttribute(tc_gemm, cudaFuncAttributeMaxDynamicSharedMemorySize, GEMM_SMEM);
    cudaFuncSetAttribute(k_attn, cudaFuncAttributeMaxDynamicSharedMemorySize, ATT_SMEM);

#define CONVB(src, dst, R, K) k_convB<<<((size_t)(R)*(K)/8)/256, 256>>>(src, dst)
#define GEMM(M, N, K, bias, add, Cp, epi) \
    tc_gemm<<<dim3((N)/256, (M)/128), 256, GEMM_SMEM>>>(pA, pB, bias, add, Cp, M, N, K, epi)

    k_init<<<64, 256>>>();
    k_router<<<NTOT, 256>>>(hs, rw);
    k_topk<<<BB, 1024>>>();

    // predictor: gelu(hs @ cfc1^T + b1) -> g_act ; then BCE
    CONVB(hs, pA, NTOT, HID);
    CONVB(cfc1_w, pB, CH, HID);
    GEMM(NTOT, CH, HID, cfc1_b, nullptr, pact, 1);
    k_pred2<<<NTOT/8, 256>>>(cfc2_w, cfc2_b);

    // gather + rmsnorm1 (fp16 A)
    k_gather<<<NTOK, 256>>>(hs);
    k_rms<<<NTOK, 256>>>(px, ln1, pA);

    // fused QKV GEMM -> fp16 qkv buffer
    CONVB(q_w, pB, HID, HID);
    CONVB(k_w, pB + (size_t)HID*HID, HID, HID);
    CONVB(v_w, pB + (size_t)2*HID*HID, HID, HID);
    k_catbias<<<QSTR/256, 256>>>(q_b, k_b, v_b);
    GEMM(NTOK, QSTR, HID, pqkvb, nullptr, (float*)pqkvh, 3);
    k_rope<<<(NTOK*NHEADS*64)/256, 256>>>();

    // tensor-core attention -> fp16 A for O-proj
    k_attn<<<dim3(KSEL/64, BB*NHEADS), 128, ATT_SMEM>>>(pA);

    // O-proj + residual -> h1 ; rmsnorm2 -> fp16 A for MLP
    CONVB(o_w, pB, HID, HID);
    GEMM(NTOK, HID, HID, nullptr, px, ph1, 2);
    k_rms<<<NTOK, 256>>>(ph1, ln2, pA);

    // MLP
    CONVB(gate_w, pB, INTER, HID);
    GEMM(NTOK, INTER, HID, nullptr, nullptr, pgb, 0);
    CONVB(up_w, pB, INTER, HID);
    GEMM(NTOK, INTER, HID, nullptr, nullptr, pub, 0);
    k_silumul<<<(NTOK*(INTER/8))/256, 256>>>(pA);
    CONVB(down_w, pB, HID, INTER);
    GEMM(NTOK, HID, INTER, nullptr, ph1, plo, 2);

    // output
    k_copy<<<((size_t)NTOT*HID/4)/256, 256>>>(hs, out);
    k_scatter<<<NTOK, 256>>>(out);
    k_final<<<1, 32>>>(out, (long long)NTOT*HID, (long long)out_size);
}

// round 11
// speedup vs baseline: 5.8341x; 1.0959x over previous
#include <cuda_runtime.h>
#include <cuda_fp16.h>
#include <stdint.h>
#include <math.h>

#define BB     4
#define TT     4096
#define HID    2048
#define NHEADS 16
#define HDIM   128
#define INTER  8192
#define KSEL   512
#define NTOK   (BB*KSEL)
#define NTOT   (BB*TT)
#define CH     (HID/4)
#define QSTR   (3*HID)   // 6144

// B-buffer regions (halves)
#define OFF_CFC1 ((size_t)0)
#define OFF_QKV  ((size_t)CH*HID)
#define OFF_O    (OFF_QKV + (size_t)3*HID*HID)
#define OFF_GATE (OFF_O + (size_t)HID*HID)
#define OFF_UP   (OFF_GATE + (size_t)INTER*HID)
#define OFF_DOWN (OFF_UP + (size_t)INTER*HID)
#define B_TOTAL  (OFF_DOWN + (size_t)INTER*HID)

// ================= helpers =================
__device__ __forceinline__ uint32_t smem_to_u32(const void* p) {
    uint32_t a;
    asm("{ .reg .u64 t; cvta.to.shared.u64 t, %1; cvt.u32.u64 %0, t; }" : "=r"(a) : "l"(p));
    return a;
}
__device__ __forceinline__ void cp16(uint32_t s, const void* g) {
    asm volatile("cp.async.cg.shared.global [%0], [%1], 16;" :: "r"(s), "l"(g));
}
__device__ __forceinline__ void ldsm_x4(uint32_t* r, uint32_t addr) {
    asm volatile("ldmatrix.sync.aligned.m8n8.x4.shared.b16 {%0,%1,%2,%3}, [%4];"
        : "=r"(r[0]), "=r"(r[1]), "=r"(r[2]), "=r"(r[3]) : "r"(addr));
}
__device__ __forceinline__ void ldsm_x4_t(uint32_t* r, uint32_t addr) {
    asm volatile("ldmatrix.sync.aligned.m8n8.x4.trans.shared.b16 {%0,%1,%2,%3}, [%4];"
        : "=r"(r[0]), "=r"(r[1]), "=r"(r[2]), "=r"(r[3]) : "r"(addr));
}
__device__ __forceinline__ void mma16816(float* d, const uint32_t* a, const uint32_t* b) {
    asm volatile(
        "mma.sync.aligned.m16n8k16.row.col.f32.f16.f16.f32 "
        "{%0,%1,%2,%3}, {%4,%5,%6,%7}, {%8,%9}, {%0,%1,%2,%3};"
        : "+f"(d[0]), "+f"(d[1]), "+f"(d[2]), "+f"(d[3])
        : "r"(a[0]), "r"(a[1]), "r"(a[2]), "r"(a[3]), "r"(b[0]), "r"(b[1]));
}
__device__ __forceinline__ uint32_t packh2(float a, float b) {
    __half2 p = __floats2half2_rn(a, b);
    return *(uint32_t*)&p;
}

// ================= device scratch =================
__device__ float g_logits[NTOT];
__device__ float g_flags[NTOT];
__device__ int   g_idx[BB*KSEL];
__device__ float g_gate[BB*KSEL];
__device__ float g_act[NTOT*CH];
__device__ float g_x [NTOK*HID];
__device__ float g_h1[NTOK*HID];
__device__ float g_lo[NTOK*HID];
__device__ float g_gu[(size_t)NTOK*2*INTER];
__device__ float g_qkvb[QSTR];
__device__ double g_f0sum, g_selsum, g_predsum;
__device__ __half g_A [33554432];
__device__ __half g_Ap[33554432];
__device__ __half g_B [B_TOTAL];
__device__ __half g_qkvh[(size_t)NTOK*QSTR];

// ================= small kernels =================
__global__ void k_init() {
    int i = blockIdx.x*blockDim.x + threadIdx.x;
    if (i < NTOT) g_flags[i] = 0.f;
    if (i == 0) { g_f0sum = 0.0; g_selsum = 0.0; g_predsum = 0.0; }
}

__global__ void k_router(const float* __restrict__ hs, const float* __restrict__ rw) {
    int t = blockIdx.x;
    const float* row = hs + (size_t)t*HID;
    float s = 0.f;
    for (int i = threadIdx.x; i < HID; i += 256) s += row[i]*rw[i];
    __shared__ float red[256];
    red[threadIdx.x] = s; __syncthreads();
    for (int st = 128; st; st >>= 1) {
        if (threadIdx.x < st) red[threadIdx.x] += red[threadIdx.x+st];
        __syncthreads();
    }
    if (threadIdx.x == 0) {
        float l = red[0];
        g_logits[t] = l;
        float f0 = fmaxf(l, 0.f) + log1pf(expf(-fabsf(l)));
        atomicAdd(&g_f0sum, (double)f0);
    }
}

__global__ void k_topk() {
    int b = blockIdx.x;
    __shared__ float sv[TT];
    __shared__ int   si[TT];
    int tid = threadIdx.x;
    for (int i = tid; i < TT; i += 1024) { sv[i] = g_logits[b*TT + i]; si[i] = i; }
    __syncthreads();
    for (int k = 2; k <= TT; k <<= 1) {
        for (int j = k >> 1; j > 0; j >>= 1) {
            for (int i = tid; i < TT; i += 1024) {
                int ixj = i ^ j;
                if (ixj > i) {
                    float va = sv[i], vb = sv[ixj];
                    int ia = si[i], ib = si[ixj];
                    bool lij = (vb > va) || (vb == va && ib < ia);
                    bool lji = (va > vb) || (va == vb && ia < ib);
                    bool sw = ((i & k) == 0) ? lij : lji;
                    if (sw) { sv[i] = vb; sv[ixj] = va; si[i] = ib; si[ixj] = ia; }
                }
            }
            __syncthreads();
        }
    }
    for (int k = 2; k <= KSEL; k <<= 1) {
        for (int j = k >> 1; j > 0; j >>= 1) {
            if (tid < KSEL) {
                int i = tid, ixj = i ^ j;
                if (ixj > i) {
                    int ia = si[i], ib = si[ixj];
                    bool sw = ((i & k) == 0) ? (ib < ia) : (ia < ib);
                    if (sw) {
                        int ti = si[i]; si[i] = si[ixj]; si[ixj] = ti;
                        float tv = sv[i]; sv[i] = sv[ixj]; sv[ixj] = tv;
                    }
                }
            }
            __syncthreads();
        }
    }
    if (tid < KSEL) {
        int token = si[tid]; float val = sv[tid];
        g_idx[b*KSEL + tid] = token;
        g_gate[b*KSEL + tid] = 1.f/(1.f + expf(-val));
        g_flags[b*TT + token] = 1.f;
        atomicAdd(&g_selsum, (double)val);
    }
}

__global__ void k_pred2(const float* __restrict__ w2, const float* __restrict__ b2) {
    int warp = threadIdx.x >> 5, lane = threadIdx.x & 31;
    int t = blockIdx.x*8 + warp;
    const float* a = g_act + (size_t)t*CH;
    float s = 0.f;
    for (int i = lane; i < CH; i += 32) s += a[i]*w2[i];
    for (int o = 16; o; o >>= 1) s += __shfl_xor_sync(0xffffffffu, s, o);
    __shared__ float ps[8];
    if (lane == 0) {
        float p = s + b2[0];
        float tg = g_flags[t];
        ps[warp] = fmaxf(p, 0.f) - p*tg + log1pf(expf(-fabsf(p)));
    }
    __syncthreads();
    if (threadIdx.x == 0) {
        float tot = 0.f;
        for (int i = 0; i < 8; i++) tot += ps[i];
        atomicAdd(&g_predsum, (double)tot);
    }
}

__global__ void k_gather(const float* __restrict__ hs) {
    int bj = blockIdx.x, b = bj >> 9;
    int t = g_idx[bj];
    const float* src = hs + ((size_t)b*TT + t)*HID;
    float* dst = g_x + (size_t)bj*HID;
    int i = threadIdx.x*8;
    *(float4*)(dst+i)   = *(const float4*)(src+i);
    *(float4*)(dst+i+4) = *(const float4*)(src+i+4);
}

__global__ void k_rms(const float* __restrict__ in, const float* __restrict__ w,
                      __half* __restrict__ ha) {
    int row = blockIdx.x;
    const float* src = in + (size_t)row*HID;
    int i = threadIdx.x*8;
    float4 a = *(const float4*)(src+i), b = *(const float4*)(src+i+4);
    float ss = a.x*a.x + a.y*a.y + a.z*a.z + a.w*a.w
             + b.x*b.x + b.y*b.y + b.z*b.z + b.w*b.w;
    __shared__ float red[256];
    red[threadIdx.x] = ss; __syncthreads();
    for (int st = 128; st; st >>= 1) {
        if (threadIdx.x < st) red[threadIdx.x] += red[threadIdx.x+st];
        __syncthreads();
    }
    float sc = 1.f/sqrtf(red[0]/(float)HID + 1e-6f);
    float4 w0 = *(const float4*)(w+i), w1 = *(const float4*)(w+i+4);
    float v[8] = {a.x*sc*w0.x, a.y*sc*w0.y, a.z*sc*w0.z, a.w*sc*w0.w,
                  b.x*sc*w1.x, b.y*sc*w1.y, b.z*sc*w1.z, b.w*sc*w1.w};
    unsigned short hv[8];
#pragma unroll
    for (int j = 0; j < 8; j++) {
        __half hb = __float2half_rn(v[j]);
        hv[j] = *(unsigned short*)&hb;
    }
    *(uint4*)(ha + (size_t)row*HID + i) = *(uint4*)hv;
}

__global__ void k_catbias(const float* __restrict__ qb, const float* __restrict__ kb,
                          const float* __restrict__ vb) {
    int i = blockIdx.x*256 + threadIdx.x;
    float v = (i < HID) ? qb[i] : (i < 2*HID ? kb[i-HID] : vb[i-2*HID]);
    g_qkvb[i] = v;
}

__global__ void k_rope() {
    int t = blockIdx.x*256 + threadIdx.x;
    int d = t & 63;
    int bh = t >> 6;
    int bj = bh >> 4, h = bh & 15;
    int pos = g_idx[bj];
    float ang = (float)pos * expf(-(float)d * 0.14391156831212787f);
    float c = cosf(ang), s = sinf(ang);
    size_t base = (size_t)bj*QSTR + h*HDIM;
    float q1 = __half2float(g_qkvh[base+d]), q2 = __half2float(g_qkvh[base+d+64]);
    g_qkvh[base+d]    = __float2half_rn(q1*c - q2*s);
    g_qkvh[base+d+64] = __float2half_rn(q2*c + q1*s);
    size_t kb = base + HID;
    float k1 = __half2float(g_qkvh[kb+d]), k2 = __half2float(g_qkvh[kb+d+64]);
    g_qkvh[kb+d]    = __float2half_rn(k1*c - k2*s);
    g_qkvh[kb+d+64] = __float2half_rn(k2*c + k1*s);
}

// ============== tensor-core flash attention ==============
#define PADQ 136
#define ATT_TB (64*PADQ*2)
#define ATT_SMEM (3*ATT_TB)

__device__ __forceinline__ void att_load_tile(uint32_t sdst, const __half* gsrc, int tid) {
#pragma unroll
    for (int u = 0; u < 8; u++) {
        int c = tid + u*128;
        int row = c >> 4, seg = (c & 15) << 3;
        cp16(sdst + (uint32_t)(row*PADQ + seg)*2, gsrc + (size_t)row*QSTR + seg);
    }
}

__global__ void __launch_bounds__(128, 1) k_attn(__half* __restrict__ oa) {
    extern __shared__ char smem[];
    uint32_t sb = smem_to_u32(smem);
    int qt = blockIdx.x, bh = blockIdx.y;
    int b = bh >> 4, h = bh & 15;
    int tid = threadIdx.x, w = tid >> 5, lane = tid & 31;

    const __half* qbase = g_qkvh + ((size_t)(b*KSEL + qt*64))*QSTR + h*HDIM;
    att_load_tile(sb, qbase, tid);
    asm volatile("cp.async.commit_group;" ::: "memory");
    asm volatile("cp.async.wait_group 0;" ::: "memory");
    __syncthreads();

    uint32_t Aq[8][4];
    {
        int arow = w*16 + (lane & 15);
        int acol = (lane >> 4) << 3;
#pragma unroll
        for (int ks = 0; ks < 8; ks++)
            ldsm_x4(Aq[ks], sb + (uint32_t)(arow*PADQ + ks*16 + acol)*2);
    }

    float co[16][4];
#pragma unroll
    for (int nt = 0; nt < 16; nt++)
#pragma unroll
        for (int i = 0; i < 4; i++) co[nt][i] = 0.f;
    float m0 = -1e30f, m1 = -1e30f, l0 = 0.f, l1 = 0.f;

    for (int kt = 0; kt <= qt; ++kt) {
        const __half* kbp = g_qkvh + ((size_t)(b*KSEL + kt*64))*QSTR + HID + h*HDIM;
        const __half* vbp = kbp + HID;
        __syncthreads();
        att_load_tile(sb + ATT_TB,   kbp, tid);
        att_load_tile(sb + 2*ATT_TB, vbp, tid);
        asm volatile("cp.async.commit_group;" ::: "memory");
        asm volatile("cp.async.wait_group 0;" ::: "memory");
        __syncthreads();

        float s[8][4];
#pragma unroll
        for (int nt = 0; nt < 8; nt++)
#pragma unroll
            for (int i = 0; i < 4; i++) s[nt][i] = 0.f;
        {
            int krow0 = (lane & 7) + ((lane >> 4) & 1)*8;
            int kcol0 = ((lane >> 3) & 1) << 3;
#pragma unroll
            for (int ks = 0; ks < 8; ks++) {
#pragma unroll
                for (int np = 0; np < 4; np++) {
                    uint32_t Kf[4];
                    ldsm_x4(Kf, sb + ATT_TB +
                        (uint32_t)((np*16 + krow0)*PADQ + ks*16 + kcol0)*2);
                    mma16816(s[2*np],   Aq[ks], Kf);
                    mma16816(s[2*np+1], Aq[ks], Kf+2);
                }
            }
        }
        const float SC = 0.08838834764831845f;
#pragma unroll
        for (int nt = 0; nt < 8; nt++)
#pragma unroll
            for (int i = 0; i < 4; i++) s[nt][i] *= SC;
        if (kt == qt) {
            int rq = w*16 + (lane >> 2);
#pragma unroll
            for (int nt = 0; nt < 8; nt++) {
                int j0 = nt*8 + 2*(lane & 3);
                if (j0   > rq)   s[nt][0] = -1e9f;
                if (j0+1 > rq)   s[nt][1] = -1e9f;
                if (j0   > rq+8) s[nt][2] = -1e9f;
                if (j0+1 > rq+8) s[nt][3] = -1e9f;
            }
        }
        float mx0 = -1e30f, mx1 = -1e30f;
#pragma unroll
        for (int nt = 0; nt < 8; nt++) {
            mx0 = fmaxf(mx0, fmaxf(s[nt][0], s[nt][1]));
            mx1 = fmaxf(mx1, fmaxf(s[nt][2], s[nt][3]));
        }
        mx0 = fmaxf(mx0, __shfl_xor_sync(0xffffffffu, mx0, 1));
        mx0 = fmaxf(mx0, __shfl_xor_sync(0xffffffffu, mx0, 2));
        mx1 = fmaxf(mx1, __shfl_xor_sync(0xffffffffu, mx1, 1));
        mx1 = fmaxf(mx1, __shfl_xor_sync(0xffffffffu, mx1, 2));
        float mn0 = fmaxf(m0, mx0), mn1 = fmaxf(m1, mx1);
        float c0 = __expf(m0 - mn0), c1 = __expf(m1 - mn1);
        float ls0 = 0.f, ls1 = 0.f;
#pragma unroll
        for (int nt = 0; nt < 8; nt++) {
            s[nt][0] = __expf(s[nt][0] - mn0); ls0 += s[nt][0];
            s[nt][1] = __expf(s[nt][1] - mn0); ls0 += s[nt][1];
            s[nt][2] = __expf(s[nt][2] - mn1); ls1 += s[nt][2];
            s[nt][3] = __expf(s[nt][3] - mn1); ls1 += s[nt][3];
        }
        ls0 += __shfl_xor_sync(0xffffffffu, ls0, 1);
        ls0 += __shfl_xor_sync(0xffffffffu, ls0, 2);
        ls1 += __shfl_xor_sync(0xffffffffu, ls1, 1);
        ls1 += __shfl_xor_sync(0xffffffffu, ls1, 2);
        l0 = l0*c0 + ls0; m0 = mn0;
        l1 = l1*c1 + ls1; m1 = mn1;
#pragma unroll
        for (int nt = 0; nt < 16; nt++) {
            co[nt][0] *= c0; co[nt][1] *= c0;
            co[nt][2] *= c1; co[nt][3] *= c1;
        }
        uint32_t Ap[4][4];
#pragma unroll
        for (int p = 0; p < 4; p++) {
            Ap[p][0] = packh2(s[2*p][0],   s[2*p][1]);
            Ap[p][1] = packh2(s[2*p][2],   s[2*p][3]);
            Ap[p][2] = packh2(s[2*p+1][0], s[2*p+1][1]);
            Ap[p][3] = packh2(s[2*p+1][2], s[2*p+1][3]);
        }
        {
            int vrow0 = lane & 15;
            int vcol0 = (lane >> 4) << 3;
#pragma unroll
            for (int ksj = 0; ksj < 4; ksj++) {
#pragma unroll
                for (int dc = 0; dc < 8; dc++) {
                    uint32_t Vf[4];
                    ldsm_x4_t(Vf, sb + 2*ATT_TB +
                        (uint32_t)((ksj*16 + vrow0)*PADQ + dc*16 + vcol0)*2);
                    mma16816(co[2*dc],   Ap[ksj], Vf);
                    mma16816(co[2*dc+1], Ap[ksj], Vf+2);
                }
            }
        }
    }
    float i0 = 1.f/l0, i1 = 1.f/l1;
    int r0 = qt*64 + w*16 + (lane >> 2);
    __half* ob = oa + ((size_t)(b*KSEL))*HID + h*HDIM;
#pragma unroll
    for (int nt = 0; nt < 16; nt++) {
        int d = nt*8 + 2*(lane & 3);
        *(uint32_t*)(ob + (size_t)r0*HID + d)     = packh2(co[nt][0]*i0, co[nt][1]*i0);
        *(uint32_t*)(ob + (size_t)(r0+8)*HID + d) = packh2(co[nt][2]*i1, co[nt][3]*i1);
    }
}

// silu(gate)*up from fused g_gu -> fp16 A operand
__global__ void k_silumul(__half* __restrict__ ha) {
    size_t idx = ((size_t)blockIdx.x*256 + threadIdx.x)*8;
    int m = (int)(idx >> 13);
    int n = (int)(idx & (INTER-1));
    const float* gp = g_gu + (size_t)m*(2*INTER) + n;
    const float* up = gp + INTER;
    float4 g0 = *(const float4*)gp,     g1 = *(const float4*)(gp+4);
    float4 u0 = *(const float4*)up,     u1 = *(const float4*)(up+4);
    float v[8] = {
        g0.x/(1.f+expf(-g0.x))*u0.x, g0.y/(1.f+expf(-g0.y))*u0.y,
        g0.z/(1.f+expf(-g0.z))*u0.z, g0.w/(1.f+expf(-g0.w))*u0.w,
        g1.x/(1.f+expf(-g1.x))*u1.x, g1.y/(1.f+expf(-g1.y))*u1.y,
        g1.z/(1.f+expf(-g1.z))*u1.z, g1.w/(1.f+expf(-g1.w))*u1.w };
    unsigned short hv[8];
#pragma unroll
    for (int j = 0; j < 8; j++) {
        __half hb = __float2half_rn(v[j]);
        hv[j] = *(unsigned short*)&hb;
    }
    *(uint4*)(ha + (size_t)m*INTER + n) = *(uint4*)hv;
}

__global__ void k_copy(const float* __restrict__ src, float* __restrict__ dst) {
    size_t i = ((size_t)blockIdx.x*256 + threadIdx.x)*4;
    *(float4*)(dst+i) = *(const float4*)(src+i);
}

__global__ void k_scatter(float* __restrict__ out) {
    int bj = blockIdx.x, b = bj >> 9;
    int t = g_idx[bj];
    float gt = g_gate[bj];
    float* dst = out + ((size_t)b*TT + t)*HID;
    const float* xp = g_x + (size_t)bj*HID;
    const float* lp = g_lo + (size_t)bj*HID;
    int i = threadIdx.x*8;
#pragma unroll
    for (int u = 0; u < 8; u++) {
        float xv = xp[i+u], lv = lp[i+u];
        dst[i+u] = xv + gt*(lv - xv);
    }
}

__global__ void k_final(float* out, long long N, long long out_size) {
    if (threadIdx.x == 0) {
        if (N   < out_size) out[N]   = (float)((g_f0sum - g_selsum)/(double)NTOT);
        if (N+1 < out_size) out[N+1] = (float)(g_predsum/(double)NTOT);
    }
}

// ======== fp32 -> fp16 cast ========
__global__ void k_convB(const float* __restrict__ src, __half* __restrict__ dst) {
    size_t base = ((size_t)blockIdx.x*256 + threadIdx.x)*8;
    const float4* s = (const float4*)(src + base);
    float4 x0 = s[0], x1 = s[1];
    float xs[8] = {x0.x, x0.y, x0.z, x0.w, x1.x, x1.y, x1.z, x1.w};
    unsigned short hv[8];
#pragma unroll
    for (int j = 0; j < 8; j++) {
        __half hb = __float2half_rn(xs[j]);
        hv[j] = *(unsigned short*)&hb;
    }
    *(uint4*)(dst + base) = *(uint4*)hv;
}

// ================= fp16 MMA GEMM =================
#define PADK 40
#define A_BYTES   (128*PADK*2)
#define B_BYTES   (256*PADK*2)
#define STAGE_BYTES (A_BYTES + B_BYTES)
#define GEMM_SMEM (3*STAGE_BYTES)

__device__ __forceinline__ void load_stage(uint32_t sb, int stage,
    const __half* A, const __half* B, int K, int kt, int tid)
{
    uint32_t s0 = sb + stage*STAGE_BYTES;
#pragma unroll
    for (int u = 0; u < 2; u++) {
        int c = tid + u*256;
        int row = c >> 2, seg = (c & 3) << 3;
        cp16(s0 + (row*PADK + seg)*2, A + (size_t)row*K + (size_t)kt*32 + seg);
    }
#pragma unroll
    for (int u = 0; u < 4; u++) {
        int c = tid + u*256;
        int row = c >> 2, seg = (c & 3) << 3;
        cp16(s0 + A_BYTES + (row*PADK + seg)*2, B + (size_t)row*K + (size_t)kt*32 + seg);
    }
    asm volatile("cp.async.commit_group;" ::: "memory");
}

__global__ void __launch_bounds__(256, 1) tc_gemm(
    const __half* __restrict__ Ag, const __half* __restrict__ Bg,
    const float* __restrict__ bias, const float* __restrict__ add,
    float* __restrict__ C, int M, int N, int K, int epi)
{
    extern __shared__ __align__(16) char smem[];
    uint32_t sb = smem_to_u32(smem);
    const int tid = threadIdx.x, wid = tid >> 5, lane = tid & 31;
    const int wm = wid & 1, wn = wid >> 1;
    const long bm = (long)blockIdx.y << 7, bn = (long)blockIdx.x << 8;

    const __half* pA = Ag + (size_t)bm*K;
    const __half* pB = Bg + (size_t)bn*K;

    float acc[4][8][4];
#pragma unroll
    for (int mt = 0; mt < 4; mt++)
#pragma unroll
        for (int nt = 0; nt < 8; nt++)
#pragma unroll
            for (int i = 0; i < 4; i++) acc[mt][nt][i] = 0.f;

    const int NK = K >> 5;
    load_stage(sb, 0, pA, pB, K, 0, tid);
    load_stage(sb, 1, pA, pB, K, 1, tid);

    for (int kt = 0; kt < NK; ++kt) {
        if (kt + 2 < NK) {
            load_stage(sb, (kt+2)%3, pA, pB, K, kt+2, tid);
            asm volatile("cp.async.wait_group 2;" ::: "memory");
        } else {
            asm volatile("cp.async.wait_group 0;" ::: "memory");
        }
        __syncthreads();

        uint32_t s0 = sb + (kt%3)*STAGE_BYTES;
#pragma unroll
        for (int kk = 0; kk < 32; kk += 16) {
            uint32_t Af[4][4];
            const int arow = wm*64 + (lane & 15);
            const int acol = kk + ((lane >> 4) << 3);
#pragma unroll
            for (int mt = 0; mt < 4; mt++)
                ldsm_x4(Af[mt], s0 + (uint32_t)((arow + mt*16)*PADK + acol)*2);
            const int brow = wn*64 + (lane & 7) + (((lane >> 4) & 1) << 3);
            const int bcol = kk + (((lane >> 3) & 1) << 3);
#pragma unroll
            for (int np = 0; np < 4; np++) {
                uint32_t Bf[4];
                ldsm_x4(Bf, s0 + A_BYTES + (uint32_t)((brow + np*16)*PADK + bcol)*2);
#pragma unroll
                for (int mt = 0; mt < 4; mt++) {
                    mma16816(acc[mt][np*2],   Af[mt], Bf);
                    mma16816(acc[mt][np*2+1], Af[mt], Bf+2);
                }
            }
        }
        __syncthreads();
    }

#pragma unroll
    for (int mt = 0; mt < 4; mt++) {
#pragma unroll
        for (int nt = 0; nt < 8; nt++) {
            long m = bm + wm*64 + mt*16 + (lane >> 2);
            long n = bn + wn*64 + nt*8 + ((lane & 3) << 1);
            float* a = acc[mt][nt];
            float b0 = bias ? bias[n] : 0.f;
            float b1 = bias ? bias[n+1] : 0.f;
            float v0 = a[0] + b0, v1 = a[1] + b1, v2 = a[2] + b0, v3 = a[3] + b1;
            if (epi == 1) {
                v0 = 0.5f*v0*(1.f + erff(v0*0.70710678118654752f));
                v1 = 0.5f*v1*(1.f + erff(v1*0.70710678118654752f));
                v2 = 0.5f*v2*(1.f + erff(v2*0.70710678118654752f));
                v3 = 0.5f*v3*(1.f + erff(v3*0.70710678118654752f));
            }
            if (epi == 2) {
                v0 += add[m*N + n];     v1 += add[m*N + n + 1];
                v2 += add[(m+8)*N + n]; v3 += add[(m+8)*N + n + 1];
            }
            if (epi == 3) {
                __half* Ch = (__half*)C;
                *(uint32_t*)(Ch + m*(size_t)N + n)     = packh2(v0, v1);
                *(uint32_t*)(Ch + (m+8)*(size_t)N + n) = packh2(v2, v3);
            } else {
                *(float2*)(C + m*N + n)     = make_float2(v0, v1);
                *(float2*)(C + (m+8)*N + n) = make_float2(v2, v3);
            }
        }
    }
}

// ================= launch =================
extern "C" void kernel_launch(void* const* d_in, const int* in_sizes, int n_in,
                              void* d_out, int out_size) {
    const float* hs     = (const float*)d_in[0];
    const float* rw     = (const float*)d_in[1];
    const float* cfc1_w = (const float*)d_in[2];
    const float* cfc1_b = (const float*)d_in[3];
    const float* cfc2_w = (const float*)d_in[4];
    const float* cfc2_b = (const float*)d_in[5];
    const float* ln1    = (const float*)d_in[6];
    const float* ln2    = (const float*)d_in[7];
    const float* q_w    = (const float*)d_in[8];
    const float* q_b    = (const float*)d_in[9];
    const float* k_w    = (const float*)d_in[10];
    const float* k_b    = (const float*)d_in[11];
    const float* v_w    = (const float*)d_in[12];
    const float* v_b    = (const float*)d_in[13];
    const float* o_w    = (const float*)d_in[14];
    const float* gate_w = (const float*)d_in[15];
    const float* up_w   = (const float*)d_in[16];
    const float* down_w = (const float*)d_in[17];
    float* out = (float*)d_out;

    float *px, *ph1, *plo, *pgu, *pact, *pqkvb;
    cudaGetSymbolAddress((void**)&px,  g_x);
    cudaGetSymbolAddress((void**)&ph1, g_h1);
    cudaGetSymbolAddress((void**)&plo, g_lo);
    cudaGetSymbolAddress((void**)&pgu, g_gu);
    cudaGetSymbolAddress((void**)&pact, g_act);
    cudaGetSymbolAddress((void**)&pqkvb, g_qkvb);
    __half *pA, *pAp, *pB, *pqkvh;
    cudaGetSymbolAddress((void**)&pA,  g_A);
    cudaGetSymbolAddress((void**)&pAp, g_Ap);
    cudaGetSymbolAddress((void**)&pB,  g_B);
    cudaGetSymbolAddress((void**)&pqkvh, g_qkvh);

    cudaFuncSetAttribute(tc_gemm, cudaFuncAttributeMaxDynamicSharedMemorySize, GEMM_SMEM);
    cudaFuncSetAttribute(k_attn, cudaFuncAttributeMaxDynamicSharedMemorySize, ATT_SMEM);

    // streams + events: created ONCE on the first (correctness) call and cached.
    // The graph-capture call then performs no allocator activity.
    static bool s_init = false;
    static cudaStream_t s1, s2, s3;
    static cudaEvent_t e0, eTopk, eCfc1, eQkv, eO, eGU, eDown, eCopy, ePred;
    if (!s_init) {
        cudaStreamCreate(&s1); cudaStreamCreate(&s2); cudaStreamCreate(&s3);
        cudaEventCreateWithFlags(&e0,    cudaEventDisableTiming);
        cudaEventCreateWithFlags(&eTopk, cudaEventDisableTiming);
        cudaEventCreateWithFlags(&eCfc1, cudaEventDisableTiming);
        cudaEventCreateWithFlags(&eQkv,  cudaEventDisableTiming);
        cudaEventCreateWithFlags(&eO,    cudaEventDisableTiming);
        cudaEventCreateWithFlags(&eGU,   cudaEventDisableTiming);
        cudaEventCreateWithFlags(&eDown, cudaEventDisableTiming);
        cudaEventCreateWithFlags(&eCopy, cudaEventDisableTiming);
        cudaEventCreateWithFlags(&ePred, cudaEventDisableTiming);
        s_init = true;
    }

#define CONVB_S(st, src, dst, R, K) k_convB<<<((size_t)(R)*(K)/8)/256, 256, 0, st>>>(src, dst)
#define GEMM_S(st, Ap_, Bp_, M, N, K, bias, add, Cp, epi) \
    tc_gemm<<<dim3((N)/256, (M)/128), 256, GEMM_SMEM, st>>>(Ap_, Bp_, bias, add, Cp, M, N, K, epi)

    // ---- fork ----
    k_init<<<64, 256>>>();
    cudaEventRecord(e0, 0);
    cudaStreamWaitEvent(s1, e0, 0);
    cudaStreamWaitEvent(s2, e0, 0);
    cudaStreamWaitEvent(s3, e0, 0);

    // s1: weight conversions into disjoint regions
    CONVB_S(s1, cfc1_w, pB + OFF_CFC1, CH, HID);
    cudaEventRecord(eCfc1, s1);
    CONVB_S(s1, q_w, pB + OFF_QKV,                     HID, HID);
    CONVB_S(s1, k_w, pB + OFF_QKV + (size_t)HID*HID,   HID, HID);
    CONVB_S(s1, v_w, pB + OFF_QKV + (size_t)2*HID*HID, HID, HID);
    k_catbias<<<QSTR/256, 256, 0, s1>>>(q_b, k_b, v_b);
    cudaEventRecord(eQkv, s1);
    CONVB_S(s1, o_w, pB + OFF_O, HID, HID);
    cudaEventRecord(eO, s1);
    CONVB_S(s1, gate_w, pB + OFF_GATE, INTER, HID);
    CONVB_S(s1, up_w,   pB + OFF_UP,   INTER, HID);
    cudaEventRecord(eGU, s1);
    CONVB_S(s1, down_w, pB + OFF_DOWN, HID, INTER);
    cudaEventRecord(eDown, s1);

    // s2: predictor chain (own A buffer)
    CONVB_S(s2, hs, pAp, NTOT, HID);
    cudaStreamWaitEvent(s2, eCfc1, 0);
    GEMM_S(s2, pAp, pB + OFF_CFC1, NTOT, CH, HID, cfc1_b, nullptr, pact, 1);

    // s3: bulk output copy
    k_copy<<<((size_t)NTOT*HID/4)/256, 256, 0, s3>>>(hs, out);
    cudaEventRecord(eCopy, s3);

    // main stream: router -> topk -> attention block -> MLP
    k_router<<<NTOT, 256>>>(hs, rw);
    k_topk<<<BB, 1024>>>();
    cudaEventRecord(eTopk, 0);

    // s2 continues: pred2 needs flags from topk
    cudaStreamWaitEvent(s2, eTopk, 0);
    k_pred2<<<NTOT/8, 256, 0, s2>>>(cfc2_w, cfc2_b);
    cudaEventRecord(ePred, s2);

    k_gather<<<NTOK, 256>>>(hs);
    k_rms<<<NTOK, 256>>>(px, ln1, pA);

    cudaStreamWaitEvent(0, eQkv, 0);
    GEMM_S(0, pA, pB + OFF_QKV, NTOK, QSTR, HID, pqkvb, nullptr, (float*)pqkvh, 3);
    k_rope<<<(NTOK*NHEADS*64)/256, 256>>>();
    k_attn<<<dim3(KSEL/64, BB*NHEADS), 128, ATT_SMEM>>>(pA);

    cudaStreamWaitEvent(0, eO, 0);
    GEMM_S(0, pA, pB + OFF_O, NTOK, HID, HID, nullptr, px, ph1, 2);
    k_rms<<<NTOK, 256>>>(ph1, ln2, pA);

    cudaStreamWaitEvent(0, eGU, 0);
    GEMM_S(0, pA, pB + OFF_GATE, NTOK, 2*INTER, HID, nullptr, nullptr, pgu, 0);
    k_silumul<<<(NTOK*(INTER/8))/256, 256>>>(pA);

    cudaStreamWaitEvent(0, eDown, 0);
    GEMM_S(0, pA, pB + OFF_DOWN, NTOK, HID, INTER, nullptr, ph1, plo, 2);

    // join + output
    cudaStreamWaitEvent(0, eCopy, 0);
    k_scatter<<<NTOK, 256>>>(out);
    cudaStreamWaitEvent(0, ePred, 0);
    k_final<<<1, 32>>>(out, (long long)NTOT*HID, (long long)out_size);
}